// round 13
// baseline (speedup 1.0000x reference)
#include <cuda_runtime.h>
#include <cuda_bf16.h>
#include <cstdint>
#include <math.h>

#define Bb   16
#define Ff   4096
#define Qq   64
#define DIMc 512
#define Hh   8
#define DHh  64
#define FCH  128
#define NSPL 8
#define FSEG (Ff / NSPL)

typedef __nv_bfloat16 bf16;
typedef __nv_bfloat162 bf162;

// ---------------- scratch (device globals; no allocation allowed) ----------------
__device__ bf16  g_xnh [(size_t)Bb * Ff * DIMc];
__device__ bf16  g_xnl [(size_t)Bb * Ff * DIMc];
__device__ bf16  g_lath[(size_t)Bb * Qq * DIMc];
__device__ bf16  g_latl[(size_t)Bb * Qq * DIMc];
__device__ bf16  g_ln2h[(size_t)Bb * Qq * DIMc];
__device__ bf16  g_ln2l[(size_t)Bb * Qq * DIMc];
__device__ bf16  g_ffhh[(size_t)Bb * Qq * 1024];
__device__ bf16  g_ffhl[(size_t)Bb * Qq * 1024];
__device__ bf16  g_wqh[DIMc * DIMc], g_wql[DIMc * DIMc];
__device__ bf16  g_wkh[DIMc * DIMc], g_wkl[DIMc * DIMc];
__device__ bf16  g_wvh[DIMc * DIMc], g_wvl[DIMc * DIMc];
__device__ bf16  g_w1h[DIMc * 1024], g_w1l[DIMc * 1024];
__device__ bf16  g_w2h[1024 * DIMc], g_w2l[1024 * DIMc];
__device__ bf16  g_qh [(size_t)Bb * Qq * DIMc], g_ql2[(size_t)Bb * Qq * DIMc];
__device__ bf16  g_kh [(size_t)Bb * Ff * DIMc], g_kl2[(size_t)Bb * Ff * DIMc];
__device__ bf16  g_vh [(size_t)Bb * Ff * DIMc], g_vl2[(size_t)Bb * Ff * DIMc];
__device__ float g_att[(size_t)Bb * Qq * DIMc];
__device__ float g_po [(size_t)Bb * Hh * NSPL * Qq * DHh];
__device__ float g_pm [(size_t)Bb * Hh * NSPL * Qq];
__device__ float g_pl [(size_t)Bb * Hh * NSPL * Qq];
__device__ float g_part[(size_t)4 * 1024 * 1024];   // split-K partials (16 MB)

// ---------------- helpers ----------------
static __device__ __forceinline__ uint32_t smem_u32(const void* p) {
    uint32_t a;
    asm("{ .reg .u64 t; cvta.to.shared.u64 t, %1; cvt.u32.u64 %0, t; }" : "=r"(a) : "l"(p));
    return a;
}
static __device__ __forceinline__ void cpa16(uint32_t dst, const void* src) {
    asm volatile("cp.async.cg.shared.global [%0], [%1], 16;" :: "r"(dst), "l"(src));
}
#define CPA_COMMIT() asm volatile("cp.async.commit_group;" ::: "memory")
#define CPA_WAIT1()  asm volatile("cp.async.wait_group 1;" ::: "memory")
#define CPA_WAIT0()  asm volatile("cp.async.wait_group 0;" ::: "memory")

#define LDSM4(r0, r1, r2, r3, addr)                                        \
    asm volatile("ldmatrix.sync.aligned.m8n8.x4.shared.b16 {%0,%1,%2,%3}, [%4];" \
                 : "=r"(r0), "=r"(r1), "=r"(r2), "=r"(r3) : "r"(addr))

#define LDSM2(r0, r1, addr)                                                \
    asm volatile("ldmatrix.sync.aligned.m8n8.x2.shared.b16 {%0,%1}, [%2];" \
                 : "=r"(r0), "=r"(r1) : "r"(addr))

#define LDSM2T(r0, r1, addr)                                               \
    asm volatile("ldmatrix.sync.aligned.m8n8.x2.trans.shared.b16 {%0,%1}, [%2];" \
                 : "=r"(r0), "=r"(r1) : "r"(addr))

#define MMA_BF16(c, a, b)                                                  \
    asm volatile("mma.sync.aligned.m16n8k16.row.col.f32.bf16.bf16.f32 "    \
                 "{%0,%1,%2,%3}, {%4,%5,%6,%7}, {%8,%9}, {%0,%1,%2,%3};"   \
                 : "+f"((c)[0]), "+f"((c)[1]), "+f"((c)[2]), "+f"((c)[3])  \
                 : "r"((a)[0]), "r"((a)[1]), "r"((a)[2]), "r"((a)[3]),     \
                   "r"((b)[0]), "r"((b)[1]))

static __device__ __forceinline__ void bf16_split(float x, bf16& h, bf16& l) {
    h = __float2bfloat16(x);
    l = __float2bfloat16(x - __bfloat162float(h));
}
static __device__ __forceinline__ void splitpack(float p0, float p1,
                                                 uint32_t& hi, uint32_t& lo) {
    bf16 h0, l0, h1, l1;
    bf16_split(p0, h0, l0);
    bf16_split(p1, h1, l1);
    bf162 H; H.x = h0; H.y = h1;
    bf162 L; L.x = l0; L.y = l1;
    hi = *(uint32_t*)&H;
    lo = *(uint32_t*)&L;
}

// ---------------- 3xBF16 mma GEMM (exact R10/R12 kernel: 128 regs, no spills) ----------------
#define STAGE_B    32768
#define GEMM_SMEM  (3 * STAGE_B)

__global__ void __launch_bounds__(256, 2) bf16_gemm(
    const bf16* __restrict__ Ah, const bf16* __restrict__ Al,
    const bf16* __restrict__ Wh, const bf16* __restrict__ Wl,
    float* __restrict__ Cf, bf16* __restrict__ Ch, bf16* __restrict__ Cl,
    int M, int N, int K, int relu)
{
    extern __shared__ __align__(1024) char smem[];
    int tid = threadIdx.x;
    int lane = tid & 31, wid = tid >> 5;
    int bn = blockIdx.x << 7, bm = blockIdx.y << 7;
    uint32_t sbase = smem_u32(smem);

    int wm = (wid & 1) << 6;
    int wn = (wid >> 1) << 5;

    float acc[4][4][4];
    #pragma unroll
    for (int i = 0; i < 4; i++)
        #pragma unroll
        for (int j = 0; j < 4; j++)
            #pragma unroll
            for (int r = 0; r < 4; r++) acc[i][j][r] = 0.f;

    int nCh = K >> 5;

    auto issue = [&](int p, int s) {
        uint32_t st = sbase + s * STAGE_B;
        int k0 = p << 5;
        #pragma unroll
        for (int r = 0; r < 2; r++) {
            int c = r * 256 + tid;
            int m = c >> 2, c4 = c & 3;
            uint32_t off = m * 64 + (c4 << 4);
            uint32_t sw = off ^ ((off >> 3) & 0x30);
            cpa16(st + sw, Ah + (size_t)(bm + m) * K + k0 + c4 * 8);
            cpa16(st + 8192 + sw, Al + (size_t)(bm + m) * K + k0 + c4 * 8);
        }
        #pragma unroll
        for (int r = 0; r < 2; r++) {
            int c = r * 256 + tid;
            int kk = c >> 4, c16 = c & 15;
            uint32_t off = kk * 256 + (c16 << 4);
            uint32_t sw = off ^ ((off >> 4) & 0x70);
            cpa16(st + 16384 + sw, Wh + (size_t)(k0 + kk) * N + bn + c16 * 8);
            cpa16(st + 24576 + sw, Wl + (size_t)(k0 + kk) * N + bn + c16 * 8);
        }
        CPA_COMMIT();
    };

    issue(0, 0);
    if (nCh > 1) issue(1, 1); else CPA_COMMIT();

    int quad = lane >> 3, rr = lane & 7;
    int lrow = ((quad & 1) << 3) + rr;
    int lcol = quad >> 1;
    int bl16 = lane & 15;

    for (int p = 0; p < nCh; p++) {
        CPA_WAIT1();
        __syncthreads();
        int s = p % 3;
        uint32_t aHi = sbase + s * STAGE_B;
        uint32_t aLo = aHi + 8192;
        uint32_t bHi = aHi + 16384;
        uint32_t bLo = aHi + 24576;

        #pragma unroll
        for (int j = 0; j < 2; j++) {
            uint32_t ahf[4][4], alf[4][4];
            #pragma unroll
            for (int mt = 0; mt < 4; mt++) {
                uint32_t off = (uint32_t)(wm + mt * 16 + lrow) * 64 + j * 32 + (lcol << 4);
                uint32_t sw = off ^ ((off >> 3) & 0x30);
                LDSM4(ahf[mt][0], ahf[mt][1], ahf[mt][2], ahf[mt][3], aHi + sw);
                LDSM4(alf[mt][0], alf[mt][1], alf[mt][2], alf[mt][3], aLo + sw);
            }
            uint32_t bhf[4][2], blf[4][2];
            {
                uint32_t krow = j * 16 + bl16;
                #pragma unroll
                for (int nt = 0; nt < 4; nt++) {
                    uint32_t off = krow * 256 + (uint32_t)(wn + nt * 8) * 2;
                    uint32_t sw = off ^ ((off >> 4) & 0x70);
                    LDSM2T(bhf[nt][0], bhf[nt][1], bHi + sw);
                    LDSM2T(blf[nt][0], blf[nt][1], bLo + sw);
                }
            }
            #pragma unroll
            for (int mt = 0; mt < 4; mt++)
                #pragma unroll
                for (int nt = 0; nt < 4; nt++) {
                    MMA_BF16(acc[mt][nt], ahf[mt], bhf[nt]);
                    MMA_BF16(acc[mt][nt], ahf[mt], blf[nt]);
                    MMA_BF16(acc[mt][nt], alf[mt], bhf[nt]);
                }
        }
        if (p + 2 < nCh) issue(p + 2, (p + 2) % 3);
        else CPA_COMMIT();
    }

    int r0 = bm + wm + (lane >> 2);
    int cc = bn + wn + ((lane & 3) << 1);
    #pragma unroll
    for (int mt = 0; mt < 4; mt++) {
        #pragma unroll
        for (int nt = 0; nt < 4; nt++) {
            float v0 = acc[mt][nt][0], v1 = acc[mt][nt][1];
            float v2 = acc[mt][nt][2], v3 = acc[mt][nt][3];
            if (relu) {
                v0 = fmaxf(v0, 0.f); v1 = fmaxf(v1, 0.f);
                v2 = fmaxf(v2, 0.f); v3 = fmaxf(v3, 0.f);
            }
            int row = r0 + mt * 16;
            int col = cc + nt * 8;
            if (Cf) {
                *(float2*)(Cf + (size_t)row * N + col) = make_float2(v0, v1);
                *(float2*)(Cf + (size_t)(row + 8) * N + col) = make_float2(v2, v3);
            } else {
                uint32_t ph, pl;
                splitpack(v0, v1, ph, pl);
                *(uint32_t*)(Ch + (size_t)row * N + col) = ph;
                *(uint32_t*)(Cl + (size_t)row * N + col) = pl;
                splitpack(v2, v3, ph, pl);
                *(uint32_t*)(Ch + (size_t)(row + 8) * N + col) = ph;
                *(uint32_t*)(Cl + (size_t)(row + 8) * N + col) = pl;
            }
        }
    }
}

// ---------------- split-K variant for small GEMMs: z owns a K-slice, writes f32 partials ----------------
__global__ void __launch_bounds__(256, 2) bf16_gemm_splitk(
    const bf16* __restrict__ Ah, const bf16* __restrict__ Al,
    const bf16* __restrict__ Wh, const bf16* __restrict__ Wl,
    float* __restrict__ P, int M, int N, int Ktot, int Kslice)
{
    extern __shared__ __align__(1024) char smem[];
    int tid = threadIdx.x;
    int lane = tid & 31, wid = tid >> 5;
    int bn = blockIdx.x << 7, bm = blockIdx.y << 7;
    int kbase = blockIdx.z * Kslice;
    uint32_t sbase = smem_u32(smem);

    int wm = (wid & 1) << 6;
    int wn = (wid >> 1) << 5;

    float acc[4][4][4];
    #pragma unroll
    for (int i = 0; i < 4; i++)
        #pragma unroll
        for (int j = 0; j < 4; j++)
            #pragma unroll
            for (int r = 0; r < 4; r++) acc[i][j][r] = 0.f;

    int nCh = Kslice >> 5;

    auto issue = [&](int p, int s) {
        uint32_t st = sbase + s * STAGE_B;
        int k0 = kbase + (p << 5);
        #pragma unroll
        for (int r = 0; r < 2; r++) {
            int c = r * 256 + tid;
            int m = c >> 2, c4 = c & 3;
            uint32_t off = m * 64 + (c4 << 4);
            uint32_t sw = off ^ ((off >> 3) & 0x30);
            cpa16(st + sw, Ah + (size_t)(bm + m) * Ktot + k0 + c4 * 8);
            cpa16(st + 8192 + sw, Al + (size_t)(bm + m) * Ktot + k0 + c4 * 8);
        }
        #pragma unroll
        for (int r = 0; r < 2; r++) {
            int c = r * 256 + tid;
            int kk = c >> 4, c16 = c & 15;
            uint32_t off = kk * 256 + (c16 << 4);
            uint32_t sw = off ^ ((off >> 4) & 0x70);
            cpa16(st + 16384 + sw, Wh + (size_t)(k0 + kk) * N + bn + c16 * 8);
            cpa16(st + 24576 + sw, Wl + (size_t)(k0 + kk) * N + bn + c16 * 8);
        }
        CPA_COMMIT();
    };

    issue(0, 0);
    if (nCh > 1) issue(1, 1); else CPA_COMMIT();

    int quad = lane >> 3, rr = lane & 7;
    int lrow = ((quad & 1) << 3) + rr;
    int lcol = quad >> 1;
    int bl16 = lane & 15;

    for (int p = 0; p < nCh; p++) {
        CPA_WAIT1();
        __syncthreads();
        int s = p % 3;
        uint32_t aHi = sbase + s * STAGE_B;
        uint32_t aLo = aHi + 8192;
        uint32_t bHi = aHi + 16384;
        uint32_t bLo = aHi + 24576;

        #pragma unroll
        for (int j = 0; j < 2; j++) {
            uint32_t ahf[4][4], alf[4][4];
            #pragma unroll
            for (int mt = 0; mt < 4; mt++) {
                uint32_t off = (uint32_t)(wm + mt * 16 + lrow) * 64 + j * 32 + (lcol << 4);
                uint32_t sw = off ^ ((off >> 3) & 0x30);
                LDSM4(ahf[mt][0], ahf[mt][1], ahf[mt][2], ahf[mt][3], aHi + sw);
                LDSM4(alf[mt][0], alf[mt][1], alf[mt][2], alf[mt][3], aLo + sw);
            }
            uint32_t bhf[4][2], blf[4][2];
            {
                uint32_t krow = j * 16 + bl16;
                #pragma unroll
                for (int nt = 0; nt < 4; nt++) {
                    uint32_t off = krow * 256 + (uint32_t)(wn + nt * 8) * 2;
                    uint32_t sw = off ^ ((off >> 4) & 0x70);
                    LDSM2T(bhf[nt][0], bhf[nt][1], bHi + sw);
                    LDSM2T(blf[nt][0], blf[nt][1], bLo + sw);
                }
            }
            #pragma unroll
            for (int mt = 0; mt < 4; mt++)
                #pragma unroll
                for (int nt = 0; nt < 4; nt++) {
                    MMA_BF16(acc[mt][nt], ahf[mt], bhf[nt]);
                    MMA_BF16(acc[mt][nt], ahf[mt], blf[nt]);
                    MMA_BF16(acc[mt][nt], alf[mt], bhf[nt]);
                }
        }
        if (p + 2 < nCh) issue(p + 2, (p + 2) % 3);
        else CPA_COMMIT();
    }

    float* Pz = P + (size_t)blockIdx.z * M * N;
    int r0 = bm + wm + (lane >> 2);
    int cc = bn + wn + ((lane & 3) << 1);
    #pragma unroll
    for (int mt = 0; mt < 4; mt++) {
        #pragma unroll
        for (int nt = 0; nt < 4; nt++) {
            int row = r0 + mt * 16;
            int col = cc + nt * 8;
            *(float2*)(Pz + (size_t)row * N + col) = make_float2(acc[mt][nt][0], acc[mt][nt][1]);
            *(float2*)(Pz + (size_t)(row + 8) * N + col) = make_float2(acc[mt][nt][2], acc[mt][nt][3]);
        }
    }
}

// ---------------- split-K reduce: sum slices, relu, emit f32 or bf16 hi/lo ----------------
__global__ void reduce_split(const float* __restrict__ P, int mn4, int KS, int relu,
                             float* __restrict__ Cf, bf16* __restrict__ Ch,
                             bf16* __restrict__ Cl) {
    int i = blockIdx.x * 256 + threadIdx.x;
    if (i >= mn4) return;
    const float4* Pv = (const float4*)P;
    float4 a = Pv[i];
    for (int z = 1; z < KS; z++) {
        float4 b = Pv[(size_t)z * mn4 + i];
        a.x += b.x; a.y += b.y; a.z += b.z; a.w += b.w;
    }
    if (relu) {
        a.x = fmaxf(a.x, 0.f); a.y = fmaxf(a.y, 0.f);
        a.z = fmaxf(a.z, 0.f); a.w = fmaxf(a.w, 0.f);
    }
    if (Cf) {
        ((float4*)Cf)[i] = a;
    } else {
        uint32_t h01, l01, h23, l23;
        splitpack(a.x, a.y, h01, l01);
        splitpack(a.z, a.w, h23, l23);
        ((uint2*)Ch)[i] = make_uint2(h01, h23);
        ((uint2*)Cl)[i] = make_uint2(l01, l23);
    }
}

// ---------------- all weight splits in one launch ----------------
__global__ void splitw_all(const float* __restrict__ Wq, const float* __restrict__ Wk,
                           const float* __restrict__ Wv, const float* __restrict__ W1,
                           const float* __restrict__ W2) {
    int q = blockIdx.x * 256 + threadIdx.x;
    const float* src; bf16 *dh, *dl; int off;
    if (q < 65536)        { src = Wq; dh = g_wqh; dl = g_wql; off = q; }
    else if (q < 131072)  { src = Wk; dh = g_wkh; dl = g_wkl; off = q - 65536; }
    else if (q < 196608)  { src = Wv; dh = g_wvh; dl = g_wvl; off = q - 131072; }
    else if (q < 327680)  { src = W1; dh = g_w1h; dl = g_w1l; off = q - 196608; }
    else                  { src = W2; dh = g_w2h; dl = g_w2l; off = q - 327680; }
    float4 v = ((const float4*)src)[off];
    uint32_t h01, l01, h23, l23;
    splitpack(v.x, v.y, h01, l01);
    splitpack(v.z, v.w, h23, l23);
    *(uint2*)(dh + (size_t)off * 4) = make_uint2(h01, h23);
    *(uint2*)(dl + (size_t)off * 4) = make_uint2(l01, l23);
}

// ---------------- LayerNorm: 2 rows per 256-thread block -> bf16 hi/lo ----------------
__global__ void ln_kernel2(const float* __restrict__ x, const float* __restrict__ g,
                           const float* __restrict__ beta,
                           bf16* __restrict__ yh, bf16* __restrict__ yl) {
    __shared__ float sm[8];
    int half = threadIdx.x >> 7;
    int t = threadIdx.x & 127;
    size_t row = (size_t)blockIdx.x * 2 + half;
    float4 v = ((const float4*)(x + row * DIMc))[t];
    float s = v.x + v.y + v.z + v.w;
    #pragma unroll
    for (int o = 16; o; o >>= 1) s += __shfl_xor_sync(0xffffffffu, s, o);
    if ((t & 31) == 0) sm[threadIdx.x >> 5] = s;
    __syncthreads();
    int sb = half * 4;
    float mean = (sm[sb] + sm[sb + 1] + sm[sb + 2] + sm[sb + 3]) * (1.0f / DIMc);
    __syncthreads();
    float dx = v.x - mean, dy = v.y - mean, dz = v.z - mean, dw = v.w - mean;
    float sq = dx * dx + dy * dy + dz * dz + dw * dw;
    #pragma unroll
    for (int o = 16; o; o >>= 1) sq += __shfl_xor_sync(0xffffffffu, sq, o);
    if ((t & 31) == 0) sm[threadIdx.x >> 5] = sq;
    __syncthreads();
    float var = (sm[sb] + sm[sb + 1] + sm[sb + 2] + sm[sb + 3]) * (1.0f / DIMc);
    float rstd = rsqrtf(var + 1e-5f);
    float4 gg = ((const float4*)g)[t];
    float4 bb = ((const float4*)beta)[t];
    float o0 = dx * rstd * gg.x + bb.x;
    float o1 = dy * rstd * gg.y + bb.y;
    float o2 = dz * rstd * gg.z + bb.z;
    float o3 = dw * rstd * gg.w + bb.w;
    uint32_t h01, l01, h23, l23;
    splitpack(o0, o1, h01, l01);
    splitpack(o2, o3, h23, l23);
    *(uint2*)(yh + row * DIMc + t * 4) = make_uint2(h01, h23);
    *(uint2*)(yl + row * DIMc + t * 4) = make_uint2(l01, l23);
}

// ---------------- flash attention with 3xBF16 mma (NSPL=8 splits) ----------------
#define oQh   0
#define oQl   8192
#define oKh   16384
#define oKl   32768
#define oVh   49152
#define oVl   65536
#define oMsk  81920
#define oPmax 82432
#define oPsum 82944
#define ATT_SMEM 83456

__global__ void __launch_bounds__(256, 2) flash_attn_mma(
    const bf16* __restrict__ qh, const bf16* __restrict__ ql,
    const bf16* __restrict__ kh, const bf16* __restrict__ kl,
    const bf16* __restrict__ vh, const bf16* __restrict__ vl,
    const int* __restrict__ mask)
{
    extern __shared__ __align__(1024) char sm_[];
    uint32_t sb = smem_u32(sm_);
    int tid = threadIdx.x, lane = tid & 31, wid = tid >> 5;
    int wm = (wid & 3) << 4;
    int wn = wid >> 2;
    int c  = blockIdx.x & (NSPL - 1);
    int h  = (blockIdx.x >> 3) & 7;
    int b  = blockIdx.x >> 6;
    int pbase = (b * Hh + h) * NSPL + c;

    size_t qoff = (size_t)b * Qq * DIMc + h * DHh;
    size_t koff = (size_t)b * Ff * DIMc + h * DHh;
    const int* mrow = mask + (size_t)b * Ff;

    float* pmax = (float*)(sm_ + oPmax);
    float* psum = (float*)(sm_ + oPsum);
    int*   msk  = (int*)(sm_ + oMsk);

    #pragma unroll
    for (int r = 0; r < 2; r++) {
        int idx = r * 256 + tid;
        int row = idx >> 3, ch = idx & 7;
        uint32_t off = row * 128 + (ch << 4);
        uint32_t sw = off ^ ((off >> 3) & 0x70);
        cpa16(sb + oQh + sw, qh + qoff + (size_t)row * DIMc + ch * 8);
        cpa16(sb + oQl + sw, ql + qoff + (size_t)row * DIMc + ch * 8);
    }
    CPA_COMMIT();

    float m0 = -INFINITY, m1 = -INFINITY, l0 = 0.f, l1 = 0.f;
    float O[8][4];
    #pragma unroll
    for (int nt = 0; nt < 8; nt++)
        #pragma unroll
        for (int r = 0; r < 4; r++) O[nt][r] = 0.f;

    int quad = lane >> 3, rr = lane & 7;
    int lrow = ((quad & 1) << 3) + rr;
    int lcol = quad >> 1;
    int row0 = wm + (lane >> 2);
    int fbeg = c * FSEG;

    for (int f0 = fbeg; f0 < fbeg + FSEG; f0 += FCH) {
        __syncthreads();
        #pragma unroll
        for (int r = 0; r < 4; r++) {
            int idx = r * 256 + tid;
            int row = idx >> 3, ch = idx & 7;
            uint32_t off = row * 128 + (ch << 4);
            uint32_t sw = off ^ ((off >> 3) & 0x70);
            size_t g = koff + (size_t)(f0 + row) * DIMc + ch * 8;
            cpa16(sb + oKh + sw, kh + g);
            cpa16(sb + oKl + sw, kl + g);
            cpa16(sb + oVh + sw, vh + g);
            cpa16(sb + oVl + sw, vl + g);
        }
        CPA_COMMIT();
        if (tid < FCH) msk[tid] = mrow[f0 + tid];
        CPA_WAIT0();
        __syncthreads();

        float S[8][4];
        #pragma unroll
        for (int nt = 0; nt < 8; nt++)
            #pragma unroll
            for (int r = 0; r < 4; r++) S[nt][r] = 0.f;

        #pragma unroll
        for (int j = 0; j < 4; j++) {
            uint32_t qoffb = (uint32_t)(wm + lrow) * 128 + j * 32 + (lcol << 4);
            uint32_t qsw = qoffb ^ ((qoffb >> 3) & 0x70);
            uint32_t qhf[4], qlf[4];
            LDSM4(qhf[0], qhf[1], qhf[2], qhf[3], sb + oQh + qsw);
            LDSM4(qlf[0], qlf[1], qlf[2], qlf[3], sb + oQl + qsw);
            #pragma unroll
            for (int nt = 0; nt < 8; nt++) {
                int fr = wn * 64 + nt * 8 + (lane & 7);
                int seg = (lane >> 3) & 1;
                uint32_t boff = (uint32_t)fr * 128 + j * 32 + (seg << 4);
                uint32_t bsw = boff ^ ((boff >> 3) & 0x70);
                uint32_t kbh[2], kbl[2];
                LDSM2(kbh[0], kbh[1], sb + oKh + bsw);
                LDSM2(kbl[0], kbl[1], sb + oKl + bsw);
                MMA_BF16(S[nt], qhf, kbh);
                MMA_BF16(S[nt], qhf, kbl);
                MMA_BF16(S[nt], qlf, kbh);
            }
        }

        #pragma unroll
        for (int nt = 0; nt < 8; nt++) {
            int col0 = wn * 64 + nt * 8 + ((lane & 3) << 1);
            int mj0 = msk[col0], mj1 = msk[col0 + 1];
            S[nt][0] = mj0 ? S[nt][0] * 0.125f : -INFINITY;
            S[nt][2] = mj0 ? S[nt][2] * 0.125f : -INFINITY;
            S[nt][1] = mj1 ? S[nt][1] * 0.125f : -INFINITY;
            S[nt][3] = mj1 ? S[nt][3] * 0.125f : -INFINITY;
        }

        float rx0 = -INFINITY, rx1 = -INFINITY;
        #pragma unroll
        for (int nt = 0; nt < 8; nt++) {
            rx0 = fmaxf(rx0, fmaxf(S[nt][0], S[nt][1]));
            rx1 = fmaxf(rx1, fmaxf(S[nt][2], S[nt][3]));
        }
        rx0 = fmaxf(rx0, __shfl_xor_sync(0xffffffffu, rx0, 1));
        rx0 = fmaxf(rx0, __shfl_xor_sync(0xffffffffu, rx0, 2));
        rx1 = fmaxf(rx1, __shfl_xor_sync(0xffffffffu, rx1, 1));
        rx1 = fmaxf(rx1, __shfl_xor_sync(0xffffffffu, rx1, 2));
        if ((lane & 3) == 0) {
            pmax[wn * 64 + row0] = rx0;
            pmax[wn * 64 + row0 + 8] = rx1;
        }
        __syncthreads();
        float nm0 = fmaxf(m0, fmaxf(pmax[row0], pmax[64 + row0]));
        float nm1 = fmaxf(m1, fmaxf(pmax[row0 + 8], pmax[64 + row0 + 8]));
        float sf0 = (nm0 == -INFINITY) ? 1.f : __expf(m0 - nm0);
        float sf1 = (nm1 == -INFINITY) ? 1.f : __expf(m1 - nm1);

        float rs0 = 0.f, rs1 = 0.f;
        #pragma unroll
        for (int nt = 0; nt < 8; nt++) {
            float e0 = (S[nt][0] == -INFINITY) ? 0.f : __expf(S[nt][0] - nm0);
            float e1 = (S[nt][1] == -INFINITY) ? 0.f : __expf(S[nt][1] - nm0);
            float e2 = (S[nt][2] == -INFINITY) ? 0.f : __expf(S[nt][2] - nm1);
            float e3 = (S[nt][3] == -INFINITY) ? 0.f : __expf(S[nt][3] - nm1);
            S[nt][0] = e0; S[nt][1] = e1; S[nt][2] = e2; S[nt][3] = e3;
            rs0 += e0 + e1; rs1 += e2 + e3;
        }
        rs0 += __shfl_xor_sync(0xffffffffu, rs0, 1);
        rs0 += __shfl_xor_sync(0xffffffffu, rs0, 2);
        rs1 += __shfl_xor_sync(0xffffffffu, rs1, 1);
        rs1 += __shfl_xor_sync(0xffffffffu, rs1, 2);
        if ((lane & 3) == 0) {
            psum[wn * 64 + row0] = rs0;
            psum[wn * 64 + row0 + 8] = rs1;
        }
        __syncthreads();
        l0 = l0 * sf0 + psum[row0] + psum[64 + row0];
        l1 = l1 * sf1 + psum[row0 + 8] + psum[64 + row0 + 8];
        m0 = nm0; m1 = nm1;
        #pragma unroll
        for (int nt = 0; nt < 8; nt++) {
            O[nt][0] *= sf0; O[nt][1] *= sf0;
            O[nt][2] *= sf1; O[nt][3] *= sf1;
        }

        #pragma unroll
        for (int j = 0; j < 4; j++) {
            uint32_t pah[4], pal[4];
            splitpack(S[2 * j][0], S[2 * j][1], pah[0], pal[0]);
            splitpack(S[2 * j][2], S[2 * j][3], pah[1], pal[1]);
            splitpack(S[2 * j + 1][0], S[2 * j + 1][1], pah[2], pal[2]);
            splitpack(S[2 * j + 1][2], S[2 * j + 1][3], pah[3], pal[3]);
            uint32_t frow = (uint32_t)(wn * 64 + j * 16 + (lane & 15));
            #pragma unroll
            for (int nt = 0; nt < 8; nt++) {
                uint32_t off = frow * 128 + (nt << 4);
                uint32_t sw = off ^ ((off >> 3) & 0x70);
                uint32_t vbh[2], vbl[2];
                LDSM2T(vbh[0], vbh[1], sb + oVh + sw);
                LDSM2T(vbl[0], vbl[1], sb + oVl + sw);
                MMA_BF16(O[nt], pah, vbh);
                MMA_BF16(O[nt], pah, vbl);
                MMA_BF16(O[nt], pal, vbh);
            }
        }
    }

    __syncthreads();
    float* ob = (float*)(sm_ + oKh);
    float* obw = ob + wn * 4096;
    #pragma unroll
    for (int nt = 0; nt < 8; nt++) {
        int col = nt * 8 + ((lane & 3) << 1);
        obw[row0 * 64 + col] = O[nt][0];
        obw[row0 * 64 + col + 1] = O[nt][1];
        obw[(row0 + 8) * 64 + col] = O[nt][2];
        obw[(row0 + 8) * 64 + col + 1] = O[nt][3];
    }
    if ((lane & 3) == 0 && wn == 0) {
        g_pm[(size_t)pbase * Qq + row0] = m0;
        g_pl[(size_t)pbase * Qq + row0] = l0;
        g_pm[(size_t)pbase * Qq + row0 + 8] = m1;
        g_pl[(size_t)pbase * Qq + row0 + 8] = l1;
    }
    __syncthreads();
    #pragma unroll
    for (int r = 0; r < 16; r++) {
        int idx = r * 256 + tid;
        int qq = idx >> 6, dd = idx & 63;
        g_po[((size_t)pbase * Qq + qq) * DHh + dd] = ob[qq * 64 + dd] + ob[4096 + qq * 64 + dd];
    }
}

// ---------------- combine partials ----------------
__global__ void attn_combine(float* __restrict__ out) {
    int bh = blockIdx.x >> 6;
    int q  = blockIdx.x & 63;
    int b  = bh >> 3, h = bh & 7;
    int d  = threadIdx.x;

    float mc[NSPL], lc[NSPL];
    float M = -INFINITY;
    #pragma unroll
    for (int c = 0; c < NSPL; c++) {
        mc[c] = g_pm[((size_t)bh * NSPL + c) * Qq + q];
        lc[c] = g_pl[((size_t)bh * NSPL + c) * Qq + q];
        M = fmaxf(M, mc[c]);
    }
    float r = 0.f;
    if (M != -INFINITY) {
        float num = 0.f, den = 0.f;
        #pragma unroll
        for (int c = 0; c < NSPL; c++) {
            if (mc[c] != -INFINITY) {
                float w = __expf(mc[c] - M);
                den += w * lc[c];
                num += w * g_po[(((size_t)bh * NSPL + c) * Qq + q) * DHh + d];
            }
        }
        r = (den > 0.f) ? num / den : 0.f;
    }
    out[((size_t)(b * Qq + q)) * DIMc + h * DHh + d] = r;
}

// ---------------- launch ----------------
extern "C" void kernel_launch(void* const* d_in, const int* in_sizes, int n_in,
                              void* d_out, int out_size) {
    const float* features = (const float*)d_in[0];
    const float* latents  = (const float*)d_in[1];
    const int*   mask     = (const int*)  d_in[2];
    const float* gf  = (const float*)d_in[3];
    const float* bf  = (const float*)d_in[4];
    const float* gl  = (const float*)d_in[5];
    const float* bl  = (const float*)d_in[6];
    const float* Wq  = (const float*)d_in[7];
    const float* Wk  = (const float*)d_in[8];
    const float* Wv  = (const float*)d_in[9];
    const float* gff = (const float*)d_in[10];
    const float* bff = (const float*)d_in[11];
    const float* W1  = (const float*)d_in[12];
    const float* W2  = (const float*)d_in[13];
    float* out = (float*)d_out;

    bf16 *xnh, *xnl, *lath, *latl, *ln2h, *ln2l, *ffhh, *ffhl;
    bf16 *wqh, *wql, *wkh, *wkl, *wvh, *wvl, *w1h, *w1l, *w2h, *w2l;
    bf16 *qh, *ql, *kh, *kl, *vh, *vl;
    float *att, *part;
    cudaGetSymbolAddress((void**)&xnh,  g_xnh);  cudaGetSymbolAddress((void**)&xnl,  g_xnl);
    cudaGetSymbolAddress((void**)&lath, g_lath); cudaGetSymbolAddress((void**)&latl, g_latl);
    cudaGetSymbolAddress((void**)&ln2h, g_ln2h); cudaGetSymbolAddress((void**)&ln2l, g_ln2l);
    cudaGetSymbolAddress((void**)&ffhh, g_ffhh); cudaGetSymbolAddress((void**)&ffhl, g_ffhl);
    cudaGetSymbolAddress((void**)&wqh, g_wqh); cudaGetSymbolAddress((void**)&wql, g_wql);
    cudaGetSymbolAddress((void**)&wkh, g_wkh); cudaGetSymbolAddress((void**)&wkl, g_wkl);
    cudaGetSymbolAddress((void**)&wvh, g_wvh); cudaGetSymbolAddress((void**)&wvl, g_wvl);
    cudaGetSymbolAddress((void**)&w1h, g_w1h); cudaGetSymbolAddress((void**)&w1l, g_w1l);
    cudaGetSymbolAddress((void**)&w2h, g_w2h); cudaGetSymbolAddress((void**)&w2l, g_w2l);
    cudaGetSymbolAddress((void**)&qh, g_qh);  cudaGetSymbolAddress((void**)&ql, g_ql2);
    cudaGetSymbolAddress((void**)&kh, g_kh);  cudaGetSymbolAddress((void**)&kl, g_kl2);
    cudaGetSymbolAddress((void**)&vh, g_vh);  cudaGetSymbolAddress((void**)&vl, g_vl2);
    cudaGetSymbolAddress((void**)&att, g_att);
    cudaGetSymbolAddress((void**)&part, g_part);

    cudaFuncSetAttribute(bf16_gemm, cudaFuncAttributeMaxDynamicSharedMemorySize, GEMM_SMEM);
    cudaFuncSetAttribute(bf16_gemm_splitk, cudaFuncAttributeMaxDynamicSharedMemorySize, GEMM_SMEM);
    cudaFuncSetAttribute(flash_attn_mma, cudaFuncAttributeMaxDynamicSharedMemorySize, ATT_SMEM);

    // all weight splits, one launch
    splitw_all<<<1792, 256>>>(Wq, Wk, Wv, W1, W2);

    // layernorms (2 rows/block)
    ln_kernel2<<<Bb * Ff / 2, 256>>>(features, gf, bf, xnh, xnl);
    ln_kernel2<<<Bb * Qq / 2, 256>>>(latents,  gl, bl, lath, latl);

    // Q projection: split-K x2 + reduce
    bf16_gemm_splitk<<<dim3(DIMc / 128, (Bb * Qq) / 128, 2), 256, GEMM_SMEM>>>(
        lath, latl, wqh, wql, part, Bb * Qq, DIMc, DIMc, DIMc / 2);
    reduce_split<<<(Bb * Qq * DIMc / 4 + 255) / 256, 256>>>(
        part, Bb * Qq * DIMc / 4, 2, 0, nullptr, qh, ql);

    // K, V projections (big kernel, unchanged)
    bf16_gemm<<<dim3(DIMc / 128, (Bb * Ff) / 128), 256, GEMM_SMEM>>>(
        xnh, xnl, wkh, wkl, nullptr, kh, kl, Bb * Ff, DIMc, DIMc, 0);
    bf16_gemm<<<dim3(DIMc / 128, (Bb * Ff) / 128), 256, GEMM_SMEM>>>(
        xnh, xnl, wvh, wvl, nullptr, vh, vl, Bb * Ff, DIMc, DIMc, 0);

    // attention (mma split-F x8 + combine)
    flash_attn_mma<<<Bb * Hh * NSPL, 256, ATT_SMEM>>>(qh, ql, kh, kl, vh, vl, mask);
    attn_combine<<<Bb * Hh * Qq, DHh>>>(att);

    // feed-forward: LN, FF1 split-K x2 (+relu), FF2 split-K x4 -> out
    ln_kernel2<<<Bb * Qq / 2, 256>>>(att, gff, bff, ln2h, ln2l);
    bf16_gemm_splitk<<<dim3(1024 / 128, (Bb * Qq) / 128, 2), 256, GEMM_SMEM>>>(
        ln2h, ln2l, w1h, w1l, part, Bb * Qq, 1024, DIMc, DIMc / 2);
    reduce_split<<<(Bb * Qq * 1024 / 4 + 255) / 256, 256>>>(
        part, Bb * Qq * 1024 / 4, 2, 1, nullptr, ffhh, ffhl);
    bf16_gemm_splitk<<<dim3(DIMc / 128, (Bb * Qq) / 128, 4), 256, GEMM_SMEM>>>(
        ffhh, ffhl, w2h, w2l, part, Bb * Qq, DIMc, 1024, 256);
    reduce_split<<<(Bb * Qq * DIMc / 4 + 255) / 256, 256>>>(
        part, Bb * Qq * DIMc / 4, 4, 0, out, nullptr, nullptr);
}

// round 14
// speedup vs baseline: 2.3714x; 2.3714x over previous
#include <cuda_runtime.h>
#include <cuda_bf16.h>
#include <cstdint>
#include <math.h>

#define Bb   16
#define Ff   4096
#define Qq   64
#define DIMc 512
#define Hh   8
#define DHh  64
#define FCH  128
#define NSPL 8
#define FSEG (Ff / NSPL)

typedef __nv_bfloat16 bf16;
typedef __nv_bfloat162 bf162;

// ---------------- scratch (device globals; no allocation allowed) ----------------
__device__ bf16  g_xnh [(size_t)Bb * Ff * DIMc];
__device__ bf16  g_xnl [(size_t)Bb * Ff * DIMc];
__device__ bf16  g_lath[(size_t)Bb * Qq * DIMc];
__device__ bf16  g_latl[(size_t)Bb * Qq * DIMc];
__device__ bf16  g_ln2h[(size_t)Bb * Qq * DIMc];
__device__ bf16  g_ln2l[(size_t)Bb * Qq * DIMc];
__device__ bf16  g_ffhh[(size_t)Bb * Qq * 1024];
__device__ bf16  g_ffhl[(size_t)Bb * Qq * 1024];
__device__ bf16  g_wqh[DIMc * DIMc], g_wql[DIMc * DIMc];
__device__ bf16  g_wkh[DIMc * DIMc], g_wkl[DIMc * DIMc];
__device__ bf16  g_wvh[DIMc * DIMc], g_wvl[DIMc * DIMc];
__device__ bf16  g_w1h[DIMc * 1024], g_w1l[DIMc * 1024];
__device__ bf16  g_w2h[1024 * DIMc], g_w2l[1024 * DIMc];
__device__ bf16  g_qh [(size_t)Bb * Qq * DIMc], g_ql2[(size_t)Bb * Qq * DIMc];
__device__ bf16  g_kh [(size_t)Bb * Ff * DIMc], g_kl2[(size_t)Bb * Ff * DIMc];
__device__ bf16  g_vh [(size_t)Bb * Ff * DIMc], g_vl2[(size_t)Bb * Ff * DIMc];
__device__ float g_att[(size_t)Bb * Qq * DIMc];
__device__ float g_po [(size_t)Bb * Hh * NSPL * Qq * DHh];
__device__ float g_pm [(size_t)Bb * Hh * NSPL * Qq];
__device__ float g_pl [(size_t)Bb * Hh * NSPL * Qq];
__device__ int   g_idx[Bb * Ff];
__device__ int   g_cnt[Bb];

// ---------------- helpers ----------------
static __device__ __forceinline__ uint32_t smem_u32(const void* p) {
    uint32_t a;
    asm("{ .reg .u64 t; cvta.to.shared.u64 t, %1; cvt.u32.u64 %0, t; }" : "=r"(a) : "l"(p));
    return a;
}
static __device__ __forceinline__ void cpa16(uint32_t dst, const void* src) {
    asm volatile("cp.async.cg.shared.global [%0], [%1], 16;" :: "r"(dst), "l"(src));
}
#define CPA_COMMIT() asm volatile("cp.async.commit_group;" ::: "memory")
#define CPA_WAIT1()  asm volatile("cp.async.wait_group 1;" ::: "memory")
#define CPA_WAIT0()  asm volatile("cp.async.wait_group 0;" ::: "memory")

#define LDSM4(r0, r1, r2, r3, addr)                                        \
    asm volatile("ldmatrix.sync.aligned.m8n8.x4.shared.b16 {%0,%1,%2,%3}, [%4];" \
                 : "=r"(r0), "=r"(r1), "=r"(r2), "=r"(r3) : "r"(addr))

#define LDSM2(r0, r1, addr)                                                \
    asm volatile("ldmatrix.sync.aligned.m8n8.x2.shared.b16 {%0,%1}, [%2];" \
                 : "=r"(r0), "=r"(r1) : "r"(addr))

#define LDSM2T(r0, r1, addr)                                               \
    asm volatile("ldmatrix.sync.aligned.m8n8.x2.trans.shared.b16 {%0,%1}, [%2];" \
                 : "=r"(r0), "=r"(r1) : "r"(addr))

#define MMA_BF16(c, a, b)                                                  \
    asm volatile("mma.sync.aligned.m16n8k16.row.col.f32.bf16.bf16.f32 "    \
                 "{%0,%1,%2,%3}, {%4,%5,%6,%7}, {%8,%9}, {%0,%1,%2,%3};"   \
                 : "+f"((c)[0]), "+f"((c)[1]), "+f"((c)[2]), "+f"((c)[3])  \
                 : "r"((a)[0]), "r"((a)[1]), "r"((a)[2]), "r"((a)[3]),     \
                   "r"((b)[0]), "r"((b)[1]))

static __device__ __forceinline__ void bf16_split(float x, bf16& h, bf16& l) {
    h = __float2bfloat16(x);
    l = __float2bfloat16(x - __bfloat162float(h));
}
static __device__ __forceinline__ void splitpack(float p0, float p1,
                                                 uint32_t& hi, uint32_t& lo) {
    bf16 h0, l0, h1, l1;
    bf16_split(p0, h0, l0);
    bf16_split(p1, h1, l1);
    bf162 H; H.x = h0; H.y = h1;
    bf162 L; L.x = l0; L.y = l1;
    hi = *(uint32_t*)&H;
    lo = *(uint32_t*)&L;
}

// ---------------- mask compaction: per-batch prefix scan ----------------
__global__ void build_idx(const int* __restrict__ mask) {
    __shared__ int ws[32];
    int b = blockIdx.x;
    const int* m = mask + b * Ff;
    int t = threadIdx.x;                  // 0..1023, 4 elements each
    int v[4];
    int s = 0;
    #pragma unroll
    for (int i = 0; i < 4; i++) { v[i] = m[t * 4 + i]; s += v[i]; }
    int lane = t & 31, w = t >> 5;
    int ps = s;
    #pragma unroll
    for (int o = 1; o < 32; o <<= 1) {
        int n = __shfl_up_sync(0xffffffffu, ps, o);
        if (lane >= o) ps += n;
    }
    if (lane == 31) ws[w] = ps;
    __syncthreads();
    if (w == 0) {
        int x = ws[lane];
        #pragma unroll
        for (int o = 1; o < 32; o <<= 1) {
            int n = __shfl_up_sync(0xffffffffu, x, o);
            if (lane >= o) x += n;
        }
        ws[lane] = x;
    }
    __syncthreads();
    int base = ps - s + (w ? ws[w - 1] : 0);   // exclusive prefix
    #pragma unroll
    for (int i = 0; i < 4; i++) {
        if (v[i]) { g_idx[b * Ff + base] = t * 4 + i; base++; }
    }
    if (t == 1023) g_cnt[b] = ws[31];
}

// ---------------- 3xBF16 mma GEMM (exact R12 kernel) ----------------
#define STAGE_B    32768
#define GEMM_SMEM  (3 * STAGE_B)

__global__ void __launch_bounds__(256, 2) bf16_gemm(
    const bf16* __restrict__ Ah, const bf16* __restrict__ Al,
    const bf16* __restrict__ Wh, const bf16* __restrict__ Wl,
    float* __restrict__ Cf, bf16* __restrict__ Ch, bf16* __restrict__ Cl,
    int M, int N, int K, int relu)
{
    extern __shared__ __align__(1024) char smem[];
    int tid = threadIdx.x;
    int lane = tid & 31, wid = tid >> 5;
    int bn = blockIdx.x << 7, bm = blockIdx.y << 7;
    uint32_t sbase = smem_u32(smem);

    int wm = (wid & 1) << 6;
    int wn = (wid >> 1) << 5;

    float acc[4][4][4];
    #pragma unroll
    for (int i = 0; i < 4; i++)
        #pragma unroll
        for (int j = 0; j < 4; j++)
            #pragma unroll
            for (int r = 0; r < 4; r++) acc[i][j][r] = 0.f;

    int nCh = K >> 5;

    auto issue = [&](int p, int s) {
        uint32_t st = sbase + s * STAGE_B;
        int k0 = p << 5;
        #pragma unroll
        for (int r = 0; r < 2; r++) {
            int c = r * 256 + tid;
            int m = c >> 2, c4 = c & 3;
            uint32_t off = m * 64 + (c4 << 4);
            uint32_t sw = off ^ ((off >> 3) & 0x30);
            cpa16(st + sw, Ah + (size_t)(bm + m) * K + k0 + c4 * 8);
            cpa16(st + 8192 + sw, Al + (size_t)(bm + m) * K + k0 + c4 * 8);
        }
        #pragma unroll
        for (int r = 0; r < 2; r++) {
            int c = r * 256 + tid;
            int kk = c >> 4, c16 = c & 15;
            uint32_t off = kk * 256 + (c16 << 4);
            uint32_t sw = off ^ ((off >> 4) & 0x70);
            cpa16(st + 16384 + sw, Wh + (size_t)(k0 + kk) * N + bn + c16 * 8);
            cpa16(st + 24576 + sw, Wl + (size_t)(k0 + kk) * N + bn + c16 * 8);
        }
        CPA_COMMIT();
    };

    issue(0, 0);
    if (nCh > 1) issue(1, 1); else CPA_COMMIT();

    int quad = lane >> 3, rr = lane & 7;
    int lrow = ((quad & 1) << 3) + rr;
    int lcol = quad >> 1;
    int bl16 = lane & 15;

    for (int p = 0; p < nCh; p++) {
        CPA_WAIT1();
        __syncthreads();
        int s = p % 3;
        uint32_t aHi = sbase + s * STAGE_B;
        uint32_t aLo = aHi + 8192;
        uint32_t bHi = aHi + 16384;
        uint32_t bLo = aHi + 24576;

        #pragma unroll
        for (int j = 0; j < 2; j++) {
            uint32_t ahf[4][4], alf[4][4];
            #pragma unroll
            for (int mt = 0; mt < 4; mt++) {
                uint32_t off = (uint32_t)(wm + mt * 16 + lrow) * 64 + j * 32 + (lcol << 4);
                uint32_t sw = off ^ ((off >> 3) & 0x30);
                LDSM4(ahf[mt][0], ahf[mt][1], ahf[mt][2], ahf[mt][3], aHi + sw);
                LDSM4(alf[mt][0], alf[mt][1], alf[mt][2], alf[mt][3], aLo + sw);
            }
            uint32_t bhf[4][2], blf[4][2];
            {
                uint32_t krow = j * 16 + bl16;
                #pragma unroll
                for (int nt = 0; nt < 4; nt++) {
                    uint32_t off = krow * 256 + (uint32_t)(wn + nt * 8) * 2;
                    uint32_t sw = off ^ ((off >> 4) & 0x70);
                    LDSM2T(bhf[nt][0], bhf[nt][1], bHi + sw);
                    LDSM2T(blf[nt][0], blf[nt][1], bLo + sw);
                }
            }
            #pragma unroll
            for (int mt = 0; mt < 4; mt++)
                #pragma unroll
                for (int nt = 0; nt < 4; nt++) {
                    MMA_BF16(acc[mt][nt], ahf[mt], bhf[nt]);
                    MMA_BF16(acc[mt][nt], ahf[mt], blf[nt]);
                    MMA_BF16(acc[mt][nt], alf[mt], bhf[nt]);
                }
        }
        if (p + 2 < nCh) issue(p + 2, (p + 2) % 3);
        else CPA_COMMIT();
    }

    int r0 = bm + wm + (lane >> 2);
    int cc = bn + wn + ((lane & 3) << 1);
    #pragma unroll
    for (int mt = 0; mt < 4; mt++) {
        #pragma unroll
        for (int nt = 0; nt < 4; nt++) {
            float v0 = acc[mt][nt][0], v1 = acc[mt][nt][1];
            float v2 = acc[mt][nt][2], v3 = acc[mt][nt][3];
            if (relu) {
                v0 = fmaxf(v0, 0.f); v1 = fmaxf(v1, 0.f);
                v2 = fmaxf(v2, 0.f); v3 = fmaxf(v3, 0.f);
            }
            int row = r0 + mt * 16;
            int col = cc + nt * 8;
            if (Cf) {
                *(float2*)(Cf + (size_t)row * N + col) = make_float2(v0, v1);
                *(float2*)(Cf + (size_t)(row + 8) * N + col) = make_float2(v2, v3);
            } else {
                uint32_t ph, pl;
                splitpack(v0, v1, ph, pl);
                *(uint32_t*)(Ch + (size_t)row * N + col) = ph;
                *(uint32_t*)(Cl + (size_t)row * N + col) = pl;
                splitpack(v2, v3, ph, pl);
                *(uint32_t*)(Ch + (size_t)(row + 8) * N + col) = ph;
                *(uint32_t*)(Cl + (size_t)(row + 8) * N + col) = pl;
            }
        }
    }
}

// ---------------- same GEMM with per-batch count early-exit (K/V projections) ----------------
// grid.y = b*32 + t over (16 batches x 32 row-tiles); tile skipped if fully beyond cnt[b].
__global__ void __launch_bounds__(256, 2) bf16_gemm_cnt(
    const bf16* __restrict__ Ah, const bf16* __restrict__ Al,
    const bf16* __restrict__ Wh, const bf16* __restrict__ Wl,
    bf16* __restrict__ Ch, bf16* __restrict__ Cl,
    int N, int K)
{
    if (((int)(blockIdx.y & 31) << 7) >= g_cnt[blockIdx.y >> 5]) return;

    extern __shared__ __align__(1024) char smem[];
    int tid = threadIdx.x;
    int lane = tid & 31, wid = tid >> 5;
    int bn = blockIdx.x << 7, bm = blockIdx.y << 7;
    uint32_t sbase = smem_u32(smem);

    int wm = (wid & 1) << 6;
    int wn = (wid >> 1) << 5;

    float acc[4][4][4];
    #pragma unroll
    for (int i = 0; i < 4; i++)
        #pragma unroll
        for (int j = 0; j < 4; j++)
            #pragma unroll
            for (int r = 0; r < 4; r++) acc[i][j][r] = 0.f;

    int nCh = K >> 5;

    auto issue = [&](int p, int s) {
        uint32_t st = sbase + s * STAGE_B;
        int k0 = p << 5;
        #pragma unroll
        for (int r = 0; r < 2; r++) {
            int c = r * 256 + tid;
            int m = c >> 2, c4 = c & 3;
            uint32_t off = m * 64 + (c4 << 4);
            uint32_t sw = off ^ ((off >> 3) & 0x30);
            cpa16(st + sw, Ah + (size_t)(bm + m) * K + k0 + c4 * 8);
            cpa16(st + 8192 + sw, Al + (size_t)(bm + m) * K + k0 + c4 * 8);
        }
        #pragma unroll
        for (int r = 0; r < 2; r++) {
            int c = r * 256 + tid;
            int kk = c >> 4, c16 = c & 15;
            uint32_t off = kk * 256 + (c16 << 4);
            uint32_t sw = off ^ ((off >> 4) & 0x70);
            cpa16(st + 16384 + sw, Wh + (size_t)(k0 + kk) * N + bn + c16 * 8);
            cpa16(st + 24576 + sw, Wl + (size_t)(k0 + kk) * N + bn + c16 * 8);
        }
        CPA_COMMIT();
    };

    issue(0, 0);
    if (nCh > 1) issue(1, 1); else CPA_COMMIT();

    int quad = lane >> 3, rr = lane & 7;
    int lrow = ((quad & 1) << 3) + rr;
    int lcol = quad >> 1;
    int bl16 = lane & 15;

    for (int p = 0; p < nCh; p++) {
        CPA_WAIT1();
        __syncthreads();
        int s = p % 3;
        uint32_t aHi = sbase + s * STAGE_B;
        uint32_t aLo = aHi + 8192;
        uint32_t bHi = aHi + 16384;
        uint32_t bLo = aHi + 24576;

        #pragma unroll
        for (int j = 0; j < 2; j++) {
            uint32_t ahf[4][4], alf[4][4];
            #pragma unroll
            for (int mt = 0; mt < 4; mt++) {
                uint32_t off = (uint32_t)(wm + mt * 16 + lrow) * 64 + j * 32 + (lcol << 4);
                uint32_t sw = off ^ ((off >> 3) & 0x30);
                LDSM4(ahf[mt][0], ahf[mt][1], ahf[mt][2], ahf[mt][3], aHi + sw);
                LDSM4(alf[mt][0], alf[mt][1], alf[mt][2], alf[mt][3], aLo + sw);
            }
            uint32_t bhf[4][2], blf[4][2];
            {
                uint32_t krow = j * 16 + bl16;
                #pragma unroll
                for (int nt = 0; nt < 4; nt++) {
                    uint32_t off = krow * 256 + (uint32_t)(wn + nt * 8) * 2;
                    uint32_t sw = off ^ ((off >> 4) & 0x70);
                    LDSM2T(bhf[nt][0], bhf[nt][1], bHi + sw);
                    LDSM2T(blf[nt][0], blf[nt][1], bLo + sw);
                }
            }
            #pragma unroll
            for (int mt = 0; mt < 4; mt++)
                #pragma unroll
                for (int nt = 0; nt < 4; nt++) {
                    MMA_BF16(acc[mt][nt], ahf[mt], bhf[nt]);
                    MMA_BF16(acc[mt][nt], ahf[mt], blf[nt]);
                    MMA_BF16(acc[mt][nt], alf[mt], bhf[nt]);
                }
        }
        if (p + 2 < nCh) issue(p + 2, (p + 2) % 3);
        else CPA_COMMIT();
    }

    int r0 = bm + wm + (lane >> 2);
    int cc = bn + wn + ((lane & 3) << 1);
    #pragma unroll
    for (int mt = 0; mt < 4; mt++) {
        #pragma unroll
        for (int nt = 0; nt < 4; nt++) {
            int row = r0 + mt * 16;
            int col = cc + nt * 8;
            uint32_t ph, pl;
            splitpack(acc[mt][nt][0], acc[mt][nt][1], ph, pl);
            *(uint32_t*)(Ch + (size_t)row * N + col) = ph;
            *(uint32_t*)(Cl + (size_t)row * N + col) = pl;
            splitpack(acc[mt][nt][2], acc[mt][nt][3], ph, pl);
            *(uint32_t*)(Ch + (size_t)(row + 8) * N + col) = ph;
            *(uint32_t*)(Cl + (size_t)(row + 8) * N + col) = pl;
        }
    }
}

// ---------------- all weight splits in one launch ----------------
__global__ void splitw_all(const float* __restrict__ Wq, const float* __restrict__ Wk,
                           const float* __restrict__ Wv, const float* __restrict__ W1,
                           const float* __restrict__ W2) {
    int q = blockIdx.x * 256 + threadIdx.x;
    const float* src; bf16 *dh, *dl; int off;
    if (q < 65536)        { src = Wq; dh = g_wqh; dl = g_wql; off = q; }
    else if (q < 131072)  { src = Wk; dh = g_wkh; dl = g_wkl; off = q - 65536; }
    else if (q < 196608)  { src = Wv; dh = g_wvh; dl = g_wvl; off = q - 131072; }
    else if (q < 327680)  { src = W1; dh = g_w1h; dl = g_w1l; off = q - 196608; }
    else                  { src = W2; dh = g_w2h; dl = g_w2l; off = q - 327680; }
    float4 v = ((const float4*)src)[off];
    uint32_t h01, l01, h23, l23;
    splitpack(v.x, v.y, h01, l01);
    splitpack(v.z, v.w, h23, l23);
    *(uint2*)(dh + (size_t)off * 4) = make_uint2(h01, h23);
    *(uint2*)(dl + (size_t)off * 4) = make_uint2(l01, l23);
}

// ---------------- LayerNorm: 2 rows per block -> bf16 hi/lo ----------------
__global__ void ln_kernel2(const float* __restrict__ x, const float* __restrict__ g,
                           const float* __restrict__ beta,
                           bf16* __restrict__ yh, bf16* __restrict__ yl) {
    __shared__ float sm[8];
    int half = threadIdx.x >> 7;
    int t = threadIdx.x & 127;
    size_t row = (size_t)blockIdx.x * 2 + half;
    float4 v = ((const float4*)(x + row * DIMc))[t];
    float s = v.x + v.y + v.z + v.w;
    #pragma unroll
    for (int o = 16; o; o >>= 1) s += __shfl_xor_sync(0xffffffffu, s, o);
    if ((t & 31) == 0) sm[threadIdx.x >> 5] = s;
    __syncthreads();
    int sb = half * 4;
    float mean = (sm[sb] + sm[sb + 1] + sm[sb + 2] + sm[sb + 3]) * (1.0f / DIMc);
    __syncthreads();
    float dx = v.x - mean, dy = v.y - mean, dz = v.z - mean, dw = v.w - mean;
    float sq = dx * dx + dy * dy + dz * dz + dw * dw;
    #pragma unroll
    for (int o = 16; o; o >>= 1) sq += __shfl_xor_sync(0xffffffffu, sq, o);
    if ((t & 31) == 0) sm[threadIdx.x >> 5] = sq;
    __syncthreads();
    float var = (sm[sb] + sm[sb + 1] + sm[sb + 2] + sm[sb + 3]) * (1.0f / DIMc);
    float rstd = rsqrtf(var + 1e-5f);
    float4 gg = ((const float4*)g)[t];
    float4 bb = ((const float4*)beta)[t];
    float o0 = dx * rstd * gg.x + bb.x;
    float o1 = dy * rstd * gg.y + bb.y;
    float o2 = dz * rstd * gg.z + bb.z;
    float o3 = dw * rstd * gg.w + bb.w;
    uint32_t h01, l01, h23, l23;
    splitpack(o0, o1, h01, l01);
    splitpack(o2, o3, h23, l23);
    *(uint2*)(yh + row * DIMc + t * 4) = make_uint2(h01, h23);
    *(uint2*)(yl + row * DIMc + t * 4) = make_uint2(l01, l23);
}

// ---------------- LN + gather: compacted feature rows; zero-fill padding ----------------
__global__ void ln_gather(const float* __restrict__ x, const float* __restrict__ g,
                          const float* __restrict__ beta,
                          bf16* __restrict__ yh, bf16* __restrict__ yl) {
    __shared__ float sm[8];
    int half = threadIdx.x >> 7;
    int t = threadIdx.x & 127;
    size_t row = (size_t)blockIdx.x * 2 + half;   // compacted row index (b*Ff + r)
    int b = (int)(row >> 12);
    int r = (int)(row & (Ff - 1));
    if (r >= g_cnt[b]) {
        *(uint2*)(yh + row * DIMc + t * 4) = make_uint2(0u, 0u);
        *(uint2*)(yl + row * DIMc + t * 4) = make_uint2(0u, 0u);
        return;
    }
    size_t src = (size_t)b * Ff + g_idx[b * Ff + r];
    float4 v = ((const float4*)(x + src * DIMc))[t];
    float s = v.x + v.y + v.z + v.w;
    #pragma unroll
    for (int o = 16; o; o >>= 1) s += __shfl_xor_sync(0xffffffffu, s, o);
    if ((t & 31) == 0) sm[threadIdx.x >> 5] = s;
    __syncthreads();
    int sb = half * 4;
    float mean = (sm[sb] + sm[sb + 1] + sm[sb + 2] + sm[sb + 3]) * (1.0f / DIMc);
    __syncthreads();
    float dx = v.x - mean, dy = v.y - mean, dz = v.z - mean, dw = v.w - mean;
    float sq = dx * dx + dy * dy + dz * dz + dw * dw;
    #pragma unroll
    for (int o = 16; o; o >>= 1) sq += __shfl_xor_sync(0xffffffffu, sq, o);
    if ((t & 31) == 0) sm[threadIdx.x >> 5] = sq;
    __syncthreads();
    float var = (sm[sb] + sm[sb + 1] + sm[sb + 2] + sm[sb + 3]) * (1.0f / DIMc);
    float rstd = rsqrtf(var + 1e-5f);
    float4 gg = ((const float4*)g)[t];
    float4 bb = ((const float4*)beta)[t];
    float o0 = dx * rstd * gg.x + bb.x;
    float o1 = dy * rstd * gg.y + bb.y;
    float o2 = dz * rstd * gg.z + bb.z;
    float o3 = dw * rstd * gg.w + bb.w;
    uint32_t h01, l01, h23, l23;
    splitpack(o0, o1, h01, l01);
    splitpack(o2, o3, h23, l23);
    *(uint2*)(yh + row * DIMc + t * 4) = make_uint2(h01, h23);
    *(uint2*)(yl + row * DIMc + t * 4) = make_uint2(l01, l23);
}

// ---------------- flash attention over compacted F (count-masked) ----------------
#define oQh   0
#define oQl   8192
#define oKh   16384
#define oKl   32768
#define oVh   49152
#define oVl   65536
#define oPmax 81920
#define oPsum 82432
#define ATT_SMEM 82944

__global__ void __launch_bounds__(256, 2) flash_attn_mma(
    const bf16* __restrict__ qh, const bf16* __restrict__ ql,
    const bf16* __restrict__ kh, const bf16* __restrict__ kl,
    const bf16* __restrict__ vh, const bf16* __restrict__ vl)
{
    extern __shared__ __align__(1024) char sm_[];
    uint32_t sb = smem_u32(sm_);
    int tid = threadIdx.x, lane = tid & 31, wid = tid >> 5;
    int wm = (wid & 3) << 4;
    int wn = wid >> 2;
    int c  = blockIdx.x & (NSPL - 1);
    int h  = (blockIdx.x >> 3) & 7;
    int b  = blockIdx.x >> 6;
    int pbase = (b * Hh + h) * NSPL + c;
    int cnt = g_cnt[b];

    size_t qoff = (size_t)b * Qq * DIMc + h * DHh;
    size_t koff = (size_t)b * Ff * DIMc + h * DHh;

    float* pmax = (float*)(sm_ + oPmax);
    float* psum = (float*)(sm_ + oPsum);

    #pragma unroll
    for (int r = 0; r < 2; r++) {
        int idx = r * 256 + tid;
        int row = idx >> 3, ch = idx & 7;
        uint32_t off = row * 128 + (ch << 4);
        uint32_t sw = off ^ ((off >> 3) & 0x70);
        cpa16(sb + oQh + sw, qh + qoff + (size_t)row * DIMc + ch * 8);
        cpa16(sb + oQl + sw, ql + qoff + (size_t)row * DIMc + ch * 8);
    }
    CPA_COMMIT();

    float m0 = -INFINITY, m1 = -INFINITY, l0 = 0.f, l1 = 0.f;
    float O[8][4];
    #pragma unroll
    for (int nt = 0; nt < 8; nt++)
        #pragma unroll
        for (int r = 0; r < 4; r++) O[nt][r] = 0.f;

    int quad = lane >> 3, rr = lane & 7;
    int lrow = ((quad & 1) << 3) + rr;
    int lcol = quad >> 1;
    int row0 = wm + (lane >> 2);
    int fbeg = c * FSEG;

    for (int f0 = fbeg; f0 < fbeg + FSEG; f0 += FCH) {
        if (f0 >= cnt) break;                       // compacted: nothing beyond cnt
        __syncthreads();
        #pragma unroll
        for (int r = 0; r < 4; r++) {
            int idx = r * 256 + tid;
            int row = idx >> 3, ch = idx & 7;
            uint32_t off = row * 128 + (ch << 4);
            uint32_t sw = off ^ ((off >> 3) & 0x70);
            size_t g = koff + (size_t)(f0 + row) * DIMc + ch * 8;
            cpa16(sb + oKh + sw, kh + g);
            cpa16(sb + oKl + sw, kl + g);
            cpa16(sb + oVh + sw, vh + g);
            cpa16(sb + oVl + sw, vl + g);
        }
        CPA_COMMIT();
        CPA_WAIT0();
        __syncthreads();

        float S[8][4];
        #pragma unroll
        for (int nt = 0; nt < 8; nt++)
            #pragma unroll
            for (int r = 0; r < 4; r++) S[nt][r] = 0.f;

        #pragma unroll
        for (int j = 0; j < 4; j++) {
            uint32_t qoffb = (uint32_t)(wm + lrow) * 128 + j * 32 + (lcol << 4);
            uint32_t qsw = qoffb ^ ((qoffb >> 3) & 0x70);
            uint32_t qhf[4], qlf[4];
            LDSM4(qhf[0], qhf[1], qhf[2], qhf[3], sb + oQh + qsw);
            LDSM4(qlf[0], qlf[1], qlf[2], qlf[3], sb + oQl + qsw);
            #pragma unroll
            for (int nt = 0; nt < 8; nt++) {
                int fr = wn * 64 + nt * 8 + (lane & 7);
                int seg = (lane >> 3) & 1;
                uint32_t boff = (uint32_t)fr * 128 + j * 32 + (seg << 4);
                uint32_t bsw = boff ^ ((boff >> 3) & 0x70);
                uint32_t kbh[2], kbl[2];
                LDSM2(kbh[0], kbh[1], sb + oKh + bsw);
                LDSM2(kbl[0], kbl[1], sb + oKl + bsw);
                MMA_BF16(S[nt], qhf, kbh);
                MMA_BF16(S[nt], qhf, kbl);
                MMA_BF16(S[nt], qlf, kbh);
            }
        }

        // scale + count-mask (column j valid iff f0 + col < cnt)
        #pragma unroll
        for (int nt = 0; nt < 8; nt++) {
            int col0 = f0 + wn * 64 + nt * 8 + ((lane & 3) << 1);
            int mj0 = col0 < cnt, mj1 = (col0 + 1) < cnt;
            S[nt][0] = mj0 ? S[nt][0] * 0.125f : -INFINITY;
            S[nt][2] = mj0 ? S[nt][2] * 0.125f : -INFINITY;
            S[nt][1] = mj1 ? S[nt][1] * 0.125f : -INFINITY;
            S[nt][3] = mj1 ? S[nt][3] * 0.125f : -INFINITY;
        }

        float rx0 = -INFINITY, rx1 = -INFINITY;
        #pragma unroll
        for (int nt = 0; nt < 8; nt++) {
            rx0 = fmaxf(rx0, fmaxf(S[nt][0], S[nt][1]));
            rx1 = fmaxf(rx1, fmaxf(S[nt][2], S[nt][3]));
        }
        rx0 = fmaxf(rx0, __shfl_xor_sync(0xffffffffu, rx0, 1));
        rx0 = fmaxf(rx0, __shfl_xor_sync(0xffffffffu, rx0, 2));
        rx1 = fmaxf(rx1, __shfl_xor_sync(0xffffffffu, rx1, 1));
        rx1 = fmaxf(rx1, __shfl_xor_sync(0xffffffffu, rx1, 2));
        if ((lane & 3) == 0) {
            pmax[wn * 64 + row0] = rx0;
            pmax[wn * 64 + row0 + 8] = rx1;
        }
        __syncthreads();
        float nm0 = fmaxf(m0, fmaxf(pmax[row0], pmax[64 + row0]));
        float nm1 = fmaxf(m1, fmaxf(pmax[row0 + 8], pmax[64 + row0 + 8]));
        float sf0 = (nm0 == -INFINITY) ? 1.f : __expf(m0 - nm0);
        float sf1 = (nm1 == -INFINITY) ? 1.f : __expf(m1 - nm1);

        float rs0 = 0.f, rs1 = 0.f;
        #pragma unroll
        for (int nt = 0; nt < 8; nt++) {
            float e0 = (S[nt][0] == -INFINITY) ? 0.f : __expf(S[nt][0] - nm0);
            float e1 = (S[nt][1] == -INFINITY) ? 0.f : __expf(S[nt][1] - nm0);
            float e2 = (S[nt][2] == -INFINITY) ? 0.f : __expf(S[nt][2] - nm1);
            float e3 = (S[nt][3] == -INFINITY) ? 0.f : __expf(S[nt][3] - nm1);
            S[nt][0] = e0; S[nt][1] = e1; S[nt][2] = e2; S[nt][3] = e3;
            rs0 += e0 + e1; rs1 += e2 + e3;
        }
        rs0 += __shfl_xor_sync(0xffffffffu, rs0, 1);
        rs0 += __shfl_xor_sync(0xffffffffu, rs0, 2);
        rs1 += __shfl_xor_sync(0xffffffffu, rs1, 1);
        rs1 += __shfl_xor_sync(0xffffffffu, rs1, 2);
        if ((lane & 3) == 0) {
            psum[wn * 64 + row0] = rs0;
            psum[wn * 64 + row0 + 8] = rs1;
        }
        __syncthreads();
        l0 = l0 * sf0 + psum[row0] + psum[64 + row0];
        l1 = l1 * sf1 + psum[row0 + 8] + psum[64 + row0 + 8];
        m0 = nm0; m1 = nm1;
        #pragma unroll
        for (int nt = 0; nt < 8; nt++) {
            O[nt][0] *= sf0; O[nt][1] *= sf0;
            O[nt][2] *= sf1; O[nt][3] *= sf1;
        }

        #pragma unroll
        for (int j = 0; j < 4; j++) {
            uint32_t pah[4], pal[4];
            splitpack(S[2 * j][0], S[2 * j][1], pah[0], pal[0]);
            splitpack(S[2 * j][2], S[2 * j][3], pah[1], pal[1]);
            splitpack(S[2 * j + 1][0], S[2 * j + 1][1], pah[2], pal[2]);
            splitpack(S[2 * j + 1][2], S[2 * j + 1][3], pah[3], pal[3]);
            uint32_t frow = (uint32_t)(wn * 64 + j * 16 + (lane & 15));
            #pragma unroll
            for (int nt = 0; nt < 8; nt++) {
                uint32_t off = frow * 128 + (nt << 4);
                uint32_t sw = off ^ ((off >> 3) & 0x70);
                uint32_t vbh[2], vbl[2];
                LDSM2T(vbh[0], vbh[1], sb + oVh + sw);
                LDSM2T(vbl[0], vbl[1], sb + oVl + sw);
                MMA_BF16(O[nt], pah, vbh);
                MMA_BF16(O[nt], pah, vbl);
                MMA_BF16(O[nt], pal, vbh);
            }
        }
    }

    __syncthreads();
    float* ob = (float*)(sm_ + oKh);
    float* obw = ob + wn * 4096;
    #pragma unroll
    for (int nt = 0; nt < 8; nt++) {
        int col = nt * 8 + ((lane & 3) << 1);
        obw[row0 * 64 + col] = O[nt][0];
        obw[row0 * 64 + col + 1] = O[nt][1];
        obw[(row0 + 8) * 64 + col] = O[nt][2];
        obw[(row0 + 8) * 64 + col + 1] = O[nt][3];
    }
    if ((lane & 3) == 0 && wn == 0) {
        g_pm[(size_t)pbase * Qq + row0] = m0;
        g_pl[(size_t)pbase * Qq + row0] = l0;
        g_pm[(size_t)pbase * Qq + row0 + 8] = m1;
        g_pl[(size_t)pbase * Qq + row0 + 8] = l1;
    }
    __syncthreads();
    #pragma unroll
    for (int r = 0; r < 16; r++) {
        int idx = r * 256 + tid;
        int qq = idx >> 6, dd = idx & 63;
        g_po[((size_t)pbase * Qq + qq) * DHh + dd] = ob[qq * 64 + dd] + ob[4096 + qq * 64 + dd];
    }
}

// ---------------- combine partials ----------------
__global__ void attn_combine(float* __restrict__ out) {
    int bh = blockIdx.x >> 6;
    int q  = blockIdx.x & 63;
    int b  = bh >> 3, h = bh & 7;
    int d  = threadIdx.x;

    float mc[NSPL], lc[NSPL];
    float M = -INFINITY;
    #pragma unroll
    for (int c = 0; c < NSPL; c++) {
        mc[c] = g_pm[((size_t)bh * NSPL + c) * Qq + q];
        lc[c] = g_pl[((size_t)bh * NSPL + c) * Qq + q];
        M = fmaxf(M, mc[c]);
    }
    float r = 0.f;
    if (M != -INFINITY) {
        float num = 0.f, den = 0.f;
        #pragma unroll
        for (int c = 0; c < NSPL; c++) {
            if (mc[c] != -INFINITY) {
                float w = __expf(mc[c] - M);
                den += w * lc[c];
                num += w * g_po[(((size_t)bh * NSPL + c) * Qq + q) * DHh + d];
            }
        }
        r = (den > 0.f) ? num / den : 0.f;
    }
    out[((size_t)(b * Qq + q)) * DIMc + h * DHh + d] = r;
}

// ---------------- launch ----------------
extern "C" void kernel_launch(void* const* d_in, const int* in_sizes, int n_in,
                              void* d_out, int out_size) {
    const float* features = (const float*)d_in[0];
    const float* latents  = (const float*)d_in[1];
    const int*   mask     = (const int*)  d_in[2];
    const float* gf  = (const float*)d_in[3];
    const float* bf  = (const float*)d_in[4];
    const float* gl  = (const float*)d_in[5];
    const float* bl  = (const float*)d_in[6];
    const float* Wq  = (const float*)d_in[7];
    const float* Wk  = (const float*)d_in[8];
    const float* Wv  = (const float*)d_in[9];
    const float* gff = (const float*)d_in[10];
    const float* bff = (const float*)d_in[11];
    const float* W1  = (const float*)d_in[12];
    const float* W2  = (const float*)d_in[13];
    float* out = (float*)d_out;

    bf16 *xnh, *xnl, *lath, *latl, *ln2h, *ln2l, *ffhh, *ffhl;
    bf16 *wqh, *wql, *wkh, *wkl, *wvh, *wvl, *w1h, *w1l, *w2h, *w2l;
    bf16 *qh, *ql, *kh, *kl, *vh, *vl;
    float *att;
    cudaGetSymbolAddress((void**)&xnh,  g_xnh);  cudaGetSymbolAddress((void**)&xnl,  g_xnl);
    cudaGetSymbolAddress((void**)&lath, g_lath); cudaGetSymbolAddress((void**)&latl, g_latl);
    cudaGetSymbolAddress((void**)&ln2h, g_ln2h); cudaGetSymbolAddress((void**)&ln2l, g_ln2l);
    cudaGetSymbolAddress((void**)&ffhh, g_ffhh); cudaGetSymbolAddress((void**)&ffhl, g_ffhl);
    cudaGetSymbolAddress((void**)&wqh, g_wqh); cudaGetSymbolAddress((void**)&wql, g_wql);
    cudaGetSymbolAddress((void**)&wkh, g_wkh); cudaGetSymbolAddress((void**)&wkl, g_wkl);
    cudaGetSymbolAddress((void**)&wvh, g_wvh); cudaGetSymbolAddress((void**)&wvl, g_wvl);
    cudaGetSymbolAddress((void**)&w1h, g_w1h); cudaGetSymbolAddress((void**)&w1l, g_w1l);
    cudaGetSymbolAddress((void**)&w2h, g_w2h); cudaGetSymbolAddress((void**)&w2l, g_w2l);
    cudaGetSymbolAddress((void**)&qh, g_qh);  cudaGetSymbolAddress((void**)&ql, g_ql2);
    cudaGetSymbolAddress((void**)&kh, g_kh);  cudaGetSymbolAddress((void**)&kl, g_kl2);
    cudaGetSymbolAddress((void**)&vh, g_vh);  cudaGetSymbolAddress((void**)&vl, g_vl2);
    cudaGetSymbolAddress((void**)&att, g_att);

    cudaFuncSetAttribute(bf16_gemm, cudaFuncAttributeMaxDynamicSharedMemorySize, GEMM_SMEM);
    cudaFuncSetAttribute(bf16_gemm_cnt, cudaFuncAttributeMaxDynamicSharedMemorySize, GEMM_SMEM);
    cudaFuncSetAttribute(flash_attn_mma, cudaFuncAttributeMaxDynamicSharedMemorySize, ATT_SMEM);

    // weight splits + mask compaction
    splitw_all<<<1792, 256>>>(Wq, Wk, Wv, W1, W2);
    build_idx<<<Bb, 1024>>>(mask);

    // layernorms: features gathered/compacted; latents plain
    ln_gather<<<Bb * Ff / 2, 256>>>(features, gf, bf, xnh, xnl);
    ln_kernel2<<<Bb * Qq / 2, 256>>>(latents,  gl, bl, lath, latl);

    // projections
    bf16_gemm<<<dim3(DIMc / 128, (Bb * Qq) / 128), 256, GEMM_SMEM>>>(
        lath, latl, wqh, wql, nullptr, qh, ql, Bb * Qq, DIMc, DIMc, 0);
    bf16_gemm_cnt<<<dim3(DIMc / 128, (Bb * Ff) / 128), 256, GEMM_SMEM>>>(
        xnh, xnl, wkh, wkl, kh, kl, DIMc, DIMc);
    bf16_gemm_cnt<<<dim3(DIMc / 128, (Bb * Ff) / 128), 256, GEMM_SMEM>>>(
        xnh, xnl, wvh, wvl, vh, vl, DIMc, DIMc);

    // attention over compacted F + combine
    flash_attn_mma<<<Bb * Hh * NSPL, 256, ATT_SMEM>>>(qh, ql, kh, kl, vh, vl);
    attn_combine<<<Bb * Hh * Qq, DHh>>>(att);

    // feed-forward
    ln_kernel2<<<Bb * Qq / 2, 256>>>(att, gff, bff, ln2h, ln2l);
    bf16_gemm<<<dim3(1024 / 128, (Bb * Qq) / 128), 256, GEMM_SMEM>>>(
        ln2h, ln2l, w1h, w1l, nullptr, ffhh, ffhl, Bb * Qq, 1024, DIMc, 1);
    bf16_gemm<<<dim3(DIMc / 128, (Bb * Qq) / 128), 256, GEMM_SMEM>>>(
        ffhh, ffhl, w2h, w2l, out, nullptr, nullptr, Bb * Qq, DIMc, 1024, 0);
}

// round 15
// speedup vs baseline: 2.4508x; 1.0335x over previous
#include <cuda_runtime.h>
#include <cuda_bf16.h>
#include <cstdint>
#include <math.h>

#define Bb   16
#define Ff   4096
#define Qq   64
#define DIMc 512
#define Hh   8
#define DHh  64
#define FCH  128
#define NSPL 16
#define FSEG (Ff / NSPL)
#define KVW  (DIMc * DIMc)
#define KVSZ ((size_t)Bb * Ff * DIMc)

typedef __nv_bfloat16 bf16;
typedef __nv_bfloat162 bf162;

// ---------------- scratch (device globals; no allocation allowed) ----------------
__device__ bf16  g_xnh [(size_t)Bb * Ff * DIMc];
__device__ bf16  g_xnl [(size_t)Bb * Ff * DIMc];
__device__ bf16  g_lath[(size_t)Bb * Qq * DIMc];
__device__ bf16  g_latl[(size_t)Bb * Qq * DIMc];
__device__ bf16  g_ln2h[(size_t)Bb * Qq * DIMc];
__device__ bf16  g_ln2l[(size_t)Bb * Qq * DIMc];
__device__ bf16  g_ffhh[(size_t)Bb * Qq * 1024];
__device__ bf16  g_ffhl[(size_t)Bb * Qq * 1024];
__device__ bf16  g_wqh[KVW], g_wql[KVW];
__device__ bf16  g_kvwh[2 * KVW], g_kvwl[2 * KVW];     // [K|V] weights contiguous
__device__ bf16  g_w1h[DIMc * 1024], g_w1l[DIMc * 1024];
__device__ bf16  g_w2h[1024 * DIMc], g_w2l[1024 * DIMc];
__device__ bf16  g_qh [(size_t)Bb * Qq * DIMc], g_ql2[(size_t)Bb * Qq * DIMc];
__device__ bf16  g_kvh[2 * KVSZ], g_kvl[2 * KVSZ];     // [K|V] outputs contiguous
__device__ float g_att[(size_t)Bb * Qq * DIMc];
__device__ float g_po [(size_t)Bb * Hh * NSPL * Qq * DHh];
__device__ float g_pm [(size_t)Bb * Hh * NSPL * Qq];
__device__ float g_pl [(size_t)Bb * Hh * NSPL * Qq];
__device__ int   g_idx[Bb * Ff];
__device__ int   g_cnt[Bb];

// ---------------- helpers ----------------
static __device__ __forceinline__ uint32_t smem_u32(const void* p) {
    uint32_t a;
    asm("{ .reg .u64 t; cvta.to.shared.u64 t, %1; cvt.u32.u64 %0, t; }" : "=r"(a) : "l"(p));
    return a;
}
static __device__ __forceinline__ void cpa16(uint32_t dst, const void* src) {
    asm volatile("cp.async.cg.shared.global [%0], [%1], 16;" :: "r"(dst), "l"(src));
}
#define CPA_COMMIT() asm volatile("cp.async.commit_group;" ::: "memory")
#define CPA_WAIT1()  asm volatile("cp.async.wait_group 1;" ::: "memory")
#define CPA_WAIT0()  asm volatile("cp.async.wait_group 0;" ::: "memory")

#define LDSM4(r0, r1, r2, r3, addr)                                        \
    asm volatile("ldmatrix.sync.aligned.m8n8.x4.shared.b16 {%0,%1,%2,%3}, [%4];" \
                 : "=r"(r0), "=r"(r1), "=r"(r2), "=r"(r3) : "r"(addr))

#define LDSM2(r0, r1, addr)                                                \
    asm volatile("ldmatrix.sync.aligned.m8n8.x2.shared.b16 {%0,%1}, [%2];" \
                 : "=r"(r0), "=r"(r1) : "r"(addr))

#define LDSM2T(r0, r1, addr)                                               \
    asm volatile("ldmatrix.sync.aligned.m8n8.x2.trans.shared.b16 {%0,%1}, [%2];" \
                 : "=r"(r0), "=r"(r1) : "r"(addr))

#define MMA_BF16(c, a, b)                                                  \
    asm volatile("mma.sync.aligned.m16n8k16.row.col.f32.bf16.bf16.f32 "    \
                 "{%0,%1,%2,%3}, {%4,%5,%6,%7}, {%8,%9}, {%0,%1,%2,%3};"   \
                 : "+f"((c)[0]), "+f"((c)[1]), "+f"((c)[2]), "+f"((c)[3])  \
                 : "r"((a)[0]), "r"((a)[1]), "r"((a)[2]), "r"((a)[3]),     \
                   "r"((b)[0]), "r"((b)[1]))

static __device__ __forceinline__ void bf16_split(float x, bf16& h, bf16& l) {
    h = __float2bfloat16(x);
    l = __float2bfloat16(x - __bfloat162float(h));
}
static __device__ __forceinline__ void splitpack(float p0, float p1,
                                                 uint32_t& hi, uint32_t& lo) {
    bf16 h0, l0, h1, l1;
    bf16_split(p0, h0, l0);
    bf16_split(p1, h1, l1);
    bf162 H; H.x = h0; H.y = h1;
    bf162 L; L.x = l0; L.y = l1;
    hi = *(uint32_t*)&H;
    lo = *(uint32_t*)&L;
}

// ---------------- mask compaction: per-batch prefix scan ----------------
__global__ void build_idx(const int* __restrict__ mask) {
    __shared__ int ws[32];
    int b = blockIdx.x;
    const int* m = mask + b * Ff;
    int t = threadIdx.x;
    int v[4];
    int s = 0;
    #pragma unroll
    for (int i = 0; i < 4; i++) { v[i] = m[t * 4 + i]; s += v[i]; }
    int lane = t & 31, w = t >> 5;
    int ps = s;
    #pragma unroll
    for (int o = 1; o < 32; o <<= 1) {
        int n = __shfl_up_sync(0xffffffffu, ps, o);
        if (lane >= o) ps += n;
    }
    if (lane == 31) ws[w] = ps;
    __syncthreads();
    if (w == 0) {
        int x = ws[lane];
        #pragma unroll
        for (int o = 1; o < 32; o <<= 1) {
            int n = __shfl_up_sync(0xffffffffu, x, o);
            if (lane >= o) x += n;
        }
        ws[lane] = x;
    }
    __syncthreads();
    int base = ps - s + (w ? ws[w - 1] : 0);
    #pragma unroll
    for (int i = 0; i < 4; i++) {
        if (v[i]) { g_idx[b * Ff + base] = t * 4 + i; base++; }
    }
    if (t == 1023) g_cnt[b] = ws[31];
}

// ---------------- 3xBF16 mma GEMM (exact R12 kernel) ----------------
#define STAGE_B    32768
#define GEMM_SMEM  (3 * STAGE_B)

__global__ void __launch_bounds__(256, 2) bf16_gemm(
    const bf16* __restrict__ Ah, const bf16* __restrict__ Al,
    const bf16* __restrict__ Wh, const bf16* __restrict__ Wl,
    float* __restrict__ Cf, bf16* __restrict__ Ch, bf16* __restrict__ Cl,
    int M, int N, int K, int relu)
{
    extern __shared__ __align__(1024) char smem[];
    int tid = threadIdx.x;
    int lane = tid & 31, wid = tid >> 5;
    int bn = blockIdx.x << 7, bm = blockIdx.y << 7;
    uint32_t sbase = smem_u32(smem);

    int wm = (wid & 1) << 6;
    int wn = (wid >> 1) << 5;

    float acc[4][4][4];
    #pragma unroll
    for (int i = 0; i < 4; i++)
        #pragma unroll
        for (int j = 0; j < 4; j++)
            #pragma unroll
            for (int r = 0; r < 4; r++) acc[i][j][r] = 0.f;

    int nCh = K >> 5;

    auto issue = [&](int p, int s) {
        uint32_t st = sbase + s * STAGE_B;
        int k0 = p << 5;
        #pragma unroll
        for (int r = 0; r < 2; r++) {
            int c = r * 256 + tid;
            int m = c >> 2, c4 = c & 3;
            uint32_t off = m * 64 + (c4 << 4);
            uint32_t sw = off ^ ((off >> 3) & 0x30);
            cpa16(st + sw, Ah + (size_t)(bm + m) * K + k0 + c4 * 8);
            cpa16(st + 8192 + sw, Al + (size_t)(bm + m) * K + k0 + c4 * 8);
        }
        #pragma unroll
        for (int r = 0; r < 2; r++) {
            int c = r * 256 + tid;
            int kk = c >> 4, c16 = c & 15;
            uint32_t off = kk * 256 + (c16 << 4);
            uint32_t sw = off ^ ((off >> 4) & 0x70);
            cpa16(st + 16384 + sw, Wh + (size_t)(k0 + kk) * N + bn + c16 * 8);
            cpa16(st + 24576 + sw, Wl + (size_t)(k0 + kk) * N + bn + c16 * 8);
        }
        CPA_COMMIT();
    };

    issue(0, 0);
    if (nCh > 1) issue(1, 1); else CPA_COMMIT();

    int quad = lane >> 3, rr = lane & 7;
    int lrow = ((quad & 1) << 3) + rr;
    int lcol = quad >> 1;
    int bl16 = lane & 15;

    for (int p = 0; p < nCh; p++) {
        CPA_WAIT1();
        __syncthreads();
        int s = p % 3;
        uint32_t aHi = sbase + s * STAGE_B;
        uint32_t aLo = aHi + 8192;
        uint32_t bHi = aHi + 16384;
        uint32_t bLo = aHi + 24576;

        #pragma unroll
        for (int j = 0; j < 2; j++) {
            uint32_t ahf[4][4], alf[4][4];
            #pragma unroll
            for (int mt = 0; mt < 4; mt++) {
                uint32_t off = (uint32_t)(wm + mt * 16 + lrow) * 64 + j * 32 + (lcol << 4);
                uint32_t sw = off ^ ((off >> 3) & 0x30);
                LDSM4(ahf[mt][0], ahf[mt][1], ahf[mt][2], ahf[mt][3], aHi + sw);
                LDSM4(alf[mt][0], alf[mt][1], alf[mt][2], alf[mt][3], aLo + sw);
            }
            uint32_t bhf[4][2], blf[4][2];
            {
                uint32_t krow = j * 16 + bl16;
                #pragma unroll
                for (int nt = 0; nt < 4; nt++) {
                    uint32_t off = krow * 256 + (uint32_t)(wn + nt * 8) * 2;
                    uint32_t sw = off ^ ((off >> 4) & 0x70);
                    LDSM2T(bhf[nt][0], bhf[nt][1], bHi + sw);
                    LDSM2T(blf[nt][0], blf[nt][1], bLo + sw);
                }
            }
            #pragma unroll
            for (int mt = 0; mt < 4; mt++)
                #pragma unroll
                for (int nt = 0; nt < 4; nt++) {
                    MMA_BF16(acc[mt][nt], ahf[mt], bhf[nt]);
                    MMA_BF16(acc[mt][nt], ahf[mt], blf[nt]);
                    MMA_BF16(acc[mt][nt], alf[mt], bhf[nt]);
                }
        }
        if (p + 2 < nCh) issue(p + 2, (p + 2) % 3);
        else CPA_COMMIT();
    }

    int r0 = bm + wm + (lane >> 2);
    int cc = bn + wn + ((lane & 3) << 1);
    #pragma unroll
    for (int mt = 0; mt < 4; mt++) {
        #pragma unroll
        for (int nt = 0; nt < 4; nt++) {
            float v0 = acc[mt][nt][0], v1 = acc[mt][nt][1];
            float v2 = acc[mt][nt][2], v3 = acc[mt][nt][3];
            if (relu) {
                v0 = fmaxf(v0, 0.f); v1 = fmaxf(v1, 0.f);
                v2 = fmaxf(v2, 0.f); v3 = fmaxf(v3, 0.f);
            }
            int row = r0 + mt * 16;
            int col = cc + nt * 8;
            if (Cf) {
                *(float2*)(Cf + (size_t)row * N + col) = make_float2(v0, v1);
                *(float2*)(Cf + (size_t)(row + 8) * N + col) = make_float2(v2, v3);
            } else {
                uint32_t ph, pl;
                splitpack(v0, v1, ph, pl);
                *(uint32_t*)(Ch + (size_t)row * N + col) = ph;
                *(uint32_t*)(Cl + (size_t)row * N + col) = pl;
                splitpack(v2, v3, ph, pl);
                *(uint32_t*)(Ch + (size_t)(row + 8) * N + col) = ph;
                *(uint32_t*)(Cl + (size_t)(row + 8) * N + col) = pl;
            }
        }
    }
}

// ---------------- fused K+V projection: z selects via global-array strides (no extra params) ----------------
__global__ void __launch_bounds__(256, 2) bf16_gemm_kv(
    const bf16* __restrict__ Ah, const bf16* __restrict__ Al)
{
    if (((int)(blockIdx.y & 31) << 7) >= g_cnt[blockIdx.y >> 5]) return;

    const int N = DIMc, K = DIMc;
    const bf16* Wh = g_kvwh + (size_t)blockIdx.z * KVW;
    const bf16* Wl = g_kvwl + (size_t)blockIdx.z * KVW;
    bf16* Ch = g_kvh + (size_t)blockIdx.z * KVSZ;
    bf16* Cl = g_kvl + (size_t)blockIdx.z * KVSZ;

    extern __shared__ __align__(1024) char smem[];
    int tid = threadIdx.x;
    int lane = tid & 31, wid = tid >> 5;
    int bn = blockIdx.x << 7, bm = blockIdx.y << 7;
    uint32_t sbase = smem_u32(smem);

    int wm = (wid & 1) << 6;
    int wn = (wid >> 1) << 5;

    float acc[4][4][4];
    #pragma unroll
    for (int i = 0; i < 4; i++)
        #pragma unroll
        for (int j = 0; j < 4; j++)
            #pragma unroll
            for (int r = 0; r < 4; r++) acc[i][j][r] = 0.f;

    int nCh = K >> 5;

    auto issue = [&](int p, int s) {
        uint32_t st = sbase + s * STAGE_B;
        int k0 = p << 5;
        #pragma unroll
        for (int r = 0; r < 2; r++) {
            int c = r * 256 + tid;
            int m = c >> 2, c4 = c & 3;
            uint32_t off = m * 64 + (c4 << 4);
            uint32_t sw = off ^ ((off >> 3) & 0x30);
            cpa16(st + sw, Ah + (size_t)(bm + m) * K + k0 + c4 * 8);
            cpa16(st + 8192 + sw, Al + (size_t)(bm + m) * K + k0 + c4 * 8);
        }
        #pragma unroll
        for (int r = 0; r < 2; r++) {
            int c = r * 256 + tid;
            int kk = c >> 4, c16 = c & 15;
            uint32_t off = kk * 256 + (c16 << 4);
            uint32_t sw = off ^ ((off >> 4) & 0x70);
            cpa16(st + 16384 + sw, Wh + (size_t)(k0 + kk) * N + bn + c16 * 8);
            cpa16(st + 24576 + sw, Wl + (size_t)(k0 + kk) * N + bn + c16 * 8);
        }
        CPA_COMMIT();
    };

    issue(0, 0);
    if (nCh > 1) issue(1, 1); else CPA_COMMIT();

    int quad = lane >> 3, rr = lane & 7;
    int lrow = ((quad & 1) << 3) + rr;
    int lcol = quad >> 1;
    int bl16 = lane & 15;

    for (int p = 0; p < nCh; p++) {
        CPA_WAIT1();
        __syncthreads();
        int s = p % 3;
        uint32_t aHi = sbase + s * STAGE_B;
        uint32_t aLo = aHi + 8192;
        uint32_t bHi = aHi + 16384;
        uint32_t bLo = aHi + 24576;

        #pragma unroll
        for (int j = 0; j < 2; j++) {
            uint32_t ahf[4][4], alf[4][4];
            #pragma unroll
            for (int mt = 0; mt < 4; mt++) {
                uint32_t off = (uint32_t)(wm + mt * 16 + lrow) * 64 + j * 32 + (lcol << 4);
                uint32_t sw = off ^ ((off >> 3) & 0x30);
                LDSM4(ahf[mt][0], ahf[mt][1], ahf[mt][2], ahf[mt][3], aHi + sw);
                LDSM4(alf[mt][0], alf[mt][1], alf[mt][2], alf[mt][3], aLo + sw);
            }
            uint32_t bhf[4][2], blf[4][2];
            {
                uint32_t krow = j * 16 + bl16;
                #pragma unroll
                for (int nt = 0; nt < 4; nt++) {
                    uint32_t off = krow * 256 + (uint32_t)(wn + nt * 8) * 2;
                    uint32_t sw = off ^ ((off >> 4) & 0x70);
                    LDSM2T(bhf[nt][0], bhf[nt][1], bHi + sw);
                    LDSM2T(blf[nt][0], blf[nt][1], bLo + sw);
                }
            }
            #pragma unroll
            for (int mt = 0; mt < 4; mt++)
                #pragma unroll
                for (int nt = 0; nt < 4; nt++) {
                    MMA_BF16(acc[mt][nt], ahf[mt], bhf[nt]);
                    MMA_BF16(acc[mt][nt], ahf[mt], blf[nt]);
                    MMA_BF16(acc[mt][nt], alf[mt], bhf[nt]);
                }
        }
        if (p + 2 < nCh) issue(p + 2, (p + 2) % 3);
        else CPA_COMMIT();
    }

    int r0 = bm + wm + (lane >> 2);
    int cc = bn + wn + ((lane & 3) << 1);
    #pragma unroll
    for (int mt = 0; mt < 4; mt++) {
        #pragma unroll
        for (int nt = 0; nt < 4; nt++) {
            int row = r0 + mt * 16;
            int col = cc + nt * 8;
            uint32_t ph, pl;
            splitpack(acc[mt][nt][0], acc[mt][nt][1], ph, pl);
            *(uint32_t*)(Ch + (size_t)row * N + col) = ph;
            *(uint32_t*)(Cl + (size_t)row * N + col) = pl;
            splitpack(acc[mt][nt][2], acc[mt][nt][3], ph, pl);
            *(uint32_t*)(Ch + (size_t)(row + 8) * N + col) = ph;
            *(uint32_t*)(Cl + (size_t)(row + 8) * N + col) = pl;
        }
    }
}

// ---------------- all weight splits in one launch ----------------
__global__ void splitw_all(const float* __restrict__ Wq, const float* __restrict__ Wk,
                           const float* __restrict__ Wv, const float* __restrict__ W1,
                           const float* __restrict__ W2) {
    int q = blockIdx.x * 256 + threadIdx.x;
    const float* src; bf16 *dh, *dl; int off;
    if (q < 65536)        { src = Wq; dh = g_wqh;        dl = g_wql;        off = q; }
    else if (q < 131072)  { src = Wk; dh = g_kvwh;       dl = g_kvwl;       off = q - 65536; }
    else if (q < 196608)  { src = Wv; dh = g_kvwh + KVW; dl = g_kvwl + KVW; off = q - 131072; }
    else if (q < 327680)  { src = W1; dh = g_w1h;        dl = g_w1l;        off = q - 196608; }
    else                  { src = W2; dh = g_w2h;        dl = g_w2l;        off = q - 327680; }
    float4 v = ((const float4*)src)[off];
    uint32_t h01, l01, h23, l23;
    splitpack(v.x, v.y, h01, l01);
    splitpack(v.z, v.w, h23, l23);
    *(uint2*)(dh + (size_t)off * 4) = make_uint2(h01, h23);
    *(uint2*)(dl + (size_t)off * 4) = make_uint2(l01, l23);
}

// ---------------- LayerNorm: 2 rows per block -> bf16 hi/lo ----------------
__global__ void ln_kernel2(const float* __restrict__ x, const float* __restrict__ g,
                           const float* __restrict__ beta,
                           bf16* __restrict__ yh, bf16* __restrict__ yl) {
    __shared__ float sm[8];
    int half = threadIdx.x >> 7;
    int t = threadIdx.x & 127;
    size_t row = (size_t)blockIdx.x * 2 + half;
    float4 v = ((const float4*)(x + row * DIMc))[t];
    float s = v.x + v.y + v.z + v.w;
    #pragma unroll
    for (int o = 16; o; o >>= 1) s += __shfl_xor_sync(0xffffffffu, s, o);
    if ((t & 31) == 0) sm[threadIdx.x >> 5] = s;
    __syncthreads();
    int sb = half * 4;
    float mean = (sm[sb] + sm[sb + 1] + sm[sb + 2] + sm[sb + 3]) * (1.0f / DIMc);
    __syncthreads();
    float dx = v.x - mean, dy = v.y - mean, dz = v.z - mean, dw = v.w - mean;
    float sq = dx * dx + dy * dy + dz * dz + dw * dw;
    #pragma unroll
    for (int o = 16; o; o >>= 1) sq += __shfl_xor_sync(0xffffffffu, sq, o);
    if ((t & 31) == 0) sm[threadIdx.x >> 5] = sq;
    __syncthreads();
    float var = (sm[sb] + sm[sb + 1] + sm[sb + 2] + sm[sb + 3]) * (1.0f / DIMc);
    float rstd = rsqrtf(var + 1e-5f);
    float4 gg = ((const float4*)g)[t];
    float4 bb = ((const float4*)beta)[t];
    float o0 = dx * rstd * gg.x + bb.x;
    float o1 = dy * rstd * gg.y + bb.y;
    float o2 = dz * rstd * gg.z + bb.z;
    float o3 = dw * rstd * gg.w + bb.w;
    uint32_t h01, l01, h23, l23;
    splitpack(o0, o1, h01, l01);
    splitpack(o2, o3, h23, l23);
    *(uint2*)(yh + row * DIMc + t * 4) = make_uint2(h01, h23);
    *(uint2*)(yl + row * DIMc + t * 4) = make_uint2(l01, l23);
}

// ---------------- LN + gather: compacted feature rows; zero-fill padding ----------------
__global__ void ln_gather(const float* __restrict__ x, const float* __restrict__ g,
                          const float* __restrict__ beta,
                          bf16* __restrict__ yh, bf16* __restrict__ yl) {
    __shared__ float sm[8];
    int half = threadIdx.x >> 7;
    int t = threadIdx.x & 127;
    size_t row = (size_t)blockIdx.x * 2 + half;
    int b = (int)(row >> 12);
    int r = (int)(row & (Ff - 1));
    if (r >= g_cnt[b]) {
        *(uint2*)(yh + row * DIMc + t * 4) = make_uint2(0u, 0u);
        *(uint2*)(yl + row * DIMc + t * 4) = make_uint2(0u, 0u);
        return;
    }
    size_t src = (size_t)b * Ff + g_idx[b * Ff + r];
    float4 v = ((const float4*)(x + src * DIMc))[t];
    float s = v.x + v.y + v.z + v.w;
    #pragma unroll
    for (int o = 16; o; o >>= 1) s += __shfl_xor_sync(0xffffffffu, s, o);
    if ((t & 31) == 0) sm[threadIdx.x >> 5] = s;
    __syncthreads();
    int sb = half * 4;
    float mean = (sm[sb] + sm[sb + 1] + sm[sb + 2] + sm[sb + 3]) * (1.0f / DIMc);
    __syncthreads();
    float dx = v.x - mean, dy = v.y - mean, dz = v.z - mean, dw = v.w - mean;
    float sq = dx * dx + dy * dy + dz * dz + dw * dw;
    #pragma unroll
    for (int o = 16; o; o >>= 1) sq += __shfl_xor_sync(0xffffffffu, sq, o);
    if ((t & 31) == 0) sm[threadIdx.x >> 5] = sq;
    __syncthreads();
    float var = (sm[sb] + sm[sb + 1] + sm[sb + 2] + sm[sb + 3]) * (1.0f / DIMc);
    float rstd = rsqrtf(var + 1e-5f);
    float4 gg = ((const float4*)g)[t];
    float4 bb = ((const float4*)beta)[t];
    float o0 = dx * rstd * gg.x + bb.x;
    float o1 = dy * rstd * gg.y + bb.y;
    float o2 = dz * rstd * gg.z + bb.z;
    float o3 = dw * rstd * gg.w + bb.w;
    uint32_t h01, l01, h23, l23;
    splitpack(o0, o1, h01, l01);
    splitpack(o2, o3, h23, l23);
    *(uint2*)(yh + row * DIMc + t * 4) = make_uint2(h01, h23);
    *(uint2*)(yl + row * DIMc + t * 4) = make_uint2(l01, l23);
}

// ---------------- flash attention over compacted F (count-masked, NSPL=16) ----------------
#define oQh   0
#define oQl   8192
#define oKh   16384
#define oKl   32768
#define oVh   49152
#define oVl   65536
#define oPmax 81920
#define oPsum 82432
#define ATT_SMEM 82944

__global__ void __launch_bounds__(256, 2) flash_attn_mma(
    const bf16* __restrict__ qh, const bf16* __restrict__ ql,
    const bf16* __restrict__ kh, const bf16* __restrict__ kl,
    const bf16* __restrict__ vh, const bf16* __restrict__ vl)
{
    extern __shared__ __align__(1024) char sm_[];
    uint32_t sb = smem_u32(sm_);
    int tid = threadIdx.x, lane = tid & 31, wid = tid >> 5;
    int wm = (wid & 3) << 4;
    int wn = wid >> 2;
    int c  = blockIdx.x & (NSPL - 1);
    int h  = (blockIdx.x >> 4) & 7;
    int b  = blockIdx.x >> 7;
    int pbase = (b * Hh + h) * NSPL + c;
    int cnt = g_cnt[b];

    size_t qoff = (size_t)b * Qq * DIMc + h * DHh;
    size_t koff = (size_t)b * Ff * DIMc + h * DHh;

    float* pmax = (float*)(sm_ + oPmax);
    float* psum = (float*)(sm_ + oPsum);

    int fbeg = c * FSEG;
    if (fbeg >= cnt) {
        // empty split: zero partials so combine sees -INF/0
        if (tid < 64 && wid == 0) {
            g_pm[(size_t)pbase * Qq + tid] = -INFINITY;
            g_pl[(size_t)pbase * Qq + tid] = 0.f;
        }
        for (int r = tid; r < Qq * DHh; r += 256)
            g_po[(size_t)pbase * Qq * DHh + r] = 0.f;
        return;
    }

    #pragma unroll
    for (int r = 0; r < 2; r++) {
        int idx = r * 256 + tid;
        int row = idx >> 3, ch = idx & 7;
        uint32_t off = row * 128 + (ch << 4);
        uint32_t sw = off ^ ((off >> 3) & 0x70);
        cpa16(sb + oQh + sw, qh + qoff + (size_t)row * DIMc + ch * 8);
        cpa16(sb + oQl + sw, ql + qoff + (size_t)row * DIMc + ch * 8);
    }
    CPA_COMMIT();

    float m0 = -INFINITY, m1 = -INFINITY, l0 = 0.f, l1 = 0.f;
    float O[8][4];
    #pragma unroll
    for (int nt = 0; nt < 8; nt++)
        #pragma unroll
        for (int r = 0; r < 4; r++) O[nt][r] = 0.f;

    int quad = lane >> 3, rr = lane & 7;
    int lrow = ((quad & 1) << 3) + rr;
    int lcol = quad >> 1;
    int row0 = wm + (lane >> 2);

    for (int f0 = fbeg; f0 < fbeg + FSEG; f0 += FCH) {
        if (f0 >= cnt) break;
        __syncthreads();
        #pragma unroll
        for (int r = 0; r < 4; r++) {
            int idx = r * 256 + tid;
            int row = idx >> 3, ch = idx & 7;
            uint32_t off = row * 128 + (ch << 4);
            uint32_t sw = off ^ ((off >> 3) & 0x70);
            size_t g = koff + (size_t)(f0 + row) * DIMc + ch * 8;
            cpa16(sb + oKh + sw, kh + g);
            cpa16(sb + oKl + sw, kl + g);
            cpa16(sb + oVh + sw, vh + g);
            cpa16(sb + oVl + sw, vl + g);
        }
        CPA_COMMIT();
        CPA_WAIT0();
        __syncthreads();

        float S[8][4];
        #pragma unroll
        for (int nt = 0; nt < 8; nt++)
            #pragma unroll
            for (int r = 0; r < 4; r++) S[nt][r] = 0.f;

        #pragma unroll
        for (int j = 0; j < 4; j++) {
            uint32_t qoffb = (uint32_t)(wm + lrow) * 128 + j * 32 + (lcol << 4);
            uint32_t qsw = qoffb ^ ((qoffb >> 3) & 0x70);
            uint32_t qhf[4], qlf[4];
            LDSM4(qhf[0], qhf[1], qhf[2], qhf[3], sb + oQh + qsw);
            LDSM4(qlf[0], qlf[1], qlf[2], qlf[3], sb + oQl + qsw);
            #pragma unroll
            for (int nt = 0; nt < 8; nt++) {
                int fr = wn * 64 + nt * 8 + (lane & 7);
                int seg = (lane >> 3) & 1;
                uint32_t boff = (uint32_t)fr * 128 + j * 32 + (seg << 4);
                uint32_t bsw = boff ^ ((boff >> 3) & 0x70);
                uint32_t kbh[2], kbl[2];
                LDSM2(kbh[0], kbh[1], sb + oKh + bsw);
                LDSM2(kbl[0], kbl[1], sb + oKl + bsw);
                MMA_BF16(S[nt], qhf, kbh);
                MMA_BF16(S[nt], qhf, kbl);
                MMA_BF16(S[nt], qlf, kbh);
            }
        }

        #pragma unroll
        for (int nt = 0; nt < 8; nt++) {
            int col0 = f0 + wn * 64 + nt * 8 + ((lane & 3) << 1);
            int mj0 = col0 < cnt, mj1 = (col0 + 1) < cnt;
            S[nt][0] = mj0 ? S[nt][0] * 0.125f : -INFINITY;
            S[nt][2] = mj0 ? S[nt][2] * 0.125f : -INFINITY;
            S[nt][1] = mj1 ? S[nt][1] * 0.125f : -INFINITY;
            S[nt][3] = mj1 ? S[nt][3] * 0.125f : -INFINITY;
        }

        float rx0 = -INFINITY, rx1 = -INFINITY;
        #pragma unroll
        for (int nt = 0; nt < 8; nt++) {
            rx0 = fmaxf(rx0, fmaxf(S[nt][0], S[nt][1]));
            rx1 = fmaxf(rx1, fmaxf(S[nt][2], S[nt][3]));
        }
        rx0 = fmaxf(rx0, __shfl_xor_sync(0xffffffffu, rx0, 1));
        rx0 = fmaxf(rx0, __shfl_xor_sync(0xffffffffu, rx0, 2));
        rx1 = fmaxf(rx1, __shfl_xor_sync(0xffffffffu, rx1, 1));
        rx1 = fmaxf(rx1, __shfl_xor_sync(0xffffffffu, rx1, 2));
        if ((lane & 3) == 0) {
            pmax[wn * 64 + row0] = rx0;
            pmax[wn * 64 + row0 + 8] = rx1;
        }
        __syncthreads();
        float nm0 = fmaxf(m0, fmaxf(pmax[row0], pmax[64 + row0]));
        float nm1 = fmaxf(m1, fmaxf(pmax[row0 + 8], pmax[64 + row0 + 8]));
        float sf0 = (nm0 == -INFINITY) ? 1.f : __expf(m0 - nm0);
        float sf1 = (nm1 == -INFINITY) ? 1.f : __expf(m1 - nm1);

        float rs0 = 0.f, rs1 = 0.f;
        #pragma unroll
        for (int nt = 0; nt < 8; nt++) {
            float e0 = (S[nt][0] == -INFINITY) ? 0.f : __expf(S[nt][0] - nm0);
            float e1 = (S[nt][1] == -INFINITY) ? 0.f : __expf(S[nt][1] - nm0);
            float e2 = (S[nt][2] == -INFINITY) ? 0.f : __expf(S[nt][2] - nm1);
            float e3 = (S[nt][3] == -INFINITY) ? 0.f : __expf(S[nt][3] - nm1);
            S[nt][0] = e0; S[nt][1] = e1; S[nt][2] = e2; S[nt][3] = e3;
            rs0 += e0 + e1; rs1 += e2 + e3;
        }
        rs0 += __shfl_xor_sync(0xffffffffu, rs0, 1);
        rs0 += __shfl_xor_sync(0xffffffffu, rs0, 2);
        rs1 += __shfl_xor_sync(0xffffffffu, rs1, 1);
        rs1 += __shfl_xor_sync(0xffffffffu, rs1, 2);
        if ((lane & 3) == 0) {
            psum[wn * 64 + row0] = rs0;
            psum[wn * 64 + row0 + 8] = rs1;
        }
        __syncthreads();
        l0 = l0 * sf0 + psum[row0] + psum[64 + row0];
        l1 = l1 * sf1 + psum[row0 + 8] + psum[64 + row0 + 8];
        m0 = nm0; m1 = nm1;
        #pragma unroll
        for (int nt = 0; nt < 8; nt++) {
            O[nt][0] *= sf0; O[nt][1] *= sf0;
            O[nt][2] *= sf1; O[nt][3] *= sf1;
        }

        #pragma unroll
        for (int j = 0; j < 4; j++) {
            uint32_t pah[4], pal[4];
            splitpack(S[2 * j][0], S[2 * j][1], pah[0], pal[0]);
            splitpack(S[2 * j][2], S[2 * j][3], pah[1], pal[1]);
            splitpack(S[2 * j + 1][0], S[2 * j + 1][1], pah[2], pal[2]);
            splitpack(S[2 * j + 1][2], S[2 * j + 1][3], pah[3], pal[3]);
            uint32_t frow = (uint32_t)(wn * 64 + j * 16 + (lane & 15));
            #pragma unroll
            for (int nt = 0; nt < 8; nt++) {
                uint32_t off = frow * 128 + (nt << 4);
                uint32_t sw = off ^ ((off >> 3) & 0x70);
                uint32_t vbh[2], vbl[2];
                LDSM2T(vbh[0], vbh[1], sb + oVh + sw);
                LDSM2T(vbl[0], vbl[1], sb + oVl + sw);
                MMA_BF16(O[nt], pah, vbh);
                MMA_BF16(O[nt], pah, vbl);
                MMA_BF16(O[nt], pal, vbh);
            }
        }
    }

    __syncthreads();
    float* ob = (float*)(sm_ + oKh);
    float* obw = ob + wn * 4096;
    #pragma unroll
    for (int nt = 0; nt < 8; nt++) {
        int col = nt * 8 + ((lane & 3) << 1);
        obw[row0 * 64 + col] = O[nt][0];
        obw[row0 * 64 + col + 1] = O[nt][1];
        obw[(row0 + 8) * 64 + col] = O[nt][2];
        obw[(row0 + 8) * 64 + col + 1] = O[nt][3];
    }
    if ((lane & 3) == 0 && wn == 0) {
        g_pm[(size_t)pbase * Qq + row0] = m0;
        g_pl[(size_t)pbase * Qq + row0] = l0;
        g_pm[(size_t)pbase * Qq + row0 + 8] = m1;
        g_pl[(size_t)pbase * Qq + row0 + 8] = l1;
    }
    __syncthreads();
    #pragma unroll
    for (int r = 0; r < 16; r++) {
        int idx = r * 256 + tid;
        int qq = idx >> 6, dd = idx & 63;
        g_po[((size_t)pbase * Qq + qq) * DHh + dd] = ob[qq * 64 + dd] + ob[4096 + qq * 64 + dd];
    }
}

// ---------------- combine partials (NSPL=16) ----------------
__global__ void attn_combine(float* __restrict__ out) {
    int bh = blockIdx.x >> 6;
    int q  = blockIdx.x & 63;
    int b  = bh >> 3, h = bh & 7;
    int d  = threadIdx.x;

    float mc[NSPL], lc[NSPL];
    float M = -INFINITY;
    #pragma unroll
    for (int c = 0; c < NSPL; c++) {
        mc[c] = g_pm[((size_t)bh * NSPL + c) * Qq + q];
        lc[c] = g_pl[((size_t)bh * NSPL + c) * Qq + q];
        M = fmaxf(M, mc[c]);
    }
    float r = 0.f;
    if (M != -INFINITY) {
        float num = 0.f, den = 0.f;
        #pragma unroll
        for (int c = 0; c < NSPL; c++) {
            if (mc[c] != -INFINITY) {
                float w = __expf(mc[c] - M);
                den += w * lc[c];
                num += w * g_po[(((size_t)bh * NSPL + c) * Qq + q) * DHh + d];
            }
        }
        r = (den > 0.f) ? num / den : 0.f;
    }
    out[((size_t)(b * Qq + q)) * DIMc + h * DHh + d] = r;
}

// ---------------- launch ----------------
extern "C" void kernel_launch(void* const* d_in, const int* in_sizes, int n_in,
                              void* d_out, int out_size) {
    const float* features = (const float*)d_in[0];
    const float* latents  = (const float*)d_in[1];
    const int*   mask     = (const int*)  d_in[2];
    const float* gf  = (const float*)d_in[3];
    const float* bf  = (const float*)d_in[4];
    const float* gl  = (const float*)d_in[5];
    const float* bl  = (const float*)d_in[6];
    const float* Wq  = (const float*)d_in[7];
    const float* Wk  = (const float*)d_in[8];
    const float* Wv  = (const float*)d_in[9];
    const float* gff = (const float*)d_in[10];
    const float* bff = (const float*)d_in[11];
    const float* W1  = (const float*)d_in[12];
    const float* W2  = (const float*)d_in[13];
    float* out = (float*)d_out;

    bf16 *xnh, *xnl, *lath, *latl, *ln2h, *ln2l, *ffhh, *ffhl;
    bf16 *wqh, *wql, *w1h, *w1l, *w2h, *w2l;
    bf16 *qh, *ql, *kvh, *kvl;
    float *att;
    cudaGetSymbolAddress((void**)&xnh,  g_xnh);  cudaGetSymbolAddress((void**)&xnl,  g_xnl);
    cudaGetSymbolAddress((void**)&lath, g_lath); cudaGetSymbolAddress((void**)&latl, g_latl);
    cudaGetSymbolAddress((void**)&ln2h, g_ln2h); cudaGetSymbolAddress((void**)&ln2l, g_ln2l);
    cudaGetSymbolAddress((void**)&ffhh, g_ffhh); cudaGetSymbolAddress((void**)&ffhl, g_ffhl);
    cudaGetSymbolAddress((void**)&wqh, g_wqh); cudaGetSymbolAddress((void**)&wql, g_wql);
    cudaGetSymbolAddress((void**)&w1h, g_w1h); cudaGetSymbolAddress((void**)&w1l, g_w1l);
    cudaGetSymbolAddress((void**)&w2h, g_w2h); cudaGetSymbolAddress((void**)&w2l, g_w2l);
    cudaGetSymbolAddress((void**)&qh, g_qh);  cudaGetSymbolAddress((void**)&ql, g_ql2);
    cudaGetSymbolAddress((void**)&kvh, g_kvh); cudaGetSymbolAddress((void**)&kvl, g_kvl);
    cudaGetSymbolAddress((void**)&att, g_att);

    cudaFuncSetAttribute(bf16_gemm, cudaFuncAttributeMaxDynamicSharedMemorySize, GEMM_SMEM);
    cudaFuncSetAttribute(bf16_gemm_kv, cudaFuncAttributeMaxDynamicSharedMemorySize, GEMM_SMEM);
    cudaFuncSetAttribute(flash_attn_mma, cudaFuncAttributeMaxDynamicSharedMemorySize, ATT_SMEM);

    // weight splits + mask compaction
    splitw_all<<<1792, 256>>>(Wq, Wk, Wv, W1, W2);
    build_idx<<<Bb, 1024>>>(mask);

    // layernorms: features gathered/compacted; latents plain
    ln_gather<<<Bb * Ff / 2, 256>>>(features, gf, bf, xnh, xnl);
    ln_kernel2<<<Bb * Qq / 2, 256>>>(latents,  gl, bl, lath, latl);

    // projections: Q plain; K+V fused via z
    bf16_gemm<<<dim3(DIMc / 128, (Bb * Qq) / 128), 256, GEMM_SMEM>>>(
        lath, latl, wqh, wql, nullptr, qh, ql, Bb * Qq, DIMc, DIMc, 0);
    bf16_gemm_kv<<<dim3(DIMc / 128, (Bb * Ff) / 128, 2), 256, GEMM_SMEM>>>(xnh, xnl);

    // attention over compacted F (NSPL=16) + combine
    flash_attn_mma<<<Bb * Hh * NSPL, 256, ATT_SMEM>>>(
        qh, ql, kvh, kvl, kvh + KVSZ, kvl + KVSZ);
    attn_combine<<<Bb * Hh * Qq, DHh>>>(att);

    // feed-forward
    ln_kernel2<<<Bb * Qq / 2, 256>>>(att, gff, bff, ln2h, ln2l);
    bf16_gemm<<<dim3(1024 / 128, (Bb * Qq) / 128), 256, GEMM_SMEM>>>(
        ln2h, ln2l, w1h, w1l, nullptr, ffhh, ffhl, Bb * Qq, 1024, DIMc, 1);
    bf16_gemm<<<dim3(DIMc / 128, (Bb * Qq) / 128), 256, GEMM_SMEM>>>(
        ffhh, ffhl, w2h, w2l, out, nullptr, nullptr, Bb * Qq, DIMc, 1024, 0);
}

// round 16
// speedup vs baseline: 2.7167x; 1.1085x over previous
#include <cuda_runtime.h>
#include <cuda_bf16.h>
#include <cstdint>
#include <math.h>

#define Bb   16
#define Ff   4096
#define Qq   64
#define DIMc 512
#define Hh   8
#define DHh  64
#define FCH  128
#define NSPL 16
#define FSEG (Ff / NSPL)
#define KVW  (DIMc * DIMc)
#define KVSZ ((size_t)Bb * Ff * DIMc)

typedef __nv_bfloat16 bf16;
typedef __nv_bfloat162 bf162;

// ---------------- scratch (device globals; no allocation allowed) ----------------
__device__ bf16  g_xnh [(size_t)Bb * Ff * DIMc];
__device__ bf16  g_xnl [(size_t)Bb * Ff * DIMc];
__device__ bf16  g_lath[(size_t)Bb * Qq * DIMc];
__device__ bf16  g_latl[(size_t)Bb * Qq * DIMc];
__device__ bf16  g_ln2h[(size_t)Bb * Qq * DIMc];
__device__ bf16  g_ln2l[(size_t)Bb * Qq * DIMc];
__device__ bf16  g_ffhh[(size_t)Bb * Qq * 1024];
__device__ bf16  g_ffhl[(size_t)Bb * Qq * 1024];
__device__ bf16  g_wqh[KVW], g_wql[KVW];
__device__ bf16  g_kvwh[2 * KVW], g_kvwl[2 * KVW];
__device__ bf16  g_w1h[DIMc * 1024], g_w1l[DIMc * 1024];
__device__ bf16  g_w2h[1024 * DIMc], g_w2l[1024 * DIMc];
__device__ bf16  g_qh [(size_t)Bb * Qq * DIMc], g_ql2[(size_t)Bb * Qq * DIMc];
__device__ bf16  g_kvh[2 * KVSZ], g_kvl[2 * KVSZ];
__device__ float g_att[(size_t)Bb * Qq * DIMc];
__device__ float g_po [(size_t)Bb * Hh * NSPL * Qq * DHh];
__device__ float g_pm [(size_t)Bb * Hh * NSPL * Qq];
__device__ float g_pl [(size_t)Bb * Hh * NSPL * Qq];
__device__ int   g_idx[Bb * Ff];
__device__ int   g_cnt[Bb];

// ---------------- helpers ----------------
static __device__ __forceinline__ uint32_t smem_u32(const void* p) {
    uint32_t a;
    asm("{ .reg .u64 t; cvta.to.shared.u64 t, %1; cvt.u32.u64 %0, t; }" : "=r"(a) : "l"(p));
    return a;
}
static __device__ __forceinline__ void cpa16(uint32_t dst, const void* src) {
    asm volatile("cp.async.cg.shared.global [%0], [%1], 16;" :: "r"(dst), "l"(src));
}
#define CPA_COMMIT() asm volatile("cp.async.commit_group;" ::: "memory")
#define CPA_WAIT1()  asm volatile("cp.async.wait_group 1;" ::: "memory")
#define CPA_WAIT0()  asm volatile("cp.async.wait_group 0;" ::: "memory")

#define LDSM4(r0, r1, r2, r3, addr)                                        \
    asm volatile("ldmatrix.sync.aligned.m8n8.x4.shared.b16 {%0,%1,%2,%3}, [%4];" \
                 : "=r"(r0), "=r"(r1), "=r"(r2), "=r"(r3) : "r"(addr))

#define LDSM2(r0, r1, addr)                                                \
    asm volatile("ldmatrix.sync.aligned.m8n8.x2.shared.b16 {%0,%1}, [%2];" \
                 : "=r"(r0), "=r"(r1) : "r"(addr))

#define LDSM2T(r0, r1, addr)                                               \
    asm volatile("ldmatrix.sync.aligned.m8n8.x2.trans.shared.b16 {%0,%1}, [%2];" \
                 : "=r"(r0), "=r"(r1) : "r"(addr))

#define MMA_BF16(c, a, b)                                                  \
    asm volatile("mma.sync.aligned.m16n8k16.row.col.f32.bf16.bf16.f32 "    \
                 "{%0,%1,%2,%3}, {%4,%5,%6,%7}, {%8,%9}, {%0,%1,%2,%3};"   \
                 : "+f"((c)[0]), "+f"((c)[1]), "+f"((c)[2]), "+f"((c)[3])  \
                 : "r"((a)[0]), "r"((a)[1]), "r"((a)[2]), "r"((a)[3]),     \
                   "r"((b)[0]), "r"((b)[1]))

static __device__ __forceinline__ void bf16_split(float x, bf16& h, bf16& l) {
    h = __float2bfloat16(x);
    l = __float2bfloat16(x - __bfloat162float(h));
}
static __device__ __forceinline__ void splitpack(float p0, float p1,
                                                 uint32_t& hi, uint32_t& lo) {
    bf16 h0, l0, h1, l1;
    bf16_split(p0, h0, l0);
    bf16_split(p1, h1, l1);
    bf162 H; H.x = h0; H.y = h1;
    bf162 L; L.x = l0; L.y = l1;
    hi = *(uint32_t*)&H;
    lo = *(uint32_t*)&L;
}

// ---------------- mask compaction: per-batch prefix scan ----------------
__global__ void build_idx(const int* __restrict__ mask) {
    __shared__ int ws[32];
    int b = blockIdx.x;
    const int* m = mask + b * Ff;
    int t = threadIdx.x;
    int v[4];
    int s = 0;
    #pragma unroll
    for (int i = 0; i < 4; i++) { v[i] = m[t * 4 + i]; s += v[i]; }
    int lane = t & 31, w = t >> 5;
    int ps = s;
    #pragma unroll
    for (int o = 1; o < 32; o <<= 1) {
        int n = __shfl_up_sync(0xffffffffu, ps, o);
        if (lane >= o) ps += n;
    }
    if (lane == 31) ws[w] = ps;
    __syncthreads();
    if (w == 0) {
        int x = ws[lane];
        #pragma unroll
        for (int o = 1; o < 32; o <<= 1) {
            int n = __shfl_up_sync(0xffffffffu, x, o);
            if (lane >= o) x += n;
        }
        ws[lane] = x;
    }
    __syncthreads();
    int base = ps - s + (w ? ws[w - 1] : 0);
    #pragma unroll
    for (int i = 0; i < 4; i++) {
        if (v[i]) { g_idx[b * Ff + base] = t * 4 + i; base++; }
    }
    if (t == 1023) g_cnt[b] = ws[31];
}

// ---------------- 3xBF16 mma GEMM 128x128 (exact R12 kernel) ----------------
#define STAGE_B    32768
#define GEMM_SMEM  (3 * STAGE_B)

__global__ void __launch_bounds__(256, 2) bf16_gemm(
    const bf16* __restrict__ Ah, const bf16* __restrict__ Al,
    const bf16* __restrict__ Wh, const bf16* __restrict__ Wl,
    float* __restrict__ Cf, bf16* __restrict__ Ch, bf16* __restrict__ Cl,
    int M, int N, int K, int relu)
{
    extern __shared__ __align__(1024) char smem[];
    int tid = threadIdx.x;
    int lane = tid & 31, wid = tid >> 5;
    int bn = blockIdx.x << 7, bm = blockIdx.y << 7;
    uint32_t sbase = smem_u32(smem);

    int wm = (wid & 1) << 6;
    int wn = (wid >> 1) << 5;

    float acc[4][4][4];
    #pragma unroll
    for (int i = 0; i < 4; i++)
        #pragma unroll
        for (int j = 0; j < 4; j++)
            #pragma unroll
            for (int r = 0; r < 4; r++) acc[i][j][r] = 0.f;

    int nCh = K >> 5;

    auto issue = [&](int p, int s) {
        uint32_t st = sbase + s * STAGE_B;
        int k0 = p << 5;
        #pragma unroll
        for (int r = 0; r < 2; r++) {
            int c = r * 256 + tid;
            int m = c >> 2, c4 = c & 3;
            uint32_t off = m * 64 + (c4 << 4);
            uint32_t sw = off ^ ((off >> 3) & 0x30);
            cpa16(st + sw, Ah + (size_t)(bm + m) * K + k0 + c4 * 8);
            cpa16(st + 8192 + sw, Al + (size_t)(bm + m) * K + k0 + c4 * 8);
        }
        #pragma unroll
        for (int r = 0; r < 2; r++) {
            int c = r * 256 + tid;
            int kk = c >> 4, c16 = c & 15;
            uint32_t off = kk * 256 + (c16 << 4);
            uint32_t sw = off ^ ((off >> 4) & 0x70);
            cpa16(st + 16384 + sw, Wh + (size_t)(k0 + kk) * N + bn + c16 * 8);
            cpa16(st + 24576 + sw, Wl + (size_t)(k0 + kk) * N + bn + c16 * 8);
        }
        CPA_COMMIT();
    };

    issue(0, 0);
    if (nCh > 1) issue(1, 1); else CPA_COMMIT();

    int quad = lane >> 3, rr = lane & 7;
    int lrow = ((quad & 1) << 3) + rr;
    int lcol = quad >> 1;
    int bl16 = lane & 15;

    for (int p = 0; p < nCh; p++) {
        CPA_WAIT1();
        __syncthreads();
        int s = p % 3;
        uint32_t aHi = sbase + s * STAGE_B;
        uint32_t aLo = aHi + 8192;
        uint32_t bHi = aHi + 16384;
        uint32_t bLo = aHi + 24576;

        #pragma unroll
        for (int j = 0; j < 2; j++) {
            uint32_t ahf[4][4], alf[4][4];
            #pragma unroll
            for (int mt = 0; mt < 4; mt++) {
                uint32_t off = (uint32_t)(wm + mt * 16 + lrow) * 64 + j * 32 + (lcol << 4);
                uint32_t sw = off ^ ((off >> 3) & 0x30);
                LDSM4(ahf[mt][0], ahf[mt][1], ahf[mt][2], ahf[mt][3], aHi + sw);
                LDSM4(alf[mt][0], alf[mt][1], alf[mt][2], alf[mt][3], aLo + sw);
            }
            uint32_t bhf[4][2], blf[4][2];
            {
                uint32_t krow = j * 16 + bl16;
                #pragma unroll
                for (int nt = 0; nt < 4; nt++) {
                    uint32_t off = krow * 256 + (uint32_t)(wn + nt * 8) * 2;
                    uint32_t sw = off ^ ((off >> 4) & 0x70);
                    LDSM2T(bhf[nt][0], bhf[nt][1], bHi + sw);
                    LDSM2T(blf[nt][0], blf[nt][1], bLo + sw);
                }
            }
            #pragma unroll
            for (int mt = 0; mt < 4; mt++)
                #pragma unroll
                for (int nt = 0; nt < 4; nt++) {
                    MMA_BF16(acc[mt][nt], ahf[mt], bhf[nt]);
                    MMA_BF16(acc[mt][nt], ahf[mt], blf[nt]);
                    MMA_BF16(acc[mt][nt], alf[mt], bhf[nt]);
                }
        }
        if (p + 2 < nCh) issue(p + 2, (p + 2) % 3);
        else CPA_COMMIT();
    }

    int r0 = bm + wm + (lane >> 2);
    int cc = bn + wn + ((lane & 3) << 1);
    #pragma unroll
    for (int mt = 0; mt < 4; mt++) {
        #pragma unroll
        for (int nt = 0; nt < 4; nt++) {
            float v0 = acc[mt][nt][0], v1 = acc[mt][nt][1];
            float v2 = acc[mt][nt][2], v3 = acc[mt][nt][3];
            if (relu) {
                v0 = fmaxf(v0, 0.f); v1 = fmaxf(v1, 0.f);
                v2 = fmaxf(v2, 0.f); v3 = fmaxf(v3, 0.f);
            }
            int row = r0 + mt * 16;
            int col = cc + nt * 8;
            if (Cf) {
                *(float2*)(Cf + (size_t)row * N + col) = make_float2(v0, v1);
                *(float2*)(Cf + (size_t)(row + 8) * N + col) = make_float2(v2, v3);
            } else {
                uint32_t ph, pl;
                splitpack(v0, v1, ph, pl);
                *(uint32_t*)(Ch + (size_t)row * N + col) = ph;
                *(uint32_t*)(Cl + (size_t)row * N + col) = pl;
                splitpack(v2, v3, ph, pl);
                *(uint32_t*)(Ch + (size_t)(row + 8) * N + col) = ph;
                *(uint32_t*)(Cl + (size_t)(row + 8) * N + col) = pl;
            }
        }
    }
}

// ---------------- 64-row-tile variant for small GEMMs (standalone, MT=2) ----------------
#define STAGE64    24576
#define GEMM64_SMEM (3 * STAGE64)

__global__ void __launch_bounds__(256, 2) bf16_gemm64(
    const bf16* __restrict__ Ah, const bf16* __restrict__ Al,
    const bf16* __restrict__ Wh, const bf16* __restrict__ Wl,
    float* __restrict__ Cf, bf16* __restrict__ Ch, bf16* __restrict__ Cl,
    int M, int N, int K, int relu)
{
    extern __shared__ __align__(1024) char smem[];
    int tid = threadIdx.x;
    int lane = tid & 31, wid = tid >> 5;
    int bn = blockIdx.x << 7, bm = blockIdx.y << 6;
    uint32_t sbase = smem_u32(smem);

    int wm = (wid & 1) << 5;      // 0/32
    int wn = (wid >> 1) << 5;

    float acc[2][4][4];
    #pragma unroll
    for (int i = 0; i < 2; i++)
        #pragma unroll
        for (int j = 0; j < 4; j++)
            #pragma unroll
            for (int r = 0; r < 4; r++) acc[i][j][r] = 0.f;

    int nCh = K >> 5;

    auto issue = [&](int p, int s) {
        uint32_t st = sbase + s * STAGE64;
        int k0 = p << 5;
        {
            int c = tid;                       // 256 chunks cover A 64x32 hi+lo
            int m = c >> 2, c4 = c & 3;
            uint32_t off = m * 64 + (c4 << 4);
            uint32_t sw = off ^ ((off >> 3) & 0x30);
            cpa16(st + sw, Ah + (size_t)(bm + m) * K + k0 + c4 * 8);
            cpa16(st + 4096 + sw, Al + (size_t)(bm + m) * K + k0 + c4 * 8);
        }
        #pragma unroll
        for (int r = 0; r < 2; r++) {
            int c = r * 256 + tid;
            int kk = c >> 4, c16 = c & 15;
            uint32_t off = kk * 256 + (c16 << 4);
            uint32_t sw = off ^ ((off >> 4) & 0x70);
            cpa16(st + 8192 + sw, Wh + (size_t)(k0 + kk) * N + bn + c16 * 8);
            cpa16(st + 16384 + sw, Wl + (size_t)(k0 + kk) * N + bn + c16 * 8);
        }
        CPA_COMMIT();
    };

    issue(0, 0);
    if (nCh > 1) issue(1, 1); else CPA_COMMIT();

    int quad = lane >> 3, rr = lane & 7;
    int lrow = ((quad & 1) << 3) + rr;
    int lcol = quad >> 1;
    int bl16 = lane & 15;

    for (int p = 0; p < nCh; p++) {
        CPA_WAIT1();
        __syncthreads();
        int s = p % 3;
        uint32_t aHi = sbase + s * STAGE64;
        uint32_t aLo = aHi + 4096;
        uint32_t bHi = aHi + 8192;
        uint32_t bLo = aHi + 16384;

        #pragma unroll
        for (int j = 0; j < 2; j++) {
            uint32_t ahf[2][4], alf[2][4];
            #pragma unroll
            for (int mt = 0; mt < 2; mt++) {
                uint32_t off = (uint32_t)(wm + mt * 16 + lrow) * 64 + j * 32 + (lcol << 4);
                uint32_t sw = off ^ ((off >> 3) & 0x30);
                LDSM4(ahf[mt][0], ahf[mt][1], ahf[mt][2], ahf[mt][3], aHi + sw);
                LDSM4(alf[mt][0], alf[mt][1], alf[mt][2], alf[mt][3], aLo + sw);
            }
            uint32_t bhf[4][2], blf[4][2];
            {
                uint32_t krow = j * 16 + bl16;
                #pragma unroll
                for (int nt = 0; nt < 4; nt++) {
                    uint32_t off = krow * 256 + (uint32_t)(wn + nt * 8) * 2;
                    uint32_t sw = off ^ ((off >> 4) & 0x70);
                    LDSM2T(bhf[nt][0], bhf[nt][1], bHi + sw);
                    LDSM2T(blf[nt][0], blf[nt][1], bLo + sw);
                }
            }
            #pragma unroll
            for (int mt = 0; mt < 2; mt++)
                #pragma unroll
                for (int nt = 0; nt < 4; nt++) {
                    MMA_BF16(acc[mt][nt], ahf[mt], bhf[nt]);
                    MMA_BF16(acc[mt][nt], ahf[mt], blf[nt]);
                    MMA_BF16(acc[mt][nt], alf[mt], bhf[nt]);
                }
        }
        if (p + 2 < nCh) issue(p + 2, (p + 2) % 3);
        else CPA_COMMIT();
    }

    int r0 = bm + wm + (lane >> 2);
    int cc = bn + wn + ((lane & 3) << 1);
    #pragma unroll
    for (int mt = 0; mt < 2; mt++) {
        #pragma unroll
        for (int nt = 0; nt < 4; nt++) {
            float v0 = acc[mt][nt][0], v1 = acc[mt][nt][1];
            float v2 = acc[mt][nt][2], v3 = acc[mt][nt][3];
            if (relu) {
                v0 = fmaxf(v0, 0.f); v1 = fmaxf(v1, 0.f);
                v2 = fmaxf(v2, 0.f); v3 = fmaxf(v3, 0.f);
            }
            int row = r0 + mt * 16;
            int col = cc + nt * 8;
            if (Cf) {
                *(float2*)(Cf + (size_t)row * N + col) = make_float2(v0, v1);
                *(float2*)(Cf + (size_t)(row + 8) * N + col) = make_float2(v2, v3);
            } else {
                uint32_t ph, pl;
                splitpack(v0, v1, ph, pl);
                *(uint32_t*)(Ch + (size_t)row * N + col) = ph;
                *(uint32_t*)(Cl + (size_t)row * N + col) = pl;
                splitpack(v2, v3, ph, pl);
                *(uint32_t*)(Ch + (size_t)(row + 8) * N + col) = ph;
                *(uint32_t*)(Cl + (size_t)(row + 8) * N + col) = pl;
            }
        }
    }
}

// ---------------- fused K+V projection (z via global strides) ----------------
__global__ void __launch_bounds__(256, 2) bf16_gemm_kv(
    const bf16* __restrict__ Ah, const bf16* __restrict__ Al)
{
    if (((int)(blockIdx.y & 31) << 7) >= g_cnt[blockIdx.y >> 5]) return;

    const int N = DIMc, K = DIMc;
    const bf16* Wh = g_kvwh + (size_t)blockIdx.z * KVW;
    const bf16* Wl = g_kvwl + (size_t)blockIdx.z * KVW;
    bf16* Ch = g_kvh + (size_t)blockIdx.z * KVSZ;
    bf16* Cl = g_kvl + (size_t)blockIdx.z * KVSZ;

    extern __shared__ __align__(1024) char smem[];
    int tid = threadIdx.x;
    int lane = tid & 31, wid = tid >> 5;
    int bn = blockIdx.x << 7, bm = blockIdx.y << 7;
    uint32_t sbase = smem_u32(smem);

    int wm = (wid & 1) << 6;
    int wn = (wid >> 1) << 5;

    float acc[4][4][4];
    #pragma unroll
    for (int i = 0; i < 4; i++)
        #pragma unroll
        for (int j = 0; j < 4; j++)
            #pragma unroll
            for (int r = 0; r < 4; r++) acc[i][j][r] = 0.f;

    int nCh = K >> 5;

    auto issue = [&](int p, int s) {
        uint32_t st = sbase + s * STAGE_B;
        int k0 = p << 5;
        #pragma unroll
        for (int r = 0; r < 2; r++) {
            int c = r * 256 + tid;
            int m = c >> 2, c4 = c & 3;
            uint32_t off = m * 64 + (c4 << 4);
            uint32_t sw = off ^ ((off >> 3) & 0x30);
            cpa16(st + sw, Ah + (size_t)(bm + m) * K + k0 + c4 * 8);
            cpa16(st + 8192 + sw, Al + (size_t)(bm + m) * K + k0 + c4 * 8);
        }
        #pragma unroll
        for (int r = 0; r < 2; r++) {
            int c = r * 256 + tid;
            int kk = c >> 4, c16 = c & 15;
            uint32_t off = kk * 256 + (c16 << 4);
            uint32_t sw = off ^ ((off >> 4) & 0x70);
            cpa16(st + 16384 + sw, Wh + (size_t)(k0 + kk) * N + bn + c16 * 8);
            cpa16(st + 24576 + sw, Wl + (size_t)(k0 + kk) * N + bn + c16 * 8);
        }
        CPA_COMMIT();
    };

    issue(0, 0);
    if (nCh > 1) issue(1, 1); else CPA_COMMIT();

    int quad = lane >> 3, rr = lane & 7;
    int lrow = ((quad & 1) << 3) + rr;
    int lcol = quad >> 1;
    int bl16 = lane & 15;

    for (int p = 0; p < nCh; p++) {
        CPA_WAIT1();
        __syncthreads();
        int s = p % 3;
        uint32_t aHi = sbase + s * STAGE_B;
        uint32_t aLo = aHi + 8192;
        uint32_t bHi = aHi + 16384;
        uint32_t bLo = aHi + 24576;

        #pragma unroll
        for (int j = 0; j < 2; j++) {
            uint32_t ahf[4][4], alf[4][4];
            #pragma unroll
            for (int mt = 0; mt < 4; mt++) {
                uint32_t off = (uint32_t)(wm + mt * 16 + lrow) * 64 + j * 32 + (lcol << 4);
                uint32_t sw = off ^ ((off >> 3) & 0x30);
                LDSM4(ahf[mt][0], ahf[mt][1], ahf[mt][2], ahf[mt][3], aHi + sw);
                LDSM4(alf[mt][0], alf[mt][1], alf[mt][2], alf[mt][3], aLo + sw);
            }
            uint32_t bhf[4][2], blf[4][2];
            {
                uint32_t krow = j * 16 + bl16;
                #pragma unroll
                for (int nt = 0; nt < 4; nt++) {
                    uint32_t off = krow * 256 + (uint32_t)(wn + nt * 8) * 2;
                    uint32_t sw = off ^ ((off >> 4) & 0x70);
                    LDSM2T(bhf[nt][0], bhf[nt][1], bHi + sw);
                    LDSM2T(blf[nt][0], blf[nt][1], bLo + sw);
                }
            }
            #pragma unroll
            for (int mt = 0; mt < 4; mt++)
                #pragma unroll
                for (int nt = 0; nt < 4; nt++) {
                    MMA_BF16(acc[mt][nt], ahf[mt], bhf[nt]);
                    MMA_BF16(acc[mt][nt], ahf[mt], blf[nt]);
                    MMA_BF16(acc[mt][nt], alf[mt], bhf[nt]);
                }
        }
        if (p + 2 < nCh) issue(p + 2, (p + 2) % 3);
        else CPA_COMMIT();
    }

    int r0 = bm + wm + (lane >> 2);
    int cc = bn + wn + ((lane & 3) << 1);
    #pragma unroll
    for (int mt = 0; mt < 4; mt++) {
        #pragma unroll
        for (int nt = 0; nt < 4; nt++) {
            int row = r0 + mt * 16;
            int col = cc + nt * 8;
            uint32_t ph, pl;
            splitpack(acc[mt][nt][0], acc[mt][nt][1], ph, pl);
            *(uint32_t*)(Ch + (size_t)row * N + col) = ph;
            *(uint32_t*)(Cl + (size_t)row * N + col) = pl;
            splitpack(acc[mt][nt][2], acc[mt][nt][3], ph, pl);
            *(uint32_t*)(Ch + (size_t)(row + 8) * N + col) = ph;
            *(uint32_t*)(Cl + (size_t)(row + 8) * N + col) = pl;
        }
    }
}

// ---------------- all weight splits in one launch ----------------
__global__ void splitw_all(const float* __restrict__ Wq, const float* __restrict__ Wk,
                           const float* __restrict__ Wv, const float* __restrict__ W1,
                           const float* __restrict__ W2) {
    int q = blockIdx.x * 256 + threadIdx.x;
    const float* src; bf16 *dh, *dl; int off;
    if (q < 65536)        { src = Wq; dh = g_wqh;        dl = g_wql;        off = q; }
    else if (q < 131072)  { src = Wk; dh = g_kvwh;       dl = g_kvwl;       off = q - 65536; }
    else if (q < 196608)  { src = Wv; dh = g_kvwh + KVW; dl = g_kvwl + KVW; off = q - 131072; }
    else if (q < 327680)  { src = W1; dh = g_w1h;        dl = g_w1l;        off = q - 196608; }
    else                  { src = W2; dh = g_w2h;        dl = g_w2l;        off = q - 327680; }
    float4 v = ((const float4*)src)[off];
    uint32_t h01, l01, h23, l23;
    splitpack(v.x, v.y, h01, l01);
    splitpack(v.z, v.w, h23, l23);
    *(uint2*)(dh + (size_t)off * 4) = make_uint2(h01, h23);
    *(uint2*)(dl + (size_t)off * 4) = make_uint2(l01, l23);
}

// ---------------- LayerNorm: 2 rows per block -> bf16 hi/lo ----------------
__global__ void ln_kernel2(const float* __restrict__ x, const float* __restrict__ g,
                           const float* __restrict__ beta,
                           bf16* __restrict__ yh, bf16* __restrict__ yl) {
    __shared__ float sm[8];
    int half = threadIdx.x >> 7;
    int t = threadIdx.x & 127;
    size_t row = (size_t)blockIdx.x * 2 + half;
    float4 v = ((const float4*)(x + row * DIMc))[t];
    float s = v.x + v.y + v.z + v.w;
    #pragma unroll
    for (int o = 16; o; o >>= 1) s += __shfl_xor_sync(0xffffffffu, s, o);
    if ((t & 31) == 0) sm[threadIdx.x >> 5] = s;
    __syncthreads();
    int sb = half * 4;
    float mean = (sm[sb] + sm[sb + 1] + sm[sb + 2] + sm[sb + 3]) * (1.0f / DIMc);
    __syncthreads();
    float dx = v.x - mean, dy = v.y - mean, dz = v.z - mean, dw = v.w - mean;
    float sq = dx * dx + dy * dy + dz * dz + dw * dw;
    #pragma unroll
    for (int o = 16; o; o >>= 1) sq += __shfl_xor_sync(0xffffffffu, sq, o);
    if ((t & 31) == 0) sm[threadIdx.x >> 5] = sq;
    __syncthreads();
    float var = (sm[sb] + sm[sb + 1] + sm[sb + 2] + sm[sb + 3]) * (1.0f / DIMc);
    float rstd = rsqrtf(var + 1e-5f);
    float4 gg = ((const float4*)g)[t];
    float4 bb = ((const float4*)beta)[t];
    float o0 = dx * rstd * gg.x + bb.x;
    float o1 = dy * rstd * gg.y + bb.y;
    float o2 = dz * rstd * gg.z + bb.z;
    float o3 = dw * rstd * gg.w + bb.w;
    uint32_t h01, l01, h23, l23;
    splitpack(o0, o1, h01, l01);
    splitpack(o2, o3, h23, l23);
    *(uint2*)(yh + row * DIMc + t * 4) = make_uint2(h01, h23);
    *(uint2*)(yl + row * DIMc + t * 4) = make_uint2(l01, l23);
}

// ---------------- LN + gather: compacted rows; zero only up to 128-aligned boundary ----------------
__global__ void ln_gather(const float* __restrict__ x, const float* __restrict__ g,
                          const float* __restrict__ beta,
                          bf16* __restrict__ yh, bf16* __restrict__ yl) {
    __shared__ float sm[8];
    int half = threadIdx.x >> 7;
    int t = threadIdx.x & 127;
    size_t row = (size_t)blockIdx.x * 2 + half;
    int b = (int)(row >> 12);
    int r = (int)(row & (Ff - 1));
    int cnt = g_cnt[b];
    if (r >= cnt) {
        int cntUp = (cnt + 127) & ~127;
        if (r < cntUp) {
            *(uint2*)(yh + row * DIMc + t * 4) = make_uint2(0u, 0u);
            *(uint2*)(yl + row * DIMc + t * 4) = make_uint2(0u, 0u);
        }
        return;
    }
    size_t src = (size_t)b * Ff + g_idx[b * Ff + r];
    float4 v = ((const float4*)(x + src * DIMc))[t];
    float s = v.x + v.y + v.z + v.w;
    #pragma unroll
    for (int o = 16; o; o >>= 1) s += __shfl_xor_sync(0xffffffffu, s, o);
    if ((t & 31) == 0) sm[threadIdx.x >> 5] = s;
    __syncthreads();
    int sb = half * 4;
    float mean = (sm[sb] + sm[sb + 1] + sm[sb + 2] + sm[sb + 3]) * (1.0f / DIMc);
    __syncthreads();
    float dx = v.x - mean, dy = v.y - mean, dz = v.z - mean, dw = v.w - mean;
    float sq = dx * dx + dy * dy + dz * dz + dw * dw;
    #pragma unroll
    for (int o = 16; o; o >>= 1) sq += __shfl_xor_sync(0xffffffffu, sq, o);
    if ((t & 31) == 0) sm[threadIdx.x >> 5] = sq;
    __syncthreads();
    float var = (sm[sb] + sm[sb + 1] + sm[sb + 2] + sm[sb + 3]) * (1.0f / DIMc);
    float rstd = rsqrtf(var + 1e-5f);
    float4 gg = ((const float4*)g)[t];
    float4 bb = ((const float4*)beta)[t];
    float o0 = dx * rstd * gg.x + bb.x;
    float o1 = dy * rstd * gg.y + bb.y;
    float o2 = dz * rstd * gg.z + bb.z;
    float o3 = dw * rstd * gg.w + bb.w;
    uint32_t h01, l01, h23, l23;
    splitpack(o0, o1, h01, l01);
    splitpack(o2, o3, h23, l23);
    *(uint2*)(yh + row * DIMc + t * 4) = make_uint2(h01, h23);
    *(uint2*)(yl + row * DIMc + t * 4) = make_uint2(l01, l23);
}

// ---------------- flash attention over compacted F (K/V load overlap) ----------------
#define oQh   0
#define oQl   8192
#define oKh   16384
#define oKl   32768
#define oVh   49152
#define oVl   65536
#define oPmax 81920
#define oPsum 82432
#define ATT_SMEM 82944

__global__ void __launch_bounds__(256, 2) flash_attn_mma(
    const bf16* __restrict__ qh, const bf16* __restrict__ ql,
    const bf16* __restrict__ kh, const bf16* __restrict__ kl,
    const bf16* __restrict__ vh, const bf16* __restrict__ vl)
{
    extern __shared__ __align__(1024) char sm_[];
    uint32_t sb = smem_u32(sm_);
    int tid = threadIdx.x, lane = tid & 31, wid = tid >> 5;
    int wm = (wid & 3) << 4;
    int wn = wid >> 2;
    int c  = blockIdx.x & (NSPL - 1);
    int h  = (blockIdx.x >> 4) & 7;
    int b  = blockIdx.x >> 7;
    int pbase = (b * Hh + h) * NSPL + c;
    int cnt = g_cnt[b];

    size_t qoff = (size_t)b * Qq * DIMc + h * DHh;
    size_t koff = (size_t)b * Ff * DIMc + h * DHh;

    float* pmax = (float*)(sm_ + oPmax);
    float* psum = (float*)(sm_ + oPsum);

    int fbeg = c * FSEG;
    if (fbeg >= cnt) {
        if (tid < 64 && wid == 0) {
            g_pm[(size_t)pbase * Qq + tid] = -INFINITY;
            g_pl[(size_t)pbase * Qq + tid] = 0.f;
        }
        for (int r = tid; r < Qq * DHh; r += 256)
            g_po[(size_t)pbase * Qq * DHh + r] = 0.f;
        return;
    }

    #pragma unroll
    for (int r = 0; r < 2; r++) {
        int idx = r * 256 + tid;
        int row = idx >> 3, ch = idx & 7;
        uint32_t off = row * 128 + (ch << 4);
        uint32_t sw = off ^ ((off >> 3) & 0x70);
        cpa16(sb + oQh + sw, qh + qoff + (size_t)row * DIMc + ch * 8);
        cpa16(sb + oQl + sw, ql + qoff + (size_t)row * DIMc + ch * 8);
    }
    CPA_COMMIT();

    float m0 = -INFINITY, m1 = -INFINITY, l0 = 0.f, l1 = 0.f;
    float O[8][4];
    #pragma unroll
    for (int nt = 0; nt < 8; nt++)
        #pragma unroll
        for (int r = 0; r < 4; r++) O[nt][r] = 0.f;

    int quad = lane >> 3, rr = lane & 7;
    int lrow = ((quad & 1) << 3) + rr;
    int lcol = quad >> 1;
    int row0 = wm + (lane >> 2);

    for (int f0 = fbeg; f0 < fbeg + FSEG; f0 += FCH) {
        if (f0 >= cnt) break;
        __syncthreads();
        // K group first, then V group: compute S under the V load
        #pragma unroll
        for (int r = 0; r < 4; r++) {
            int idx = r * 256 + tid;
            int row = idx >> 3, ch = idx & 7;
            uint32_t off = row * 128 + (ch << 4);
            uint32_t sw = off ^ ((off >> 3) & 0x70);
            size_t g = koff + (size_t)(f0 + row) * DIMc + ch * 8;
            cpa16(sb + oKh + sw, kh + g);
            cpa16(sb + oKl + sw, kl + g);
        }
        CPA_COMMIT();
        #pragma unroll
        for (int r = 0; r < 4; r++) {
            int idx = r * 256 + tid;
            int row = idx >> 3, ch = idx & 7;
            uint32_t off = row * 128 + (ch << 4);
            uint32_t sw = off ^ ((off >> 3) & 0x70);
            size_t g = koff + (size_t)(f0 + row) * DIMc + ch * 8;
            cpa16(sb + oVh + sw, vh + g);
            cpa16(sb + oVl + sw, vl + g);
        }
        CPA_COMMIT();
        CPA_WAIT1();                 // Q (first iter) + K complete; V may be in flight
        __syncthreads();

        float S[8][4];
        #pragma unroll
        for (int nt = 0; nt < 8; nt++)
            #pragma unroll
            for (int r = 0; r < 4; r++) S[nt][r] = 0.f;

        #pragma unroll
        for (int j = 0; j < 4; j++) {
            uint32_t qoffb = (uint32_t)(wm + lrow) * 128 + j * 32 + (lcol << 4);
            uint32_t qsw = qoffb ^ ((qoffb >> 3) & 0x70);
            uint32_t qhf[4], qlf[4];
            LDSM4(qhf[0], qhf[1], qhf[2], qhf[3], sb + oQh + qsw);
            LDSM4(qlf[0], qlf[1], qlf[2], qlf[3], sb + oQl + qsw);
            #pragma unroll
            for (int nt = 0; nt < 8; nt++) {
                int fr = wn * 64 + nt * 8 + (lane & 7);
                int seg = (lane >> 3) & 1;
                uint32_t boff = (uint32_t)fr * 128 + j * 32 + (seg << 4);
                uint32_t bsw = boff ^ ((boff >> 3) & 0x70);
                uint32_t kbh[2], kbl[2];
                LDSM2(kbh[0], kbh[1], sb + oKh + bsw);
                LDSM2(kbl[0], kbl[1], sb + oKl + bsw);
                MMA_BF16(S[nt], qhf, kbh);
                MMA_BF16(S[nt], qhf, kbl);
                MMA_BF16(S[nt], qlf, kbh);
            }
        }

        #pragma unroll
        for (int nt = 0; nt < 8; nt++) {
            int col0 = f0 + wn * 64 + nt * 8 + ((lane & 3) << 1);
            int mj0 = col0 < cnt, mj1 = (col0 + 1) < cnt;
            S[nt][0] = mj0 ? S[nt][0] * 0.125f : -INFINITY;
            S[nt][2] = mj0 ? S[nt][2] * 0.125f : -INFINITY;
            S[nt][1] = mj1 ? S[nt][1] * 0.125f : -INFINITY;
            S[nt][3] = mj1 ? S[nt][3] * 0.125f : -INFINITY;
        }

        float rx0 = -INFINITY, rx1 = -INFINITY;
        #pragma unroll
        for (int nt = 0; nt < 8; nt++) {
            rx0 = fmaxf(rx0, fmaxf(S[nt][0], S[nt][1]));
            rx1 = fmaxf(rx1, fmaxf(S[nt][2], S[nt][3]));
        }
        rx0 = fmaxf(rx0, __shfl_xor_sync(0xffffffffu, rx0, 1));
        rx0 = fmaxf(rx0, __shfl_xor_sync(0xffffffffu, rx0, 2));
        rx1 = fmaxf(rx1, __shfl_xor_sync(0xffffffffu, rx1, 1));
        rx1 = fmaxf(rx1, __shfl_xor_sync(0xffffffffu, rx1, 2));
        if ((lane & 3) == 0) {
            pmax[wn * 64 + row0] = rx0;
            pmax[wn * 64 + row0 + 8] = rx1;
        }
        __syncthreads();
        float nm0 = fmaxf(m0, fmaxf(pmax[row0], pmax[64 + row0]));
        float nm1 = fmaxf(m1, fmaxf(pmax[row0 + 8], pmax[64 + row0 + 8]));
        float sf0 = (nm0 == -INFINITY) ? 1.f : __expf(m0 - nm0);
        float sf1 = (nm1 == -INFINITY) ? 1.f : __expf(m1 - nm1);

        float rs0 = 0.f, rs1 = 0.f;
        #pragma unroll
        for (int nt = 0; nt < 8; nt++) {
            float e0 = (S[nt][0] == -INFINITY) ? 0.f : __expf(S[nt][0] - nm0);
            float e1 = (S[nt][1] == -INFINITY) ? 0.f : __expf(S[nt][1] - nm0);
            float e2 = (S[nt][2] == -INFINITY) ? 0.f : __expf(S[nt][2] - nm1);
            float e3 = (S[nt][3] == -INFINITY) ? 0.f : __expf(S[nt][3] - nm1);
            S[nt][0] = e0; S[nt][1] = e1; S[nt][2] = e2; S[nt][3] = e3;
            rs0 += e0 + e1; rs1 += e2 + e3;
        }
        rs0 += __shfl_xor_sync(0xffffffffu, rs0, 1);
        rs0 += __shfl_xor_sync(0xffffffffu, rs0, 2);
        rs1 += __shfl_xor_sync(0xffffffffu, rs1, 1);
        rs1 += __shfl_xor_sync(0xffffffffu, rs1, 2);
        if ((lane & 3) == 0) {
            psum[wn * 64 + row0] = rs0;
            psum[wn * 64 + row0 + 8] = rs1;
        }
        CPA_WAIT0();                 // V complete before the barrier below
        __syncthreads();
        l0 = l0 * sf0 + psum[row0] + psum[64 + row0];
        l1 = l1 * sf1 + psum[row0 + 8] + psum[64 + row0 + 8];
        m0 = nm0; m1 = nm1;
        #pragma unroll
        for (int nt = 0; nt < 8; nt++) {
            O[nt][0] *= sf0; O[nt][1] *= sf0;
            O[nt][2] *= sf1; O[nt][3] *= sf1;
        }

        #pragma unroll
        for (int j = 0; j < 4; j++) {
            uint32_t pah[4], pal[4];
            splitpack(S[2 * j][0], S[2 * j][1], pah[0], pal[0]);
            splitpack(S[2 * j][2], S[2 * j][3], pah[1], pal[1]);
            splitpack(S[2 * j + 1][0], S[2 * j + 1][1], pah[2], pal[2]);
            splitpack(S[2 * j + 1][2], S[2 * j + 1][3], pah[3], pal[3]);
            uint32_t frow = (uint32_t)(wn * 64 + j * 16 + (lane & 15));
            #pragma unroll
            for (int nt = 0; nt < 8; nt++) {
                uint32_t off = frow * 128 + (nt << 4);
                uint32_t sw = off ^ ((off >> 3) & 0x70);
                uint32_t vbh[2], vbl[2];
                LDSM2T(vbh[0], vbh[1], sb + oVh + sw);
                LDSM2T(vbl[0], vbl[1], sb + oVl + sw);
                MMA_BF16(O[nt], pah, vbh);
                MMA_BF16(O[nt], pah, vbl);
                MMA_BF16(O[nt], pal, vbh);
            }
        }
    }

    __syncthreads();
    float* ob = (float*)(sm_ + oKh);
    float* obw = ob + wn * 4096;
    #pragma unroll
    for (int nt = 0; nt < 8; nt++) {
        int col = nt * 8 + ((lane & 3) << 1);
        obw[row0 * 64 + col] = O[nt][0];
        obw[row0 * 64 + col + 1] = O[nt][1];
        obw[(row0 + 8) * 64 + col] = O[nt][2];
        obw[(row0 + 8) * 64 + col + 1] = O[nt][3];
    }
    if ((lane & 3) == 0 && wn == 0) {
        g_pm[(size_t)pbase * Qq + row0] = m0;
        g_pl[(size_t)pbase * Qq + row0] = l0;
        g_pm[(size_t)pbase * Qq + row0 + 8] = m1;
        g_pl[(size_t)pbase * Qq + row0 + 8] = l1;
    }
    __syncthreads();
    #pragma unroll
    for (int r = 0; r < 16; r++) {
        int idx = r * 256 + tid;
        int qq = idx >> 6, dd = idx & 63;
        g_po[((size_t)pbase * Qq + qq) * DHh + dd] = ob[qq * 64 + dd] + ob[4096 + qq * 64 + dd];
    }
}

// ---------------- combine partials ----------------
__global__ void attn_combine(float* __restrict__ out) {
    int bh = blockIdx.x >> 6;
    int q  = blockIdx.x & 63;
    int b  = bh >> 3, h = bh & 7;
    int d  = threadIdx.x;

    float mc[NSPL], lc[NSPL];
    float M = -INFINITY;
    #pragma unroll
    for (int c = 0; c < NSPL; c++) {
        mc[c] = g_pm[((size_t)bh * NSPL + c) * Qq + q];
        lc[c] = g_pl[((size_t)bh * NSPL + c) * Qq + q];
        M = fmaxf(M, mc[c]);
    }
    float r = 0.f;
    if (M != -INFINITY) {
        float num = 0.f, den = 0.f;
        #pragma unroll
        for (int c = 0; c < NSPL; c++) {
            if (mc[c] != -INFINITY) {
                float w = __expf(mc[c] - M);
                den += w * lc[c];
                num += w * g_po[(((size_t)bh * NSPL + c) * Qq + q) * DHh + d];
            }
        }
        r = (den > 0.f) ? num / den : 0.f;
    }
    out[((size_t)(b * Qq + q)) * DIMc + h * DHh + d] = r;
}

// ---------------- launch ----------------
extern "C" void kernel_launch(void* const* d_in, const int* in_sizes, int n_in,
                              void* d_out, int out_size) {
    const float* features = (const float*)d_in[0];
    const float* latents  = (const float*)d_in[1];
    const int*   mask     = (const int*)  d_in[2];
    const float* gf  = (const float*)d_in[3];
    const float* bf  = (const float*)d_in[4];
    const float* gl  = (const float*)d_in[5];
    const float* bl  = (const float*)d_in[6];
    const float* Wq  = (const float*)d_in[7];
    const float* Wk  = (const float*)d_in[8];
    const float* Wv  = (const float*)d_in[9];
    const float* gff = (const float*)d_in[10];
    const float* bff = (const float*)d_in[11];
    const float* W1  = (const float*)d_in[12];
    const float* W2  = (const float*)d_in[13];
    float* out = (float*)d_out;

    bf16 *xnh, *xnl, *lath, *latl, *ln2h, *ln2l, *ffhh, *ffhl;
    bf16 *wqh, *wql, *w1h, *w1l, *w2h, *w2l;
    bf16 *qh, *ql, *kvh, *kvl;
    float *att;
    cudaGetSymbolAddress((void**)&xnh,  g_xnh);  cudaGetSymbolAddress((void**)&xnl,  g_xnl);
    cudaGetSymbolAddress((void**)&lath, g_lath); cudaGetSymbolAddress((void**)&latl, g_latl);
    cudaGetSymbolAddress((void**)&ln2h, g_ln2h); cudaGetSymbolAddress((void**)&ln2l, g_ln2l);
    cudaGetSymbolAddress((void**)&ffhh, g_ffhh); cudaGetSymbolAddress((void**)&ffhl, g_ffhl);
    cudaGetSymbolAddress((void**)&wqh, g_wqh); cudaGetSymbolAddress((void**)&wql, g_wql);
    cudaGetSymbolAddress((void**)&w1h, g_w1h); cudaGetSymbolAddress((void**)&w1l, g_w1l);
    cudaGetSymbolAddress((void**)&w2h, g_w2h); cudaGetSymbolAddress((void**)&w2l, g_w2l);
    cudaGetSymbolAddress((void**)&qh, g_qh);  cudaGetSymbolAddress((void**)&ql, g_ql2);
    cudaGetSymbolAddress((void**)&kvh, g_kvh); cudaGetSymbolAddress((void**)&kvl, g_kvl);
    cudaGetSymbolAddress((void**)&att, g_att);

    cudaFuncSetAttribute(bf16_gemm, cudaFuncAttributeMaxDynamicSharedMemorySize, GEMM_SMEM);
    cudaFuncSetAttribute(bf16_gemm64, cudaFuncAttributeMaxDynamicSharedMemorySize, GEMM64_SMEM);
    cudaFuncSetAttribute(bf16_gemm_kv, cudaFuncAttributeMaxDynamicSharedMemorySize, GEMM_SMEM);
    cudaFuncSetAttribute(flash_attn_mma, cudaFuncAttributeMaxDynamicSharedMemorySize, ATT_SMEM);

    // weight splits + mask compaction
    splitw_all<<<1792, 256>>>(Wq, Wk, Wv, W1, W2);
    build_idx<<<Bb, 1024>>>(mask);

    // layernorms: features gathered/compacted; latents plain
    ln_gather<<<Bb * Ff / 2, 256>>>(features, gf, bf, xnh, xnl);
    ln_kernel2<<<Bb * Qq / 2, 256>>>(latents,  gl, bl, lath, latl);

    // projections: Q (64-row tiles); K+V fused via z
    bf16_gemm64<<<dim3(DIMc / 128, (Bb * Qq) / 64), 256, GEMM64_SMEM>>>(
        lath, latl, wqh, wql, nullptr, qh, ql, Bb * Qq, DIMc, DIMc, 0);
    bf16_gemm_kv<<<dim3(DIMc / 128, (Bb * Ff) / 128, 2), 256, GEMM_SMEM>>>(xnh, xnl);

    // attention over compacted F (NSPL=16) + combine
    flash_attn_mma<<<Bb * Hh * NSPL, 256, ATT_SMEM>>>(
        qh, ql, kvh, kvl, kvh + KVSZ, kvl + KVSZ);
    attn_combine<<<Bb * Hh * Qq, DHh>>>(att);

    // feed-forward (64-row tiles)
    ln_kernel2<<<Bb * Qq / 2, 256>>>(att, gff, bff, ln2h, ln2l);
    bf16_gemm64<<<dim3(1024 / 128, (Bb * Qq) / 64), 256, GEMM64_SMEM>>>(
        ln2h, ln2l, w1h, w1l, nullptr, ffhh, ffhl, Bb * Qq, 1024, DIMc, 1);
    bf16_gemm64<<<dim3(DIMc / 128, (Bb * Qq) / 64), 256, GEMM64_SMEM>>>(
        ffhh, ffhl, w2h, w2l, out, nullptr, nullptr, Bb * Qq, DIMc, 1024, 0);
}

// round 17
// speedup vs baseline: 2.8042x; 1.0322x over previous
#include <cuda_runtime.h>
#include <cuda_bf16.h>
#include <cstdint>
#include <math.h>

#define Bb   16
#define Ff   4096
#define Qq   64
#define DIMc 512
#define Hh   8
#define DHh  64
#define FCH  128
#define NSPL 16
#define FSEG (Ff / NSPL)
#define KVW  (DIMc * DIMc)
#define KVSZ ((size_t)Bb * Ff * DIMc)

typedef __nv_bfloat16 bf16;
typedef __nv_bfloat162 bf162;

// ---------------- scratch (device globals; no allocation allowed) ----------------
__device__ bf16  g_xnh [(size_t)Bb * Ff * DIMc];
__device__ bf16  g_xnl [(size_t)Bb * Ff * DIMc];
__device__ bf16  g_lath[(size_t)Bb * Qq * DIMc];
__device__ bf16  g_latl[(size_t)Bb * Qq * DIMc];
__device__ bf16  g_ln2h[(size_t)Bb * Qq * DIMc];
__device__ bf16  g_ln2l[(size_t)Bb * Qq * DIMc];
__device__ bf16  g_ffhh[(size_t)Bb * Qq * 1024];
__device__ bf16  g_ffhl[(size_t)Bb * Qq * 1024];
__device__ bf16  g_wqh[KVW], g_wql[KVW];
__device__ bf16  g_kvwh[2 * KVW], g_kvwl[2 * KVW];
__device__ bf16  g_w1h[DIMc * 1024], g_w1l[DIMc * 1024];
__device__ bf16  g_w2h[1024 * DIMc], g_w2l[1024 * DIMc];
__device__ bf16  g_qh [(size_t)Bb * Qq * DIMc], g_ql2[(size_t)Bb * Qq * DIMc];
__device__ bf16  g_kvh[2 * KVSZ], g_kvl[2 * KVSZ];
__device__ float g_att[(size_t)Bb * Qq * DIMc];
__device__ float g_po [(size_t)Bb * Hh * NSPL * Qq * DHh];
__device__ float g_pm [(size_t)Bb * Hh * NSPL * Qq];
__device__ float g_pl [(size_t)Bb * Hh * NSPL * Qq];
__device__ int   g_idx[Bb * Ff];
__device__ int   g_cnt[Bb];

// ---------------- helpers ----------------
static __device__ __forceinline__ uint32_t smem_u32(const void* p) {
    uint32_t a;
    asm("{ .reg .u64 t; cvta.to.shared.u64 t, %1; cvt.u32.u64 %0, t; }" : "=r"(a) : "l"(p));
    return a;
}
static __device__ __forceinline__ void cpa16(uint32_t dst, const void* src) {
    asm volatile("cp.async.cg.shared.global [%0], [%1], 16;" :: "r"(dst), "l"(src));
}
#define CPA_COMMIT() asm volatile("cp.async.commit_group;" ::: "memory")
#define CPA_WAIT1()  asm volatile("cp.async.wait_group 1;" ::: "memory")
#define CPA_WAIT0()  asm volatile("cp.async.wait_group 0;" ::: "memory")

#define LDSM4(r0, r1, r2, r3, addr)                                        \
    asm volatile("ldmatrix.sync.aligned.m8n8.x4.shared.b16 {%0,%1,%2,%3}, [%4];" \
                 : "=r"(r0), "=r"(r1), "=r"(r2), "=r"(r3) : "r"(addr))

#define LDSM2(r0, r1, addr)                                                \
    asm volatile("ldmatrix.sync.aligned.m8n8.x2.shared.b16 {%0,%1}, [%2];" \
                 : "=r"(r0), "=r"(r1) : "r"(addr))

#define LDSM2T(r0, r1, addr)                                               \
    asm volatile("ldmatrix.sync.aligned.m8n8.x2.trans.shared.b16 {%0,%1}, [%2];" \
                 : "=r"(r0), "=r"(r1) : "r"(addr))

#define MMA_BF16(c, a, b)                                                  \
    asm volatile("mma.sync.aligned.m16n8k16.row.col.f32.bf16.bf16.f32 "    \
                 "{%0,%1,%2,%3}, {%4,%5,%6,%7}, {%8,%9}, {%0,%1,%2,%3};"   \
                 : "+f"((c)[0]), "+f"((c)[1]), "+f"((c)[2]), "+f"((c)[3])  \
                 : "r"((a)[0]), "r"((a)[1]), "r"((a)[2]), "r"((a)[3]),     \
                   "r"((b)[0]), "r"((b)[1]))

static __device__ __forceinline__ void bf16_split(float x, bf16& h, bf16& l) {
    h = __float2bfloat16(x);
    l = __float2bfloat16(x - __bfloat162float(h));
}
static __device__ __forceinline__ void splitpack(float p0, float p1,
                                                 uint32_t& hi, uint32_t& lo) {
    bf16 h0, l0, h1, l1;
    bf16_split(p0, h0, l0);
    bf16_split(p1, h1, l1);
    bf162 H; H.x = h0; H.y = h1;
    bf162 L; L.x = l0; L.y = l1;
    hi = *(uint32_t*)&H;
    lo = *(uint32_t*)&L;
}

// ---------------- mask compaction: per-batch prefix scan ----------------
__global__ void build_idx(const int* __restrict__ mask) {
    __shared__ int ws[32];
    int b = blockIdx.x;
    const int* m = mask + b * Ff;
    int t = threadIdx.x;
    int v[4];
    int s = 0;
    #pragma unroll
    for (int i = 0; i < 4; i++) { v[i] = m[t * 4 + i]; s += v[i]; }
    int lane = t & 31, w = t >> 5;
    int ps = s;
    #pragma unroll
    for (int o = 1; o < 32; o <<= 1) {
        int n = __shfl_up_sync(0xffffffffu, ps, o);
        if (lane >= o) ps += n;
    }
    if (lane == 31) ws[w] = ps;
    __syncthreads();
    if (w == 0) {
        int x = ws[lane];
        #pragma unroll
        for (int o = 1; o < 32; o <<= 1) {
            int n = __shfl_up_sync(0xffffffffu, x, o);
            if (lane >= o) x += n;
        }
        ws[lane] = x;
    }
    __syncthreads();
    int base = ps - s + (w ? ws[w - 1] : 0);
    #pragma unroll
    for (int i = 0; i < 4; i++) {
        if (v[i]) { g_idx[b * Ff + base] = t * 4 + i; base++; }
    }
    if (t == 1023) g_cnt[b] = ws[31];
}

// ---------------- 3xBF16 mma GEMM 128x128 ----------------
#define STAGE_B    32768
#define GEMM_SMEM  (3 * STAGE_B)

__global__ void __launch_bounds__(256, 2) bf16_gemm(
    const bf16* __restrict__ Ah, const bf16* __restrict__ Al,
    const bf16* __restrict__ Wh, const bf16* __restrict__ Wl,
    float* __restrict__ Cf, bf16* __restrict__ Ch, bf16* __restrict__ Cl,
    int M, int N, int K, int relu)
{
    extern __shared__ __align__(1024) char smem[];
    int tid = threadIdx.x;
    int lane = tid & 31, wid = tid >> 5;
    int bn = blockIdx.x << 7, bm = blockIdx.y << 7;
    uint32_t sbase = smem_u32(smem);

    int wm = (wid & 1) << 6;
    int wn = (wid >> 1) << 5;

    float acc[4][4][4];
    #pragma unroll
    for (int i = 0; i < 4; i++)
        #pragma unroll
        for (int j = 0; j < 4; j++)
            #pragma unroll
            for (int r = 0; r < 4; r++) acc[i][j][r] = 0.f;

    int nCh = K >> 5;

    auto issue = [&](int p, int s) {
        uint32_t st = sbase + s * STAGE_B;
        int k0 = p << 5;
        #pragma unroll
        for (int r = 0; r < 2; r++) {
            int c = r * 256 + tid;
            int m = c >> 2, c4 = c & 3;
            uint32_t off = m * 64 + (c4 << 4);
            uint32_t sw = off ^ ((off >> 3) & 0x30);
            cpa16(st + sw, Ah + (size_t)(bm + m) * K + k0 + c4 * 8);
            cpa16(st + 8192 + sw, Al + (size_t)(bm + m) * K + k0 + c4 * 8);
        }
        #pragma unroll
        for (int r = 0; r < 2; r++) {
            int c = r * 256 + tid;
            int kk = c >> 4, c16 = c & 15;
            uint32_t off = kk * 256 + (c16 << 4);
            uint32_t sw = off ^ ((off >> 4) & 0x70);
            cpa16(st + 16384 + sw, Wh + (size_t)(k0 + kk) * N + bn + c16 * 8);
            cpa16(st + 24576 + sw, Wl + (size_t)(k0 + kk) * N + bn + c16 * 8);
        }
        CPA_COMMIT();
    };

    issue(0, 0);
    if (nCh > 1) issue(1, 1); else CPA_COMMIT();

    int quad = lane >> 3, rr = lane & 7;
    int lrow = ((quad & 1) << 3) + rr;
    int lcol = quad >> 1;
    int bl16 = lane & 15;

    for (int p = 0; p < nCh; p++) {
        CPA_WAIT1();
        __syncthreads();
        int s = p % 3;
        uint32_t aHi = sbase + s * STAGE_B;
        uint32_t aLo = aHi + 8192;
        uint32_t bHi = aHi + 16384;
        uint32_t bLo = aHi + 24576;

        #pragma unroll
        for (int j = 0; j < 2; j++) {
            uint32_t ahf[4][4], alf[4][4];
            #pragma unroll
            for (int mt = 0; mt < 4; mt++) {
                uint32_t off = (uint32_t)(wm + mt * 16 + lrow) * 64 + j * 32 + (lcol << 4);
                uint32_t sw = off ^ ((off >> 3) & 0x30);
                LDSM4(ahf[mt][0], ahf[mt][1], ahf[mt][2], ahf[mt][3], aHi + sw);
                LDSM4(alf[mt][0], alf[mt][1], alf[mt][2], alf[mt][3], aLo + sw);
            }
            uint32_t bhf[4][2], blf[4][2];
            {
                uint32_t krow = j * 16 + bl16;
                #pragma unroll
                for (int nt = 0; nt < 4; nt++) {
                    uint32_t off = krow * 256 + (uint32_t)(wn + nt * 8) * 2;
                    uint32_t sw = off ^ ((off >> 4) & 0x70);
                    LDSM2T(bhf[nt][0], bhf[nt][1], bHi + sw);
                    LDSM2T(blf[nt][0], blf[nt][1], bLo + sw);
                }
            }
            #pragma unroll
            for (int mt = 0; mt < 4; mt++)
                #pragma unroll
                for (int nt = 0; nt < 4; nt++) {
                    MMA_BF16(acc[mt][nt], ahf[mt], bhf[nt]);
                    MMA_BF16(acc[mt][nt], ahf[mt], blf[nt]);
                    MMA_BF16(acc[mt][nt], alf[mt], bhf[nt]);
                }
        }
        if (p + 2 < nCh) issue(p + 2, (p + 2) % 3);
        else CPA_COMMIT();
    }

    int r0 = bm + wm + (lane >> 2);
    int cc = bn + wn + ((lane & 3) << 1);
    #pragma unroll
    for (int mt = 0; mt < 4; mt++) {
        #pragma unroll
        for (int nt = 0; nt < 4; nt++) {
            float v0 = acc[mt][nt][0], v1 = acc[mt][nt][1];
            float v2 = acc[mt][nt][2], v3 = acc[mt][nt][3];
            if (relu) {
                v0 = fmaxf(v0, 0.f); v1 = fmaxf(v1, 0.f);
                v2 = fmaxf(v2, 0.f); v3 = fmaxf(v3, 0.f);
            }
            int row = r0 + mt * 16;
            int col = cc + nt * 8;
            if (Cf) {
                *(float2*)(Cf + (size_t)row * N + col) = make_float2(v0, v1);
                *(float2*)(Cf + (size_t)(row + 8) * N + col) = make_float2(v2, v3);
            } else {
                uint32_t ph, pl;
                splitpack(v0, v1, ph, pl);
                *(uint32_t*)(Ch + (size_t)row * N + col) = ph;
                *(uint32_t*)(Cl + (size_t)row * N + col) = pl;
                splitpack(v2, v3, ph, pl);
                *(uint32_t*)(Ch + (size_t)(row + 8) * N + col) = ph;
                *(uint32_t*)(Cl + (size_t)(row + 8) * N + col) = pl;
            }
        }
    }
}

// ---------------- 64-row-tile variant for small GEMMs ----------------
#define STAGE64    24576
#define GEMM64_SMEM (3 * STAGE64)

__global__ void __launch_bounds__(256, 2) bf16_gemm64(
    const bf16* __restrict__ Ah, const bf16* __restrict__ Al,
    const bf16* __restrict__ Wh, const bf16* __restrict__ Wl,
    float* __restrict__ Cf, bf16* __restrict__ Ch, bf16* __restrict__ Cl,
    int M, int N, int K, int relu)
{
    extern __shared__ __align__(1024) char smem[];
    int tid = threadIdx.x;
    int lane = tid & 31, wid = tid >> 5;
    int bn = blockIdx.x << 7, bm = blockIdx.y << 6;
    uint32_t sbase = smem_u32(smem);

    int wm = (wid & 1) << 5;
    int wn = (wid >> 1) << 5;

    float acc[2][4][4];
    #pragma unroll
    for (int i = 0; i < 2; i++)
        #pragma unroll
        for (int j = 0; j < 4; j++)
            #pragma unroll
            for (int r = 0; r < 4; r++) acc[i][j][r] = 0.f;

    int nCh = K >> 5;

    auto issue = [&](int p, int s) {
        uint32_t st = sbase + s * STAGE64;
        int k0 = p << 5;
        {
            int c = tid;
            int m = c >> 2, c4 = c & 3;
            uint32_t off = m * 64 + (c4 << 4);
            uint32_t sw = off ^ ((off >> 3) & 0x30);
            cpa16(st + sw, Ah + (size_t)(bm + m) * K + k0 + c4 * 8);
            cpa16(st + 4096 + sw, Al + (size_t)(bm + m) * K + k0 + c4 * 8);
        }
        #pragma unroll
        for (int r = 0; r < 2; r++) {
            int c = r * 256 + tid;
            int kk = c >> 4, c16 = c & 15;
            uint32_t off = kk * 256 + (c16 << 4);
            uint32_t sw = off ^ ((off >> 4) & 0x70);
            cpa16(st + 8192 + sw, Wh + (size_t)(k0 + kk) * N + bn + c16 * 8);
            cpa16(st + 16384 + sw, Wl + (size_t)(k0 + kk) * N + bn + c16 * 8);
        }
        CPA_COMMIT();
    };

    issue(0, 0);
    if (nCh > 1) issue(1, 1); else CPA_COMMIT();

    int quad = lane >> 3, rr = lane & 7;
    int lrow = ((quad & 1) << 3) + rr;
    int lcol = quad >> 1;
    int bl16 = lane & 15;

    for (int p = 0; p < nCh; p++) {
        CPA_WAIT1();
        __syncthreads();
        int s = p % 3;
        uint32_t aHi = sbase + s * STAGE64;
        uint32_t aLo = aHi + 4096;
        uint32_t bHi = aHi + 8192;
        uint32_t bLo = aHi + 16384;

        #pragma unroll
        for (int j = 0; j < 2; j++) {
            uint32_t ahf[2][4], alf[2][4];
            #pragma unroll
            for (int mt = 0; mt < 2; mt++) {
                uint32_t off = (uint32_t)(wm + mt * 16 + lrow) * 64 + j * 32 + (lcol << 4);
                uint32_t sw = off ^ ((off >> 3) & 0x30);
                LDSM4(ahf[mt][0], ahf[mt][1], ahf[mt][2], ahf[mt][3], aHi + sw);
                LDSM4(alf[mt][0], alf[mt][1], alf[mt][2], alf[mt][3], aLo + sw);
            }
            uint32_t bhf[4][2], blf[4][2];
            {
                uint32_t krow = j * 16 + bl16;
                #pragma unroll
                for (int nt = 0; nt < 4; nt++) {
                    uint32_t off = krow * 256 + (uint32_t)(wn + nt * 8) * 2;
                    uint32_t sw = off ^ ((off >> 4) & 0x70);
                    LDSM2T(bhf[nt][0], bhf[nt][1], bHi + sw);
                    LDSM2T(blf[nt][0], blf[nt][1], bLo + sw);
                }
            }
            #pragma unroll
            for (int mt = 0; mt < 2; mt++)
                #pragma unroll
                for (int nt = 0; nt < 4; nt++) {
                    MMA_BF16(acc[mt][nt], ahf[mt], bhf[nt]);
                    MMA_BF16(acc[mt][nt], ahf[mt], blf[nt]);
                    MMA_BF16(acc[mt][nt], alf[mt], bhf[nt]);
                }
        }
        if (p + 2 < nCh) issue(p + 2, (p + 2) % 3);
        else CPA_COMMIT();
    }

    int r0 = bm + wm + (lane >> 2);
    int cc = bn + wn + ((lane & 3) << 1);
    #pragma unroll
    for (int mt = 0; mt < 2; mt++) {
        #pragma unroll
        for (int nt = 0; nt < 4; nt++) {
            float v0 = acc[mt][nt][0], v1 = acc[mt][nt][1];
            float v2 = acc[mt][nt][2], v3 = acc[mt][nt][3];
            if (relu) {
                v0 = fmaxf(v0, 0.f); v1 = fmaxf(v1, 0.f);
                v2 = fmaxf(v2, 0.f); v3 = fmaxf(v3, 0.f);
            }
            int row = r0 + mt * 16;
            int col = cc + nt * 8;
            if (Cf) {
                *(float2*)(Cf + (size_t)row * N + col) = make_float2(v0, v1);
                *(float2*)(Cf + (size_t)(row + 8) * N + col) = make_float2(v2, v3);
            } else {
                uint32_t ph, pl;
                splitpack(v0, v1, ph, pl);
                *(uint32_t*)(Ch + (size_t)row * N + col) = ph;
                *(uint32_t*)(Cl + (size_t)row * N + col) = pl;
                splitpack(v2, v3, ph, pl);
                *(uint32_t*)(Ch + (size_t)(row + 8) * N + col) = ph;
                *(uint32_t*)(Cl + (size_t)(row + 8) * N + col) = pl;
            }
        }
    }
}

// ---------------- fused K+V projection (z via global strides) ----------------
__global__ void __launch_bounds__(256, 2) bf16_gemm_kv(
    const bf16* __restrict__ Ah, const bf16* __restrict__ Al)
{
    if (((int)(blockIdx.y & 31) << 7) >= g_cnt[blockIdx.y >> 5]) return;

    const int N = DIMc, K = DIMc;
    const bf16* Wh = g_kvwh + (size_t)blockIdx.z * KVW;
    const bf16* Wl = g_kvwl + (size_t)blockIdx.z * KVW;
    bf16* Ch = g_kvh + (size_t)blockIdx.z * KVSZ;
    bf16* Cl = g_kvl + (size_t)blockIdx.z * KVSZ;

    extern __shared__ __align__(1024) char smem[];
    int tid = threadIdx.x;
    int lane = tid & 31, wid = tid >> 5;
    int bn = blockIdx.x << 7, bm = blockIdx.y << 7;
    uint32_t sbase = smem_u32(smem);

    int wm = (wid & 1) << 6;
    int wn = (wid >> 1) << 5;

    float acc[4][4][4];
    #pragma unroll
    for (int i = 0; i < 4; i++)
        #pragma unroll
        for (int j = 0; j < 4; j++)
            #pragma unroll
            for (int r = 0; r < 4; r++) acc[i][j][r] = 0.f;

    int nCh = K >> 5;

    auto issue = [&](int p, int s) {
        uint32_t st = sbase + s * STAGE_B;
        int k0 = p << 5;
        #pragma unroll
        for (int r = 0; r < 2; r++) {
            int c = r * 256 + tid;
            int m = c >> 2, c4 = c & 3;
            uint32_t off = m * 64 + (c4 << 4);
            uint32_t sw = off ^ ((off >> 3) & 0x30);
            cpa16(st + sw, Ah + (size_t)(bm + m) * K + k0 + c4 * 8);
            cpa16(st + 8192 + sw, Al + (size_t)(bm + m) * K + k0 + c4 * 8);
        }
        #pragma unroll
        for (int r = 0; r < 2; r++) {
            int c = r * 256 + tid;
            int kk = c >> 4, c16 = c & 15;
            uint32_t off = kk * 256 + (c16 << 4);
            uint32_t sw = off ^ ((off >> 4) & 0x70);
            cpa16(st + 16384 + sw, Wh + (size_t)(k0 + kk) * N + bn + c16 * 8);
            cpa16(st + 24576 + sw, Wl + (size_t)(k0 + kk) * N + bn + c16 * 8);
        }
        CPA_COMMIT();
    };

    issue(0, 0);
    if (nCh > 1) issue(1, 1); else CPA_COMMIT();

    int quad = lane >> 3, rr = lane & 7;
    int lrow = ((quad & 1) << 3) + rr;
    int lcol = quad >> 1;
    int bl16 = lane & 15;

    for (int p = 0; p < nCh; p++) {
        CPA_WAIT1();
        __syncthreads();
        int s = p % 3;
        uint32_t aHi = sbase + s * STAGE_B;
        uint32_t aLo = aHi + 8192;
        uint32_t bHi = aHi + 16384;
        uint32_t bLo = aHi + 24576;

        #pragma unroll
        for (int j = 0; j < 2; j++) {
            uint32_t ahf[4][4], alf[4][4];
            #pragma unroll
            for (int mt = 0; mt < 4; mt++) {
                uint32_t off = (uint32_t)(wm + mt * 16 + lrow) * 64 + j * 32 + (lcol << 4);
                uint32_t sw = off ^ ((off >> 3) & 0x30);
                LDSM4(ahf[mt][0], ahf[mt][1], ahf[mt][2], ahf[mt][3], aHi + sw);
                LDSM4(alf[mt][0], alf[mt][1], alf[mt][2], alf[mt][3], aLo + sw);
            }
            uint32_t bhf[4][2], blf[4][2];
            {
                uint32_t krow = j * 16 + bl16;
                #pragma unroll
                for (int nt = 0; nt < 4; nt++) {
                    uint32_t off = krow * 256 + (uint32_t)(wn + nt * 8) * 2;
                    uint32_t sw = off ^ ((off >> 4) & 0x70);
                    LDSM2T(bhf[nt][0], bhf[nt][1], bHi + sw);
                    LDSM2T(blf[nt][0], blf[nt][1], bLo + sw);
                }
            }
            #pragma unroll
            for (int mt = 0; mt < 4; mt++)
                #pragma unroll
                for (int nt = 0; nt < 4; nt++) {
                    MMA_BF16(acc[mt][nt], ahf[mt], bhf[nt]);
                    MMA_BF16(acc[mt][nt], ahf[mt], blf[nt]);
                    MMA_BF16(acc[mt][nt], alf[mt], bhf[nt]);
                }
        }
        if (p + 2 < nCh) issue(p + 2, (p + 2) % 3);
        else CPA_COMMIT();
    }

    int r0 = bm + wm + (lane >> 2);
    int cc = bn + wn + ((lane & 3) << 1);
    #pragma unroll
    for (int mt = 0; mt < 4; mt++) {
        #pragma unroll
        for (int nt = 0; nt < 4; nt++) {
            int row = r0 + mt * 16;
            int col = cc + nt * 8;
            uint32_t ph, pl;
            splitpack(acc[mt][nt][0], acc[mt][nt][1], ph, pl);
            *(uint32_t*)(Ch + (size_t)row * N + col) = ph;
            *(uint32_t*)(Cl + (size_t)row * N + col) = pl;
            splitpack(acc[mt][nt][2], acc[mt][nt][3], ph, pl);
            *(uint32_t*)(Ch + (size_t)(row + 8) * N + col) = ph;
            *(uint32_t*)(Cl + (size_t)(row + 8) * N + col) = pl;
        }
    }
}

// ---------------- all weight splits in one launch ----------------
__global__ void splitw_all(const float* __restrict__ Wq, const float* __restrict__ Wk,
                           const float* __restrict__ Wv, const float* __restrict__ W1,
                           const float* __restrict__ W2) {
    int q = blockIdx.x * 256 + threadIdx.x;
    const float* src; bf16 *dh, *dl; int off;
    if (q < 65536)        { src = Wq; dh = g_wqh;        dl = g_wql;        off = q; }
    else if (q < 131072)  { src = Wk; dh = g_kvwh;       dl = g_kvwl;       off = q - 65536; }
    else if (q < 196608)  { src = Wv; dh = g_kvwh + KVW; dl = g_kvwl + KVW; off = q - 131072; }
    else if (q < 327680)  { src = W1; dh = g_w1h;        dl = g_w1l;        off = q - 196608; }
    else                  { src = W2; dh = g_w2h;        dl = g_w2l;        off = q - 327680; }
    float4 v = ((const float4*)src)[off];
    uint32_t h01, l01, h23, l23;
    splitpack(v.x, v.y, h01, l01);
    splitpack(v.z, v.w, h23, l23);
    *(uint2*)(dh + (size_t)off * 4) = make_uint2(h01, h23);
    *(uint2*)(dl + (size_t)off * 4) = make_uint2(l01, l23);
}

// ---------------- LayerNorm: 2 rows per block -> bf16 hi/lo ----------------
__global__ void ln_kernel2(const float* __restrict__ x, const float* __restrict__ g,
                           const float* __restrict__ beta,
                           bf16* __restrict__ yh, bf16* __restrict__ yl) {
    __shared__ float sm[8];
    int half = threadIdx.x >> 7;
    int t = threadIdx.x & 127;
    size_t row = (size_t)blockIdx.x * 2 + half;
    float4 v = ((const float4*)(x + row * DIMc))[t];
    float s = v.x + v.y + v.z + v.w;
    #pragma unroll
    for (int o = 16; o; o >>= 1) s += __shfl_xor_sync(0xffffffffu, s, o);
    if ((t & 31) == 0) sm[threadIdx.x >> 5] = s;
    __syncthreads();
    int sb = half * 4;
    float mean = (sm[sb] + sm[sb + 1] + sm[sb + 2] + sm[sb + 3]) * (1.0f / DIMc);
    __syncthreads();
    float dx = v.x - mean, dy = v.y - mean, dz = v.z - mean, dw = v.w - mean;
    float sq = dx * dx + dy * dy + dz * dz + dw * dw;
    #pragma unroll
    for (int o = 16; o; o >>= 1) sq += __shfl_xor_sync(0xffffffffu, sq, o);
    if ((t & 31) == 0) sm[threadIdx.x >> 5] = sq;
    __syncthreads();
    float var = (sm[sb] + sm[sb + 1] + sm[sb + 2] + sm[sb + 3]) * (1.0f / DIMc);
    float rstd = rsqrtf(var + 1e-5f);
    float4 gg = ((const float4*)g)[t];
    float4 bb = ((const float4*)beta)[t];
    float o0 = dx * rstd * gg.x + bb.x;
    float o1 = dy * rstd * gg.y + bb.y;
    float o2 = dz * rstd * gg.z + bb.z;
    float o3 = dw * rstd * gg.w + bb.w;
    uint32_t h01, l01, h23, l23;
    splitpack(o0, o1, h01, l01);
    splitpack(o2, o3, h23, l23);
    *(uint2*)(yh + row * DIMc + t * 4) = make_uint2(h01, h23);
    *(uint2*)(yl + row * DIMc + t * 4) = make_uint2(l01, l23);
}

// ---------------- LN + gather ----------------
__global__ void ln_gather(const float* __restrict__ x, const float* __restrict__ g,
                          const float* __restrict__ beta,
                          bf16* __restrict__ yh, bf16* __restrict__ yl) {
    __shared__ float sm[8];
    int half = threadIdx.x >> 7;
    int t = threadIdx.x & 127;
    size_t row = (size_t)blockIdx.x * 2 + half;
    int b = (int)(row >> 12);
    int r = (int)(row & (Ff - 1));
    int cnt = g_cnt[b];
    if (r >= cnt) {
        int cntUp = (cnt + 127) & ~127;
        if (r < cntUp) {
            *(uint2*)(yh + row * DIMc + t * 4) = make_uint2(0u, 0u);
            *(uint2*)(yl + row * DIMc + t * 4) = make_uint2(0u, 0u);
        }
        return;
    }
    size_t src = (size_t)b * Ff + g_idx[b * Ff + r];
    float4 v = ((const float4*)(x + src * DIMc))[t];
    float s = v.x + v.y + v.z + v.w;
    #pragma unroll
    for (int o = 16; o; o >>= 1) s += __shfl_xor_sync(0xffffffffu, s, o);
    if ((t & 31) == 0) sm[threadIdx.x >> 5] = s;
    __syncthreads();
    int sb = half * 4;
    float mean = (sm[sb] + sm[sb + 1] + sm[sb + 2] + sm[sb + 3]) * (1.0f / DIMc);
    __syncthreads();
    float dx = v.x - mean, dy = v.y - mean, dz = v.z - mean, dw = v.w - mean;
    float sq = dx * dx + dy * dy + dz * dz + dw * dw;
    #pragma unroll
    for (int o = 16; o; o >>= 1) sq += __shfl_xor_sync(0xffffffffu, sq, o);
    if ((t & 31) == 0) sm[threadIdx.x >> 5] = sq;
    __syncthreads();
    float var = (sm[sb] + sm[sb + 1] + sm[sb + 2] + sm[sb + 3]) * (1.0f / DIMc);
    float rstd = rsqrtf(var + 1e-5f);
    float4 gg = ((const float4*)g)[t];
    float4 bb = ((const float4*)beta)[t];
    float o0 = dx * rstd * gg.x + bb.x;
    float o1 = dy * rstd * gg.y + bb.y;
    float o2 = dz * rstd * gg.z + bb.z;
    float o3 = dw * rstd * gg.w + bb.w;
    uint32_t h01, l01, h23, l23;
    splitpack(o0, o1, h01, l01);
    splitpack(o2, o3, h23, l23);
    *(uint2*)(yh + row * DIMc + t * 4) = make_uint2(h01, h23);
    *(uint2*)(yl + row * DIMc + t * 4) = make_uint2(l01, l23);
}

// ---------------- flash attention over compacted F (K/V load overlap) ----------------
#define oQh   0
#define oQl   8192
#define oKh   16384
#define oKl   32768
#define oVh   49152
#define oVl   65536
#define oPmax 81920
#define oPsum 82432
#define ATT_SMEM 82944

__global__ void __launch_bounds__(256, 2) flash_attn_mma(
    const bf16* __restrict__ qh, const bf16* __restrict__ ql,
    const bf16* __restrict__ kh, const bf16* __restrict__ kl,
    const bf16* __restrict__ vh, const bf16* __restrict__ vl)
{
    extern __shared__ __align__(1024) char sm_[];
    uint32_t sb = smem_u32(sm_);
    int tid = threadIdx.x, lane = tid & 31, wid = tid >> 5;
    int wm = (wid & 3) << 4;
    int wn = wid >> 2;
    int c  = blockIdx.x & (NSPL - 1);
    int h  = (blockIdx.x >> 4) & 7;
    int b  = blockIdx.x >> 7;
    int pbase = (b * Hh + h) * NSPL + c;
    int cnt = g_cnt[b];

    size_t qoff = (size_t)b * Qq * DIMc + h * DHh;
    size_t koff = (size_t)b * Ff * DIMc + h * DHh;

    float* pmax = (float*)(sm_ + oPmax);
    float* psum = (float*)(sm_ + oPsum);

    int fbeg = c * FSEG;
    if (fbeg >= cnt) {
        // empty split: combine skips g_po when m == -INF, so only mark m/l
        if (tid < 64 && wid == 0) {
            g_pm[(size_t)pbase * Qq + tid] = -INFINITY;
            g_pl[(size_t)pbase * Qq + tid] = 0.f;
        }
        return;
    }

    #pragma unroll
    for (int r = 0; r < 2; r++) {
        int idx = r * 256 + tid;
        int row = idx >> 3, ch = idx & 7;
        uint32_t off = row * 128 + (ch << 4);
        uint32_t sw = off ^ ((off >> 3) & 0x70);
        cpa16(sb + oQh + sw, qh + qoff + (size_t)row * DIMc + ch * 8);
        cpa16(sb + oQl + sw, ql + qoff + (size_t)row * DIMc + ch * 8);
    }
    CPA_COMMIT();

    float m0 = -INFINITY, m1 = -INFINITY, l0 = 0.f, l1 = 0.f;
    float O[8][4];
    #pragma unroll
    for (int nt = 0; nt < 8; nt++)
        #pragma unroll
        for (int r = 0; r < 4; r++) O[nt][r] = 0.f;

    int quad = lane >> 3, rr = lane & 7;
    int lrow = ((quad & 1) << 3) + rr;
    int lcol = quad >> 1;
    int row0 = wm + (lane >> 2);

    for (int f0 = fbeg; f0 < fbeg + FSEG; f0 += FCH) {
        if (f0 >= cnt) break;
        __syncthreads();
        #pragma unroll
        for (int r = 0; r < 4; r++) {
            int idx = r * 256 + tid;
            int row = idx >> 3, ch = idx & 7;
            uint32_t off = row * 128 + (ch << 4);
            uint32_t sw = off ^ ((off >> 3) & 0x70);
            size_t g = koff + (size_t)(f0 + row) * DIMc + ch * 8;
            cpa16(sb + oKh + sw, kh + g);
            cpa16(sb + oKl + sw, kl + g);
        }
        CPA_COMMIT();
        #pragma unroll
        for (int r = 0; r < 4; r++) {
            int idx = r * 256 + tid;
            int row = idx >> 3, ch = idx & 7;
            uint32_t off = row * 128 + (ch << 4);
            uint32_t sw = off ^ ((off >> 3) & 0x70);
            size_t g = koff + (size_t)(f0 + row) * DIMc + ch * 8;
            cpa16(sb + oVh + sw, vh + g);
            cpa16(sb + oVl + sw, vl + g);
        }
        CPA_COMMIT();
        CPA_WAIT1();
        __syncthreads();

        float S[8][4];
        #pragma unroll
        for (int nt = 0; nt < 8; nt++)
            #pragma unroll
            for (int r = 0; r < 4; r++) S[nt][r] = 0.f;

        #pragma unroll
        for (int j = 0; j < 4; j++) {
            uint32_t qoffb = (uint32_t)(wm + lrow) * 128 + j * 32 + (lcol << 4);
            uint32_t qsw = qoffb ^ ((qoffb >> 3) & 0x70);
            uint32_t qhf[4], qlf[4];
            LDSM4(qhf[0], qhf[1], qhf[2], qhf[3], sb + oQh + qsw);
            LDSM4(qlf[0], qlf[1], qlf[2], qlf[3], sb + oQl + qsw);
            #pragma unroll
            for (int nt = 0; nt < 8; nt++) {
                int fr = wn * 64 + nt * 8 + (lane & 7);
                int seg = (lane >> 3) & 1;
                uint32_t boff = (uint32_t)fr * 128 + j * 32 + (seg << 4);
                uint32_t bsw = boff ^ ((boff >> 3) & 0x70);
                uint32_t kbh[2], kbl[2];
                LDSM2(kbh[0], kbh[1], sb + oKh + bsw);
                LDSM2(kbl[0], kbl[1], sb + oKl + bsw);
                MMA_BF16(S[nt], qhf, kbh);
                MMA_BF16(S[nt], qhf, kbl);
                MMA_BF16(S[nt], qlf, kbh);
            }
        }

        #pragma unroll
        for (int nt = 0; nt < 8; nt++) {
            int col0 = f0 + wn * 64 + nt * 8 + ((lane & 3) << 1);
            int mj0 = col0 < cnt, mj1 = (col0 + 1) < cnt;
            S[nt][0] = mj0 ? S[nt][0] * 0.125f : -INFINITY;
            S[nt][2] = mj0 ? S[nt][2] * 0.125f : -INFINITY;
            S[nt][1] = mj1 ? S[nt][1] * 0.125f : -INFINITY;
            S[nt][3] = mj1 ? S[nt][3] * 0.125f : -INFINITY;
        }

        float rx0 = -INFINITY, rx1 = -INFINITY;
        #pragma unroll
        for (int nt = 0; nt < 8; nt++) {
            rx0 = fmaxf(rx0, fmaxf(S[nt][0], S[nt][1]));
            rx1 = fmaxf(rx1, fmaxf(S[nt][2], S[nt][3]));
        }
        rx0 = fmaxf(rx0, __shfl_xor_sync(0xffffffffu, rx0, 1));
        rx0 = fmaxf(rx0, __shfl_xor_sync(0xffffffffu, rx0, 2));
        rx1 = fmaxf(rx1, __shfl_xor_sync(0xffffffffu, rx1, 1));
        rx1 = fmaxf(rx1, __shfl_xor_sync(0xffffffffu, rx1, 2));
        if ((lane & 3) == 0) {
            pmax[wn * 64 + row0] = rx0;
            pmax[wn * 64 + row0 + 8] = rx1;
        }
        __syncthreads();
        float nm0 = fmaxf(m0, fmaxf(pmax[row0], pmax[64 + row0]));
        float nm1 = fmaxf(m1, fmaxf(pmax[row0 + 8], pmax[64 + row0 + 8]));
        float sf0 = (nm0 == -INFINITY) ? 1.f : __expf(m0 - nm0);
        float sf1 = (nm1 == -INFINITY) ? 1.f : __expf(m1 - nm1);

        float rs0 = 0.f, rs1 = 0.f;
        #pragma unroll
        for (int nt = 0; nt < 8; nt++) {
            float e0 = (S[nt][0] == -INFINITY) ? 0.f : __expf(S[nt][0] - nm0);
            float e1 = (S[nt][1] == -INFINITY) ? 0.f : __expf(S[nt][1] - nm0);
            float e2 = (S[nt][2] == -INFINITY) ? 0.f : __expf(S[nt][2] - nm1);
            float e3 = (S[nt][3] == -INFINITY) ? 0.f : __expf(S[nt][3] - nm1);
            S[nt][0] = e0; S[nt][1] = e1; S[nt][2] = e2; S[nt][3] = e3;
            rs0 += e0 + e1; rs1 += e2 + e3;
        }
        rs0 += __shfl_xor_sync(0xffffffffu, rs0, 1);
        rs0 += __shfl_xor_sync(0xffffffffu, rs0, 2);
        rs1 += __shfl_xor_sync(0xffffffffu, rs1, 1);
        rs1 += __shfl_xor_sync(0xffffffffu, rs1, 2);
        if ((lane & 3) == 0) {
            psum[wn * 64 + row0] = rs0;
            psum[wn * 64 + row0 + 8] = rs1;
        }
        CPA_WAIT0();
        __syncthreads();
        l0 = l0 * sf0 + psum[row0] + psum[64 + row0];
        l1 = l1 * sf1 + psum[row0 + 8] + psum[64 + row0 + 8];
        m0 = nm0; m1 = nm1;
        #pragma unroll
        for (int nt = 0; nt < 8; nt++) {
            O[nt][0] *= sf0; O[nt][1] *= sf0;
            O[nt][2] *= sf1; O[nt][3] *= sf1;
        }

        #pragma unroll
        for (int j = 0; j < 4; j++) {
            uint32_t pah[4], pal[4];
            splitpack(S[2 * j][0], S[2 * j][1], pah[0], pal[0]);
            splitpack(S[2 * j][2], S[2 * j][3], pah[1], pal[1]);
            splitpack(S[2 * j + 1][0], S[2 * j + 1][1], pah[2], pal[2]);
            splitpack(S[2 * j + 1][2], S[2 * j + 1][3], pah[3], pal[3]);
            uint32_t frow = (uint32_t)(wn * 64 + j * 16 + (lane & 15));
            #pragma unroll
            for (int nt = 0; nt < 8; nt++) {
                uint32_t off = frow * 128 + (nt << 4);
                uint32_t sw = off ^ ((off >> 3) & 0x70);
                uint32_t vbh[2], vbl[2];
                LDSM2T(vbh[0], vbh[1], sb + oVh + sw);
                LDSM2T(vbl[0], vbl[1], sb + oVl + sw);
                MMA_BF16(O[nt], pah, vbh);
                MMA_BF16(O[nt], pah, vbl);
                MMA_BF16(O[nt], pal, vbh);
            }
        }
    }

    __syncthreads();
    float* ob = (float*)(sm_ + oKh);
    float* obw = ob + wn * 4096;
    #pragma unroll
    for (int nt = 0; nt < 8; nt++) {
        int col = nt * 8 + ((lane & 3) << 1);
        obw[row0 * 64 + col] = O[nt][0];
        obw[row0 * 64 + col + 1] = O[nt][1];
        obw[(row0 + 8) * 64 + col] = O[nt][2];
        obw[(row0 + 8) * 64 + col + 1] = O[nt][3];
    }
    if ((lane & 3) == 0 && wn == 0) {
        g_pm[(size_t)pbase * Qq + row0] = m0;
        g_pl[(size_t)pbase * Qq + row0] = l0;
        g_pm[(size_t)pbase * Qq + row0 + 8] = m1;
        g_pl[(size_t)pbase * Qq + row0 + 8] = l1;
    }
    __syncthreads();
    #pragma unroll
    for (int r = 0; r < 16; r++) {
        int idx = r * 256 + tid;
        int qq = idx >> 6, dd = idx & 63;
        g_po[((size_t)pbase * Qq + qq) * DHh + dd] = ob[qq * 64 + dd] + ob[4096 + qq * 64 + dd];
    }
}

// ---------------- combine partials ----------------
__global__ void attn_combine(float* __restrict__ out) {
    int bh = blockIdx.x >> 6;
    int q  = blockIdx.x & 63;
    int b  = bh >> 3, h = bh & 7;
    int d  = threadIdx.x;

    float mc[NSPL], lc[NSPL];
    float M = -INFINITY;
    #pragma unroll
    for (int c = 0; c < NSPL; c++) {
        mc[c] = g_pm[((size_t)bh * NSPL + c) * Qq + q];
        lc[c] = g_pl[((size_t)bh * NSPL + c) * Qq + q];
        M = fmaxf(M, mc[c]);
    }
    float r = 0.f;
    if (M != -INFINITY) {
        float num = 0.f, den = 0.f;
        #pragma unroll
        for (int c = 0; c < NSPL; c++) {
            if (mc[c] != -INFINITY) {
                float w = __expf(mc[c] - M);
                den += w * lc[c];
                num += w * g_po[(((size_t)bh * NSPL + c) * Qq + q) * DHh + d];
            }
        }
        r = (den > 0.f) ? num / den : 0.f;
    }
    out[((size_t)(b * Qq + q)) * DIMc + h * DHh + d] = r;
}

// ---------------- launch ----------------
extern "C" void kernel_launch(void* const* d_in, const int* in_sizes, int n_in,
                              void* d_out, int out_size) {
    const float* features = (const float*)d_in[0];
    const float* latents  = (const float*)d_in[1];
    const int*   mask     = (const int*)  d_in[2];
    const float* gf  = (const float*)d_in[3];
    const float* bf  = (const float*)d_in[4];
    const float* gl  = (const float*)d_in[5];
    const float* bl  = (const float*)d_in[6];
    const float* Wq  = (const float*)d_in[7];
    const float* Wk  = (const float*)d_in[8];
    const float* Wv  = (const float*)d_in[9];
    const float* gff = (const float*)d_in[10];
    const float* bff = (const float*)d_in[11];
    const float* W1  = (const float*)d_in[12];
    const float* W2  = (const float*)d_in[13];
    float* out = (float*)d_out;

    bf16 *xnh, *xnl, *lath, *latl, *ln2h, *ln2l, *ffhh, *ffhl;
    bf16 *wqh, *wql, *w1h, *w1l, *w2h, *w2l;
    bf16 *qh, *ql, *kvh, *kvl;
    float *att;
    cudaGetSymbolAddress((void**)&xnh,  g_xnh);  cudaGetSymbolAddress((void**)&xnl,  g_xnl);
    cudaGetSymbolAddress((void**)&lath, g_lath); cudaGetSymbolAddress((void**)&latl, g_latl);
    cudaGetSymbolAddress((void**)&ln2h, g_ln2h); cudaGetSymbolAddress((void**)&ln2l, g_ln2l);
    cudaGetSymbolAddress((void**)&ffhh, g_ffhh); cudaGetSymbolAddress((void**)&ffhl, g_ffhl);
    cudaGetSymbolAddress((void**)&wqh, g_wqh); cudaGetSymbolAddress((void**)&wql, g_wql);
    cudaGetSymbolAddress((void**)&w1h, g_w1h); cudaGetSymbolAddress((void**)&w1l, g_w1l);
    cudaGetSymbolAddress((void**)&w2h, g_w2h); cudaGetSymbolAddress((void**)&w2l, g_w2l);
    cudaGetSymbolAddress((void**)&qh, g_qh);  cudaGetSymbolAddress((void**)&ql, g_ql2);
    cudaGetSymbolAddress((void**)&kvh, g_kvh); cudaGetSymbolAddress((void**)&kvl, g_kvl);
    cudaGetSymbolAddress((void**)&att, g_att);

    cudaFuncSetAttribute(bf16_gemm, cudaFuncAttributeMaxDynamicSharedMemorySize, GEMM_SMEM);
    cudaFuncSetAttribute(bf16_gemm64, cudaFuncAttributeMaxDynamicSharedMemorySize, GEMM64_SMEM);
    cudaFuncSetAttribute(bf16_gemm_kv, cudaFuncAttributeMaxDynamicSharedMemorySize, GEMM_SMEM);
    cudaFuncSetAttribute(flash_attn_mma, cudaFuncAttributeMaxDynamicSharedMemorySize, ATT_SMEM);

    // lazily-created side stream + fork/join events (host objects; no device memory)
    static cudaStream_t s1 = nullptr;
    static cudaEvent_t evFork = nullptr, evJoin = nullptr;
    if (!s1) {
        cudaStreamCreateWithFlags(&s1, cudaStreamNonBlocking);
        cudaEventCreateWithFlags(&evFork, cudaEventDisableTiming);
        cudaEventCreateWithFlags(&evJoin, cudaEventDisableTiming);
    }

    // weight splits first (both tracks need them)
    splitw_all<<<1792, 256>>>(Wq, Wk, Wv, W1, W2);

    // fork: side stream runs the Q track (LN latents -> Q GEMM)
    cudaEventRecord(evFork, 0);
    cudaStreamWaitEvent(s1, evFork, 0);
    ln_kernel2<<<Bb * Qq / 2, 256, 0, s1>>>(latents, gl, bl, lath, latl);
    bf16_gemm64<<<dim3(DIMc / 128, (Bb * Qq) / 64), 256, GEMM64_SMEM, s1>>>(
        lath, latl, wqh, wql, nullptr, qh, ql, Bb * Qq, DIMc, DIMc, 0);
    cudaEventRecord(evJoin, s1);

    // main track: compaction -> feature LN -> K+V
    build_idx<<<Bb, 1024>>>(mask);
    ln_gather<<<Bb * Ff / 2, 256>>>(features, gf, bf, xnh, xnl);
    bf16_gemm_kv<<<dim3(DIMc / 128, (Bb * Ff) / 128, 2), 256, GEMM_SMEM>>>(xnh, xnl);

    // join before attention
    cudaStreamWaitEvent(0, evJoin, 0);
    flash_attn_mma<<<Bb * Hh * NSPL, 256, ATT_SMEM>>>(
        qh, ql, kvh, kvl, kvh + KVSZ, kvl + KVSZ);
    attn_combine<<<Bb * Hh * Qq, DHh>>>(att);

    // feed-forward
    ln_kernel2<<<Bb * Qq / 2, 256>>>(att, gff, bff, ln2h, ln2l);
    bf16_gemm64<<<dim3(1024 / 128, (Bb * Qq) / 64), 256, GEMM64_SMEM>>>(
        ln2h, ln2l, w1h, w1l, nullptr, ffhh, ffhl, Bb * Qq, 1024, DIMc, 1);
    bf16_gemm64<<<dim3(DIMc / 128, (Bb * Qq) / 64), 256, GEMM64_SMEM>>>(
        ffhh, ffhl, w2h, w2l, out, nullptr, nullptr, Bb * Qq, DIMc, 1024, 0);
}